// round 3
// baseline (speedup 1.0000x reference)
#include <cuda_runtime.h>
#include <math.h>

// Problem constants (fixed shapes)
#define NN   15135
#define BSZ  8
#define FF   64
#define GG   73
#define HH   256
#define EE   242160
#define MM   (NN*BSZ)       // 121080 rows
#define K1   (FF+GG)        // 137
#define HFCC 512

// ------------------- scratch (device globals; no allocation) -------------------
__device__ __align__(16) float d_h0[MM*K1];     // concat(x, pe) rows [n*8+b][k]
__device__ __align__(16) float d_hw[MM*HH];     // GEMM output (pre-aggregation)
__device__ __align__(16) float d_h1[MM*HH];
__device__ __align__(16) float d_h2[MM*HH];
__device__ __align__(16) float d_h3[MM*HH];
__device__ float d_dis[NN];
__device__ float d_dinv[NN];
__device__ int   d_cnt[NN];
__device__ int   d_rowptr[NN+1];
__device__ int   d_cursor[NN];
__device__ int   d_src[EE];
__device__ int   d_row32[EE];
__device__ int   d_col32[EE];
__device__ float d_g[BSZ*NN];
__device__ float d_zacc[BSZ*HFCC];
__device__ float d_z[BSZ*HFCC];

__device__ __forceinline__ float elu1(float x) { return x > 0.f ? x : expm1f(x); }

// ------------------- graph preprocessing -------------------
__global__ void zero_k()
{
    int i = blockIdx.x * 256 + threadIdx.x;
    if (i < NN) { d_cnt[i] = 0; d_cursor[i] = 0; }
    if (i < BSZ*HFCC) d_zacc[i] = 0.f;
}

// edge_index may be int64 or int32 depending on harness dtype handling.
// Detect: if values are int64 (< 2^31), every odd 32-bit word of the first
// 64 entries is zero. If int32 (random node ids in [0,15135)), the chance
// all 64 are zero is ~0.
__global__ void edges_k(const void* __restrict__ ei_raw)
{
    __shared__ int is64;
    const int* ei32 = (const int*)ei_raw;
    if (threadIdx.x == 0) {
        int allz = 1;
        for (int i = 0; i < 64; i++) if (ei32[2 * i + 1] != 0) { allz = 0; break; }
        is64 = allz;
    }
    __syncthreads();

    int e = blockIdx.x * 256 + threadIdx.x;
    if (e >= EE) return;
    int r, c;
    if (is64) {
        const long long* ei = (const long long*)ei_raw;
        r = (int)ei[e];
        c = (int)ei[EE + e];
    } else {
        r = ei32[e];
        c = ei32[EE + e];
    }
    d_row32[e] = r;
    d_col32[e] = c;
    atomicAdd(&d_cnt[c], 1);
}

__global__ void deg_k()
{
    int j = blockIdx.x * 256 + threadIdx.x;
    if (j >= NN) return;
    float dg = (float)d_cnt[j] + 1.0f;
    d_dis[j]  = rsqrtf(dg);
    d_dinv[j] = 1.0f / dg;
}

// single-block exclusive scan of d_cnt -> d_rowptr  (N=15135, 15 chunks of 1024)
__global__ void scan_k()
{
    __shared__ int sh[1024];
    int tid = threadIdx.x;
    int carry = 0;
    for (int base = 0; base < NN; base += 1024) {
        int i = base + tid;
        int v = (i < NN) ? d_cnt[i] : 0;
        sh[tid] = v;
        __syncthreads();
        #pragma unroll
        for (int off = 1; off < 1024; off <<= 1) {
            int t = (tid >= off) ? sh[tid - off] : 0;
            __syncthreads();
            sh[tid] += t;
            __syncthreads();
        }
        if (i < NN) d_rowptr[i] = carry + sh[tid] - v;  // exclusive
        carry += sh[1023];
        __syncthreads();
    }
    if (tid == 0) d_rowptr[NN] = carry;
}

__global__ void fill_k()
{
    int e = blockIdx.x * 256 + threadIdx.x;
    if (e >= EE) return;
    int c = d_col32[e];
    int p = atomicAdd(&d_cursor[c], 1);
    d_src[d_rowptr[c] + p] = d_row32[e];
}

// ------------------- input concat: h0[(n*8+b)*137 + k] -------------------
__global__ void concat_k(const float* __restrict__ x, const float* __restrict__ pe)
{
    int idx = blockIdx.x * 256 + threadIdx.x;
    if (idx >= MM * K1) return;
    int r = idx / K1;
    int k = idx - r * K1;
    int n = r >> 3, b = r & 7;
    float v = (k < FF) ? x[(b * NN + n) * FF + k] : pe[n * GG + (k - FF)];
    d_h0[idx] = v;
}

// ------------------- GEMM: C[M,256] = A[M,K] @ B[K,256] -------------------
// 128x128 block tile, 8x8 per thread, K-tile 8. A from device scratch (16B
// aligned); B from harness input -> scalar loads only.
__global__ __launch_bounds__(256) void gemm_k(const float* __restrict__ B, int asel, int K)
{
    const float* A = (asel == 0) ? d_h0 : (asel == 1) ? d_h1 : d_h2;
    float* C = d_hw;
    const int M = MM;

    __shared__ float As[8][128];
    __shared__ float Bs[8][128];

    int colBase = blockIdx.x * 128;
    int rowBase = blockIdx.y * 128;
    int t = threadIdx.x;
    int tx = t & 15, ty = t >> 4;

    float acc[8][8];
    #pragma unroll
    for (int i = 0; i < 8; i++)
        #pragma unroll
        for (int j = 0; j < 8; j++) acc[i][j] = 0.f;

    for (int k0 = 0; k0 < K; k0 += 8) {
        // A tile -> As[k][m] (transposed)
        {
            int m = t >> 1;
            int kk = (t & 1) * 4;
            int row = rowBase + m;
            #pragma unroll
            for (int i = 0; i < 4; i++) {
                int k = k0 + kk + i;
                As[kk + i][m] = (row < M && k < K) ? A[row * K + k] : 0.f;
            }
        }
        // B tile -> Bs[k][n]; scalar loads (harness pointer alignment unknown)
        {
            int kb = t >> 5;
            int nb = (t & 31) * 4;
            #pragma unroll
            for (int i = 0; i < 4; i++) {
                float bv = 0.f;
                if (k0 + kb < K) bv = B[(k0 + kb) * 256 + colBase + nb + i];
                Bs[kb][nb + i] = bv;
            }
        }
        __syncthreads();
        #pragma unroll
        for (int kk = 0; kk < 8; kk++) {
            float a[8], b[8];
            *(float4*)(a)     = *(const float4*)(&As[kk][ty * 8]);
            *(float4*)(a + 4) = *(const float4*)(&As[kk][ty * 8 + 4]);
            *(float4*)(b)     = *(const float4*)(&Bs[kk][tx * 8]);
            *(float4*)(b + 4) = *(const float4*)(&Bs[kk][tx * 8 + 4]);
            #pragma unroll
            for (int i = 0; i < 8; i++)
                #pragma unroll
                for (int j = 0; j < 8; j++)
                    acc[i][j] = fmaf(a[i], b[j], acc[i][j]);
        }
        __syncthreads();
    }

    #pragma unroll
    for (int i = 0; i < 8; i++) {
        int row = rowBase + ty * 8 + i;
        if (row < M) {
            float4 v0 = make_float4(acc[i][0], acc[i][1], acc[i][2], acc[i][3]);
            float4 v1 = make_float4(acc[i][4], acc[i][5], acc[i][6], acc[i][7]);
            *(float4*)(C + row * 256 + colBase + tx * 8)     = v0;
            *(float4*)(C + row * 256 + colBase + tx * 8 + 4) = v1;
        }
    }
}

// ------------------- CSR gather + self-loop + bias + ELU (per feature chunk) -------------------
// node row = 2048 floats = 512 float4; chunk = 128 float4 (2KB) -> 31MB working set, L2 resident.
__global__ __launch_bounds__(128) void gather_k(const float* __restrict__ bias, int chunk, int layer)
{
    float4* hout = (layer == 0) ? (float4*)d_h1 : (layer == 1) ? (float4*)d_h2 : (float4*)d_h3;
    const float4* hw = (const float4*)d_hw;

    int j   = blockIdx.x;
    int tid = threadIdx.x;          // 0..127
    int fo  = chunk * 128 + tid;    // float4 offset within node row

    float dj = d_dis[j];
    float di = d_dinv[j];
    float4 a = hw[j * 512 + fo];
    float4 acc;
    acc.x = a.x * di; acc.y = a.y * di; acc.z = a.z * di; acc.w = a.w * di;

    int s0 = d_rowptr[j], s1 = d_rowptr[j + 1];
    for (int k = s0; k < s1; k++) {
        int s = d_src[k];
        float w = d_dis[s] * dj;
        float4 v = hw[s * 512 + fo];
        acc.x = fmaf(w, v.x, acc.x);
        acc.y = fmaf(w, v.y, acc.y);
        acc.z = fmaf(w, v.z, acc.z);
        acc.w = fmaf(w, v.w, acc.w);
    }

    int h = (tid * 4) & 255;  // feature index within H=256
    acc.x = elu1(acc.x + bias[h]);
    acc.y = elu1(acc.y + bias[h + 1]);
    acc.z = elu1(acc.z + bias[h + 2]);
    acc.w = elu1(acc.w + bias[h + 3]);
    hout[j * 512 + fo] = acc;
}

// ------------------- g[b][n] = sum_l sum_h h_l[b,n,h] * fcW[3h+l] + fcb -------------------
__global__ __launch_bounds__(256) void g_k(const float* __restrict__ fcW, const float* __restrict__ fcb)
{
    int j = blockIdx.x;
    int b = threadIdx.x >> 5;
    int lane = threadIdx.x & 31;
    int base = (j * 8 + b) * 256;
    float s = 0.f;
    #pragma unroll
    for (int i = 0; i < 8; i++) {
        int h = lane + i * 32;
        s = fmaf(d_h1[base + h], fcW[3 * h],     s);
        s = fmaf(d_h2[base + h], fcW[3 * h + 1], s);
        s = fmaf(d_h3[base + h], fcW[3 * h + 2], s);
    }
    #pragma unroll
    for (int o = 16; o; o >>= 1) s += __shfl_xor_sync(0xffffffffu, s, o);
    if (lane == 0) d_g[b * NN + j] = s + fcb[0];
}

// ------------------- z = elu(g @ lin1_W + lin1_b), split-K -------------------
__global__ __launch_bounds__(256) void lin1_k(const float* __restrict__ W)
{
    int o = blockIdx.x * 256 + threadIdx.x;  // 0..511
    const int NS = (NN + 63) / 64;           // 237
    int n0 = blockIdx.y * NS;
    int n1 = n0 + NS; if (n1 > NN) n1 = NN;
    float acc[8];
    #pragma unroll
    for (int b = 0; b < 8; b++) acc[b] = 0.f;
    for (int n = n0; n < n1; n++) {
        float w = W[n * 512 + o];
        #pragma unroll
        for (int b = 0; b < 8; b++) acc[b] = fmaf(d_g[b * NN + n], w, acc[b]);
    }
    #pragma unroll
    for (int b = 0; b < 8; b++) atomicAdd(&d_zacc[b * 512 + o], acc[b]);
}

__global__ void lin1fin_k(const float* __restrict__ bias)
{
    int i = blockIdx.x * 256 + threadIdx.x;
    if (i >= BSZ * HFCC) return;
    d_z[i] = elu1(d_zacc[i] + bias[i & 511]);
}

// ------------------- out = log_softmax(z @ lin2_W + lin2_b) -------------------
__global__ void final_k(const float* __restrict__ W, const float* __restrict__ bv,
                        float* __restrict__ out)
{
    int b = threadIdx.x >> 5;
    int lane = threadIdx.x & 31;
    float a0 = 0.f, a1 = 0.f;
    for (int i = lane; i < 512; i += 32) {
        float z = d_z[b * 512 + i];
        a0 = fmaf(z, W[2 * i],     a0);
        a1 = fmaf(z, W[2 * i + 1], a1);
    }
    #pragma unroll
    for (int o = 16; o; o >>= 1) {
        a0 += __shfl_xor_sync(0xffffffffu, a0, o);
        a1 += __shfl_xor_sync(0xffffffffu, a1, o);
    }
    if (lane == 0) {
        float v0 = a0 + bv[0], v1 = a1 + bv[1];
        float m = fmaxf(v0, v1);
        float l = m + logf(expf(v0 - m) + expf(v1 - m));
        out[2 * b]     = v0 - l;
        out[2 * b + 1] = v1 - l;
    }
}

// ------------------- host launcher -------------------
extern "C" void kernel_launch(void* const* d_in, const int* in_sizes, int n_in,
                              void* d_out, int out_size)
{
    const float* x      = (const float*)d_in[0];
    // d_in[1] = batch (unused, all zeros)
    const void*  ei     = d_in[2];                 // int32 or int64, auto-detected
    const float* pe     = (const float*)d_in[3];
    const float* W1     = (const float*)d_in[4];
    const float* b1     = (const float*)d_in[5];
    const float* W2     = (const float*)d_in[6];
    const float* b2     = (const float*)d_in[7];
    const float* W3     = (const float*)d_in[8];
    const float* b3     = (const float*)d_in[9];
    const float* fcW    = (const float*)d_in[10];
    const float* fcb    = (const float*)d_in[11];
    const float* lin1W  = (const float*)d_in[12];
    const float* lin1b  = (const float*)d_in[13];
    const float* lin2W  = (const float*)d_in[14];
    const float* lin2b  = (const float*)d_in[15];
    float* out = (float*)d_out;

    // graph preprocessing
    zero_k<<<(NN + 255) / 256, 256>>>();
    edges_k<<<(EE + 255) / 256, 256>>>(ei);
    deg_k<<<(NN + 255) / 256, 256>>>();
    scan_k<<<1, 1024>>>();
    fill_k<<<(EE + 255) / 256, 256>>>();

    // input concat
    concat_k<<<(MM * K1 + 255) / 256, 256>>>(x, pe);

    dim3 ggrid(2, (MM + 127) / 128);

    // layer 1
    gemm_k<<<ggrid, 256>>>(W1, 0, K1);
    for (int c = 0; c < 4; c++) gather_k<<<NN, 128>>>(b1, c, 0);
    // layer 2
    gemm_k<<<ggrid, 256>>>(W2, 1, HH);
    for (int c = 0; c < 4; c++) gather_k<<<NN, 128>>>(b2, c, 1);
    // layer 3
    gemm_k<<<ggrid, 256>>>(W3, 2, HH);
    for (int c = 0; c < 4; c++) gather_k<<<NN, 128>>>(b3, c, 2);

    // head
    g_k<<<NN, 256>>>(fcW, fcb);
    {
        dim3 lg(2, 64);
        lin1_k<<<lg, 256>>>(lin1W);
    }
    lin1fin_k<<<16, 256>>>(lin1b);
    final_k<<<1, 256>>>(lin2W, lin2b, out);
}

// round 6
// speedup vs baseline: 1.2467x; 1.2467x over previous
#include <cuda_runtime.h>
#include <cuda_bf16.h>
#include <math.h>
#include <stdint.h>

// Problem constants (fixed shapes)
#define NN   15135
#define BSZ  8
#define FF   64
#define GG   73
#define HH   256
#define EE   242160
#define MM   (NN*BSZ)       // 121080 rows
#define K1   (FF+GG)        // 137
#define K1P  160            // padded to multiple of 32
#define HFCC 512

// ------------------- scratch (device globals; no allocation) -------------------
__device__ __align__(16) float d_hw[MM*HH];     // GEMM output (pre-aggregation)
__device__ __align__(16) float d_h1[MM*HH];
__device__ __align__(16) float d_h2[MM*HH];
__device__ __align__(16) float d_h3[MM*HH];
// bf16 hi/lo GEMM operands
__device__ __align__(16) __nv_bfloat16 d_a0hi[MM*K1P];
__device__ __align__(16) __nv_bfloat16 d_a0lo[MM*K1P];
__device__ __align__(16) __nv_bfloat16 d_ahi[MM*HH];
__device__ __align__(16) __nv_bfloat16 d_alo[MM*HH];
__device__ __align__(16) __nv_bfloat16 d_w0hi[HH*K1P];
__device__ __align__(16) __nv_bfloat16 d_w0lo[HH*K1P];
__device__ __align__(16) __nv_bfloat16 d_w1hi[HH*HH];
__device__ __align__(16) __nv_bfloat16 d_w1lo[HH*HH];
__device__ __align__(16) __nv_bfloat16 d_w2hi[HH*HH];
__device__ __align__(16) __nv_bfloat16 d_w2lo[HH*HH];

__device__ float d_dis[NN];
__device__ float d_dinv[NN];
__device__ int   d_cnt[NN];
__device__ int   d_rowptr[NN+1];
__device__ int   d_cursor[NN];
__device__ int   d_src[EE];
__device__ int   d_row32[EE];
__device__ int   d_col32[EE];
__device__ float d_g[BSZ*NN];
__device__ float d_zacc[BSZ*HFCC];
__device__ float d_z[BSZ*HFCC];

__device__ __forceinline__ float elu1(float x) { return x > 0.f ? x : expm1f(x); }

__device__ __forceinline__ uint32_t smem_u32(const void* p) {
    uint32_t a;
    asm("{ .reg .u64 t; cvta.to.shared.u64 t, %1; cvt.u32.u64 %0, t; }" : "=r"(a) : "l"(p));
    return a;
}
__device__ __forceinline__ void ldm_x4(uint32_t& r0, uint32_t& r1, uint32_t& r2, uint32_t& r3, uint32_t addr)
{
    asm volatile("ldmatrix.sync.aligned.m8n8.x4.shared.b16 {%0,%1,%2,%3}, [%4];"
                 : "=r"(r0), "=r"(r1), "=r"(r2), "=r"(r3) : "r"(addr));
}
__device__ __forceinline__ void mma16816(float* c, uint32_t a0, uint32_t a1, uint32_t a2, uint32_t a3,
                                         uint32_t b0, uint32_t b1)
{
    asm volatile(
        "mma.sync.aligned.m16n8k16.row.col.f32.bf16.bf16.f32 "
        "{%0,%1,%2,%3}, {%4,%5,%6,%7}, {%8,%9}, {%0,%1,%2,%3};"
        : "+f"(c[0]), "+f"(c[1]), "+f"(c[2]), "+f"(c[3])
        : "r"(a0), "r"(a1), "r"(a2), "r"(a3), "r"(b0), "r"(b1));
}

// ------------------- graph preprocessing -------------------
__global__ void zero_k()
{
    int i = blockIdx.x * 256 + threadIdx.x;
    if (i < NN) { d_cnt[i] = 0; d_cursor[i] = 0; }
    if (i < BSZ*HFCC) d_zacc[i] = 0.f;
}

// edge_index may be int64 or int32 (auto-detect).
__global__ void edges_k(const void* __restrict__ ei_raw)
{
    __shared__ int is64;
    const int* ei32 = (const int*)ei_raw;
    if (threadIdx.x == 0) {
        int allz = 1;
        for (int i = 0; i < 64; i++) if (ei32[2 * i + 1] != 0) { allz = 0; break; }
        is64 = allz;
    }
    __syncthreads();

    int e = blockIdx.x * 256 + threadIdx.x;
    if (e >= EE) return;
    int r, c;
    if (is64) {
        const long long* ei = (const long long*)ei_raw;
        r = (int)ei[e];
        c = (int)ei[EE + e];
    } else {
        r = ei32[e];
        c = ei32[EE + e];
    }
    d_row32[e] = r;
    d_col32[e] = c;
    atomicAdd(&d_cnt[c], 1);
}

__global__ void deg_k()
{
    int j = blockIdx.x * 256 + threadIdx.x;
    if (j >= NN) return;
    float dg = (float)d_cnt[j] + 1.0f;
    d_dis[j]  = rsqrtf(dg);
    d_dinv[j] = 1.0f / dg;
}

// exclusive scan d_cnt -> d_rowptr, 1024 threads, 15 elems/thread, shuffle scan
__global__ void scan_k()
{
    __shared__ int wsum[32];
    int t = threadIdx.x, lane = t & 31, w = t >> 5;
    int base = t * 15;
    int v[15];
    int s = 0;
    #pragma unroll
    for (int i = 0; i < 15; i++) {
        int idx = base + i;
        v[i] = (idx < NN) ? d_cnt[idx] : 0;
        s += v[i];
    }
    int ps = s;
    #pragma unroll
    for (int o = 1; o < 32; o <<= 1) {
        int u = __shfl_up_sync(0xffffffffu, ps, o);
        if (lane >= o) ps += u;
    }
    if (lane == 31) wsum[w] = ps;
    __syncthreads();
    if (w == 0) {
        int ws = wsum[lane];
        #pragma unroll
        for (int o = 1; o < 32; o <<= 1) {
            int u = __shfl_up_sync(0xffffffffu, ws, o);
            if (lane >= o) ws += u;
        }
        wsum[lane] = ws;
    }
    __syncthreads();
    int prefix = ps - s + (w > 0 ? wsum[w - 1] : 0);
    #pragma unroll
    for (int i = 0; i < 15; i++) {
        int idx = base + i;
        if (idx <= NN) d_rowptr[idx] = prefix;
        prefix += v[i];
    }
}

__global__ void fill_k()
{
    int e = blockIdx.x * 256 + threadIdx.x;
    if (e >= EE) return;
    int c = d_col32[e];
    int p = atomicAdd(&d_cursor[c], 1);
    d_src[d_rowptr[c] + p] = d_row32[e];
}

// ------------------- input concat -> bf16 hi/lo, padded K=160 -------------------
__global__ void concat_k(const float* __restrict__ x, const float* __restrict__ pe)
{
    int idx = blockIdx.x * 256 + threadIdx.x;
    if (idx >= MM * K1P) return;
    int r = idx / K1P;
    int k = idx - r * K1P;
    int n = r >> 3, b = r & 7;
    float v = 0.f;
    if (k < FF) v = x[(b * NN + n) * FF + k];
    else if (k < K1) v = pe[n * GG + (k - FF)];
    __nv_bfloat16 h = __float2bfloat16(v);
    d_a0hi[idx] = h;
    d_a0lo[idx] = __float2bfloat16(v - __bfloat162float(h));
}

// ------------------- weight transpose + bf16 hi/lo split: [K,256] -> [256,Kpad] -------------------
__global__ void convw_k(const float* __restrict__ W, __nv_bfloat16* __restrict__ hi,
                        __nv_bfloat16* __restrict__ lo, int K, int Kpad)
{
    int idx = blockIdx.x * 256 + threadIdx.x;
    if (idx >= HH * Kpad) return;
    int n = idx / Kpad, k = idx - n * Kpad;
    float v = (k < K) ? W[k * HH + n] : 0.f;
    __nv_bfloat16 h = __float2bfloat16(v);
    hi[idx] = h;
    lo[idx] = __float2bfloat16(v - __bfloat162float(h));
}

// ------------------- mma.sync bf16 hi/lo GEMM: d_hw[M,256] = A @ W^T -------------------
// A [M][Kpad] bf16 hi/lo; W [256 n][Kpad k] bf16 hi/lo. Grid (946, 2): CTA tile 128m x 128n.
// 8 warps: warp tile 32m x 64n. K chunks of 32 in SMEM (stride-40 rows, conflict-free ldmatrix).
#define ASTRIDE 40
__global__ __launch_bounds__(256) void mma_gemm_k(
    const __nv_bfloat16* __restrict__ Ahi, const __nv_bfloat16* __restrict__ Alo,
    const __nv_bfloat16* __restrict__ Whi, const __nv_bfloat16* __restrict__ Wlo,
    int Kpad)
{
    __shared__ __align__(16) __nv_bfloat16 AsH[128 * ASTRIDE];
    __shared__ __align__(16) __nv_bfloat16 AsL[128 * ASTRIDE];
    __shared__ __align__(16) __nv_bfloat16 BsH[128 * ASTRIDE];
    __shared__ __align__(16) __nv_bfloat16 BsL[128 * ASTRIDE];

    int tid = threadIdx.x, wid = tid >> 5, lane = tid & 31;
    int rowBase = blockIdx.x * 128;
    int colBase = blockIdx.y * 128;
    int wm = wid >> 1, wn = wid & 1;
    int m0 = wm * 32, n0 = wn * 64;

    float acc[2][8][4];
    #pragma unroll
    for (int i = 0; i < 2; i++)
        #pragma unroll
        for (int j = 0; j < 8; j++)
            #pragma unroll
            for (int q = 0; q < 4; q++) acc[i][j][q] = 0.f;

    int nch = Kpad >> 5;
    for (int c = 0; c < nch; c++) {
        int k0 = c * 32;
        // ---- load A (128 rows x 32 k, hi+lo) ----
        #pragma unroll
        for (int i = tid; i < 512; i += 256) {
            int r = i >> 2, q = i & 3;
            int grow = rowBase + r;
            uint4 vh = make_uint4(0u, 0u, 0u, 0u), vl = vh;
            if (grow < MM) {
                const __nv_bfloat16* pH = Ahi + (size_t)grow * Kpad + k0 + q * 8;
                const __nv_bfloat16* pL = Alo + (size_t)grow * Kpad + k0 + q * 8;
                vh = *(const uint4*)pH;
                vl = *(const uint4*)pL;
            }
            int off = r * ASTRIDE + q * 8;
            *(uint4*)(AsH + off) = vh;
            *(uint4*)(AsL + off) = vl;
        }
        // ---- load B (128 n-rows x 32 k, hi+lo) ----
        #pragma unroll
        for (int i = tid; i < 512; i += 256) {
            int r = i >> 2, q = i & 3;
            int gn = colBase + r;
            uint4 vh = *(const uint4*)(Whi + (size_t)gn * Kpad + k0 + q * 8);
            uint4 vl = *(const uint4*)(Wlo + (size_t)gn * Kpad + k0 + q * 8);
            int off = r * ASTRIDE + q * 8;
            *(uint4*)(BsH + off) = vh;
            *(uint4*)(BsL + off) = vl;
        }
        __syncthreads();

        // ---- two k16 steps ----
        #pragma unroll
        for (int s = 0; s < 2; s++) {
            int kk = s * 16;
            // A fragments (2 m16 tiles, hi+lo)
            uint32_t ah[2][4], al[2][4];
            {
                int t = lane >> 3, rr = lane & 7;
                int arow = ((t & 1) << 3) + rr;
                int acol = kk + ((t >> 1) << 3);
                #pragma unroll
                for (int mt = 0; mt < 2; mt++) {
                    uint32_t ad = smem_u32(&AsH[(m0 + mt * 16 + arow) * ASTRIDE + acol]);
                    ldm_x4(ah[mt][0], ah[mt][1], ah[mt][2], ah[mt][3], ad);
                    uint32_t ad2 = smem_u32(&AsL[(m0 + mt * 16 + arow) * ASTRIDE + acol]);
                    ldm_x4(al[mt][0], al[mt][1], al[mt][2], al[mt][3], ad2);
                }
            }
            // B fragments (4 x n16 = 8 n8 tiles, hi+lo)
            uint32_t bh[8][2], bl[8][2];
            {
                int brow = (((lane >> 4) & 1) << 3) + (lane & 7);
                int bcol = kk + (((lane >> 3) & 1) << 3);
                #pragma unroll
                for (int nt = 0; nt < 4; nt++) {
                    uint32_t bd = smem_u32(&BsH[(n0 + nt * 16 + brow) * ASTRIDE + bcol]);
                    uint32_t r0, r1, r2, r3;
                    ldm_x4(r0, r1, r2, r3, bd);
                    bh[nt * 2][0] = r0; bh[nt * 2][1] = r1;
                    bh[nt * 2 + 1][0] = r2; bh[nt * 2 + 1][1] = r3;
                    uint32_t bd2 = smem_u32(&BsL[(n0 + nt * 16 + brow) * ASTRIDE + bcol]);
                    ldm_x4(r0, r1, r2, r3, bd2);
                    bl[nt * 2][0] = r0; bl[nt * 2][1] = r1;
                    bl[nt * 2 + 1][0] = r2; bl[nt * 2 + 1][1] = r3;
                }
            }
            #pragma unroll
            for (int mt = 0; mt < 2; mt++)
                #pragma unroll
                for (int nt = 0; nt < 8; nt++) {
                    mma16816(acc[mt][nt], ah[mt][0], ah[mt][1], ah[mt][2], ah[mt][3], bh[nt][0], bh[nt][1]);
                    mma16816(acc[mt][nt], ah[mt][0], ah[mt][1], ah[mt][2], ah[mt][3], bl[nt][0], bl[nt][1]);
                    mma16816(acc[mt][nt], al[mt][0], al[mt][1], al[mt][2], al[mt][3], bh[nt][0], bh[nt][1]);
                }
        }
        __syncthreads();
    }

    // ---- epilogue ----
    int g = lane >> 2, tig = lane & 3;
    #pragma unroll
    for (int mt = 0; mt < 2; mt++) {
        int r0 = rowBase + m0 + mt * 16 + g;
        int r1 = r0 + 8;
        #pragma unroll
        for (int nt = 0; nt < 8; nt++) {
            int col = colBase + n0 + nt * 8 + tig * 2;
            if (r0 < MM) *(float2*)(d_hw + (size_t)r0 * 256 + col) = make_float2(acc[mt][nt][0], acc[mt][nt][1]);
            if (r1 < MM) *(float2*)(d_hw + (size_t)r1 * 256 + col) = make_float2(acc[mt][nt][2], acc[mt][nt][3]);
        }
    }
}

// ------------------- CSR gather + self-loop + bias + ELU (per feature chunk) -------------------
// Also emits bf16 hi/lo copy for next layer's GEMM (layers 0,1).
__global__ __launch_bounds__(128) void gather_k(const float* __restrict__ bias, int chunk, int layer)
{
    float4* hout = (layer == 0) ? (float4*)d_h1 : (layer == 1) ? (float4*)d_h2 : (float4*)d_h3;
    const float4* hw = (const float4*)d_hw;

    int j   = blockIdx.x;
    int tid = threadIdx.x;          // 0..127
    int fo  = chunk * 128 + tid;    // float4 offset within node row (512 per node)

    float dj = d_dis[j];
    float di = d_dinv[j];
    float4 a = hw[j * 512 + fo];
    float4 acc;
    acc.x = a.x * di; acc.y = a.y * di; acc.z = a.z * di; acc.w = a.w * di;

    int s0 = d_rowptr[j], s1 = d_rowptr[j + 1];
    for (int k = s0; k < s1; k++) {
        int s = d_src[k];
        float w = d_dis[s] * dj;
        float4 v = hw[s * 512 + fo];
        acc.x = fmaf(w, v.x, acc.x);
        acc.y = fmaf(w, v.y, acc.y);
        acc.z = fmaf(w, v.z, acc.z);
        acc.w = fmaf(w, v.w, acc.w);
    }

    int h = (tid & 63) * 4;         // feature index within H=256
    acc.x = elu1(acc.x + bias[h]);
    acc.y = elu1(acc.y + bias[h + 1]);
    acc.z = elu1(acc.z + bias[h + 2]);
    acc.w = elu1(acc.w + bias[h + 3]);
    hout[j * 512 + fo] = acc;

    if (layer < 2) {
        int b = fo >> 6;
        size_t row = (size_t)(j * 8 + b) * 256 + h;
        __nv_bfloat162 h0, h1, l0, l1;
        h0.x = __float2bfloat16(acc.x); h0.y = __float2bfloat16(acc.y);
        h1.x = __float2bfloat16(acc.z); h1.y = __float2bfloat16(acc.w);
        l0.x = __float2bfloat16(acc.x - __bfloat162float(h0.x));
        l0.y = __float2bfloat16(acc.y - __bfloat162float(h0.y));
        l1.x = __float2bfloat16(acc.z - __bfloat162float(h1.x));
        l1.y = __float2bfloat16(acc.w - __bfloat162float(h1.y));
        *(__nv_bfloat162*)(d_ahi + row)     = h0;
        *(__nv_bfloat162*)(d_ahi + row + 2) = h1;
        *(__nv_bfloat162*)(d_alo + row)     = l0;
        *(__nv_bfloat162*)(d_alo + row + 2) = l1;
    }
}

// ------------------- g[b][n] = sum_l sum_h h_l[b,n,h] * fcW[3h+l] + fcb -------------------
__global__ __launch_bounds__(256) void g_k(const float* __restrict__ fcW, const float* __restrict__ fcb)
{
    int j = blockIdx.x;
    int b = threadIdx.x >> 5;
    int lane = threadIdx.x & 31;
    int base = (j * 8 + b) * 256;
    float s = 0.f;
    #pragma unroll
    for (int i = 0; i < 8; i++) {
        int h = lane + i * 32;
        s = fmaf(d_h1[base + h], fcW[3 * h],     s);
        s = fmaf(d_h2[base + h], fcW[3 * h + 1], s);
        s = fmaf(d_h3[base + h], fcW[3 * h + 2], s);
    }
    #pragma unroll
    for (int o = 16; o; o >>= 1) s += __shfl_xor_sync(0xffffffffu, s, o);
    if (lane == 0) d_g[b * NN + j] = s + fcb[0];
}

// ------------------- z = elu(g @ lin1_W + lin1_b), split-K -------------------
__global__ __launch_bounds__(256) void lin1_k(const float* __restrict__ W)
{
    int o = blockIdx.x * 256 + threadIdx.x;  // 0..511
    const int NS = (NN + 63) / 64;           // 237
    int n0 = blockIdx.y * NS;
    int n1 = n0 + NS; if (n1 > NN) n1 = NN;
    float acc[8];
    #pragma unroll
    for (int b = 0; b < 8; b++) acc[b] = 0.f;
    for (int n = n0; n < n1; n++) {
        float w = W[n * 512 + o];
        #pragma unroll
        for (int b = 0; b < 8; b++) acc[b] = fmaf(d_g[b * NN + n], w, acc[b]);
    }
    #pragma unroll
    for (int b = 0; b < 8; b++) atomicAdd(&d_zacc[b * 512 + o], acc[b]);
}

__global__ void lin1fin_k(const float* __restrict__ bias)
{
    int i = blockIdx.x * 256 + threadIdx.x;
    if (i >= BSZ * HFCC) return;
    d_z[i] = elu1(d_zacc[i] + bias[i & 511]);
}

// ------------------- out = log_softmax(z @ lin2_W + lin2_b) -------------------
__global__ void final_k(const float* __restrict__ W, const float* __restrict__ bv,
                        float* __restrict__ out)
{
    int b = threadIdx.x >> 5;
    int lane = threadIdx.x & 31;
    float a0 = 0.f, a1 = 0.f;
    for (int i = lane; i < 512; i += 32) {
        float z = d_z[b * 512 + i];
        a0 = fmaf(z, W[2 * i],     a0);
        a1 = fmaf(z, W[2 * i + 1], a1);
    }
    #pragma unroll
    for (int o = 16; o; o >>= 1) {
        a0 += __shfl_xor_sync(0xffffffffu, a0, o);
        a1 += __shfl_xor_sync(0xffffffffu, a1, o);
    }
    if (lane == 0) {
        float v0 = a0 + bv[0], v1 = a1 + bv[1];
        float m = fmaxf(v0, v1);
        float l = m + logf(expf(v0 - m) + expf(v1 - m));
        out[2 * b]     = v0 - l;
        out[2 * b + 1] = v1 - l;
    }
}

// ------------------- host launcher -------------------
extern "C" void kernel_launch(void* const* d_in, const int* in_sizes, int n_in,
                              void* d_out, int out_size)
{
    const float* x      = (const float*)d_in[0];
    // d_in[1] = batch (unused, all zeros)
    const void*  ei     = d_in[2];                 // int32 or int64, auto-detected
    const float* pe     = (const float*)d_in[3];
    const float* W1     = (const float*)d_in[4];
    const float* b1     = (const float*)d_in[5];
    const float* W2     = (const float*)d_in[6];
    const float* b2     = (const float*)d_in[7];
    const float* W3     = (const float*)d_in[8];
    const float* b3     = (const float*)d_in[9];
    const float* fcW    = (const float*)d_in[10];
    const float* fcb    = (const float*)d_in[11];
    const float* lin1W  = (const float*)d_in[12];
    const float* lin1b  = (const float*)d_in[13];
    const float* lin2W  = (const float*)d_in[14];
    const float* lin2b  = (const float*)d_in[15];
    float* out = (float*)d_out;

    // resolve device-global addresses for kernel args
    __nv_bfloat16 *a0hi, *a0lo, *ahi, *alo, *w0hi, *w0lo, *w1hi, *w1lo, *w2hi, *w2lo;
    cudaGetSymbolAddress((void**)&a0hi, d_a0hi);
    cudaGetSymbolAddress((void**)&a0lo, d_a0lo);
    cudaGetSymbolAddress((void**)&ahi,  d_ahi);
    cudaGetSymbolAddress((void**)&alo,  d_alo);
    cudaGetSymbolAddress((void**)&w0hi, d_w0hi);
    cudaGetSymbolAddress((void**)&w0lo, d_w0lo);
    cudaGetSymbolAddress((void**)&w1hi, d_w1hi);
    cudaGetSymbolAddress((void**)&w1lo, d_w1lo);
    cudaGetSymbolAddress((void**)&w2hi, d_w2hi);
    cudaGetSymbolAddress((void**)&w2lo, d_w2lo);

    // graph preprocessing
    zero_k<<<(NN + 255) / 256, 256>>>();
    edges_k<<<(EE + 255) / 256, 256>>>(ei);
    deg_k<<<(NN + 255) / 256, 256>>>();
    scan_k<<<1, 1024>>>();
    fill_k<<<(EE + 255) / 256, 256>>>();

    // operand conversion
    concat_k<<<(MM * K1P + 255) / 256, 256>>>(x, pe);
    convw_k<<<(HH * K1P + 255) / 256, 256>>>(W1, w0hi, w0lo, K1, K1P);
    convw_k<<<(HH * HH + 255) / 256, 256>>>(W2, w1hi, w1lo, HH, HH);
    convw_k<<<(HH * HH + 255) / 256, 256>>>(W3, w2hi, w2lo, HH, HH);

    const int MTILES = (MM + 127) / 128;  // 946
    dim3 ggrid(MTILES, 2);

    // layer 1
    mma_gemm_k<<<ggrid, 256>>>(a0hi, a0lo, w0hi, w0lo, K1P);
    for (int c = 0; c < 4; c++) gather_k<<<NN, 128>>>(b1, c, 0);
    // layer 2
    mma_gemm_k<<<ggrid, 256>>>(ahi, alo, w1hi, w1lo, HH);
    for (int c = 0; c < 4; c++) gather_k<<<NN, 128>>>(b2, c, 1);
    // layer 3
    mma_gemm_k<<<ggrid, 256>>>(ahi, alo, w2hi, w2lo, HH);
    for (int c = 0; c < 4; c++) gather_k<<<NN, 128>>>(b3, c, 2);

    // head
    g_k<<<NN, 256>>>(fcW, fcb);
    {
        dim3 lg(2, 64);
        lin1_k<<<lg, 256>>>(lin1W);
    }
    lin1fin_k<<<16, 256>>>(lin1b);
    final_k<<<1, 256>>>(lin2W, lin2b, out);
}

// round 7
// speedup vs baseline: 1.6748x; 1.3434x over previous
#include <cuda_runtime.h>
#include <cuda_bf16.h>
#include <math.h>
#include <stdint.h>

// Problem constants (fixed shapes)
#define NN   15135
#define BSZ  8
#define FF   64
#define GG   73
#define HH   256
#define EE   242160
#define MM   (NN*BSZ)       // 121080 rows
#define K1   (FF+GG)        // 137
#define K1P  160            // padded to multiple of 32
#define HFCC 512

// ------------------- scratch (device globals; no allocation) -------------------
__device__ __align__(16) float d_hw[MM*HH];     // GEMM output (pre-aggregation)
__device__ __align__(16) float d_h1[MM*HH];
__device__ __align__(16) float d_h2[MM*HH];
__device__ __align__(16) float d_h3[MM*HH];
// bf16 hi/lo GEMM operands
__device__ __align__(16) __nv_bfloat16 d_a0hi[MM*K1P];
__device__ __align__(16) __nv_bfloat16 d_a0lo[MM*K1P];
__device__ __align__(16) __nv_bfloat16 d_ahi[MM*HH];
__device__ __align__(16) __nv_bfloat16 d_alo[MM*HH];
__device__ __align__(16) __nv_bfloat16 d_w0hi[HH*K1P];
__device__ __align__(16) __nv_bfloat16 d_w0lo[HH*K1P];
__device__ __align__(16) __nv_bfloat16 d_w1hi[HH*HH];
__device__ __align__(16) __nv_bfloat16 d_w1lo[HH*HH];
__device__ __align__(16) __nv_bfloat16 d_w2hi[HH*HH];
__device__ __align__(16) __nv_bfloat16 d_w2lo[HH*HH];

__device__ float d_dis[NN];
__device__ float d_dinv[NN];
__device__ int   d_cnt[NN];
__device__ int   d_rowptr[NN+1];
__device__ int   d_cursor[NN];
__device__ int   d_src[EE];
__device__ int   d_row32[EE];
__device__ int   d_col32[EE];
__device__ float d_g[BSZ*NN];
__device__ float d_zacc[BSZ*HFCC];
__device__ float d_z[BSZ*HFCC];

__device__ __forceinline__ float elu1(float x) { return x > 0.f ? x : expm1f(x); }

__device__ __forceinline__ uint32_t smem_u32(const void* p) {
    uint32_t a;
    asm("{ .reg .u64 t; cvta.to.shared.u64 t, %1; cvt.u32.u64 %0, t; }" : "=r"(a) : "l"(p));
    return a;
}
__device__ __forceinline__ void ldm_x4(uint32_t& r0, uint32_t& r1, uint32_t& r2, uint32_t& r3, uint32_t addr)
{
    asm volatile("ldmatrix.sync.aligned.m8n8.x4.shared.b16 {%0,%1,%2,%3}, [%4];"
                 : "=r"(r0), "=r"(r1), "=r"(r2), "=r"(r3) : "r"(addr));
}
__device__ __forceinline__ void mma16816(float* c, uint32_t a0, uint32_t a1, uint32_t a2, uint32_t a3,
                                         uint32_t b0, uint32_t b1)
{
    asm volatile(
        "mma.sync.aligned.m16n8k16.row.col.f32.bf16.bf16.f32 "
        "{%0,%1,%2,%3}, {%4,%5,%6,%7}, {%8,%9}, {%0,%1,%2,%3};"
        : "+f"(c[0]), "+f"(c[1]), "+f"(c[2]), "+f"(c[3])
        : "r"(a0), "r"(a1), "r"(a2), "r"(a3), "r"(b0), "r"(b1));
}
__device__ __forceinline__ void cp16(uint32_t dst, const void* src, uint32_t srcsize)
{
    asm volatile("cp.async.cg.shared.global [%0], [%1], 16, %2;"
                 :: "r"(dst), "l"(src), "r"(srcsize) : "memory");
}
__device__ __forceinline__ void cp_commit() { asm volatile("cp.async.commit_group;" ::: "memory"); }

// ------------------- graph preprocessing -------------------
__global__ void zero_k()
{
    int i = blockIdx.x * 256 + threadIdx.x;
    if (i < NN) { d_cnt[i] = 0; d_cursor[i] = 0; }
    if (i < BSZ*HFCC) d_zacc[i] = 0.f;
}

// edge_index may be int64 or int32 (auto-detect).
__global__ void edges_k(const void* __restrict__ ei_raw)
{
    __shared__ int is64;
    const int* ei32 = (const int*)ei_raw;
    if (threadIdx.x == 0) {
        int allz = 1;
        for (int i = 0; i < 64; i++) if (ei32[2 * i + 1] != 0) { allz = 0; break; }
        is64 = allz;
    }
    __syncthreads();

    int e = blockIdx.x * 256 + threadIdx.x;
    if (e >= EE) return;
    int r, c;
    if (is64) {
        const long long* ei = (const long long*)ei_raw;
        r = (int)ei[e];
        c = (int)ei[EE + e];
    } else {
        r = ei32[e];
        c = ei32[EE + e];
    }
    d_row32[e] = r;
    d_col32[e] = c;
    atomicAdd(&d_cnt[c], 1);
}

__global__ void deg_k()
{
    int j = blockIdx.x * 256 + threadIdx.x;
    if (j >= NN) return;
    float dg = (float)d_cnt[j] + 1.0f;
    d_dis[j]  = rsqrtf(dg);
    d_dinv[j] = 1.0f / dg;
}

// exclusive scan d_cnt -> d_rowptr, 1024 threads, 15 elems/thread, shuffle scan
__global__ void scan_k()
{
    __shared__ int wsum[32];
    int t = threadIdx.x, lane = t & 31, w = t >> 5;
    int base = t * 15;
    int v[15];
    int s = 0;
    #pragma unroll
    for (int i = 0; i < 15; i++) {
        int idx = base + i;
        v[i] = (idx < NN) ? d_cnt[idx] : 0;
        s += v[i];
    }
    int ps = s;
    #pragma unroll
    for (int o = 1; o < 32; o <<= 1) {
        int u = __shfl_up_sync(0xffffffffu, ps, o);
        if (lane >= o) ps += u;
    }
    if (lane == 31) wsum[w] = ps;
    __syncthreads();
    if (w == 0) {
        int ws = wsum[lane];
        #pragma unroll
        for (int o = 1; o < 32; o <<= 1) {
            int u = __shfl_up_sync(0xffffffffu, ws, o);
            if (lane >= o) ws += u;
        }
        wsum[lane] = ws;
    }
    __syncthreads();
    int prefix = ps - s + (w > 0 ? wsum[w - 1] : 0);
    #pragma unroll
    for (int i = 0; i < 15; i++) {
        int idx = base + i;
        if (idx <= NN) d_rowptr[idx] = prefix;
        prefix += v[i];
    }
}

__global__ void fill_k()
{
    int e = blockIdx.x * 256 + threadIdx.x;
    if (e >= EE) return;
    int c = d_col32[e];
    int p = atomicAdd(&d_cursor[c], 1);
    d_src[d_rowptr[c] + p] = d_row32[e];
}

// ------------------- input concat -> bf16 hi/lo, padded K=160 -------------------
__global__ void concat_k(const float* __restrict__ x, const float* __restrict__ pe)
{
    int idx = blockIdx.x * 256 + threadIdx.x;
    if (idx >= MM * K1P) return;
    int r = idx / K1P;
    int k = idx - r * K1P;
    int n = r >> 3, b = r & 7;
    float v = 0.f;
    if (k < FF) v = x[(b * NN + n) * FF + k];
    else if (k < K1) v = pe[n * GG + (k - FF)];
    __nv_bfloat16 h = __float2bfloat16(v);
    d_a0hi[idx] = h;
    d_a0lo[idx] = __float2bfloat16(v - __bfloat162float(h));
}

// ------------------- weight transpose + bf16 hi/lo split: [K,256] -> [256,Kpad] -------------------
__global__ void convw_k(const float* __restrict__ W, __nv_bfloat16* __restrict__ hi,
                        __nv_bfloat16* __restrict__ lo, int K, int Kpad)
{
    int idx = blockIdx.x * 256 + threadIdx.x;
    if (idx >= HH * Kpad) return;
    int n = idx / Kpad, k = idx - n * Kpad;
    float v = (k < K) ? W[k * HH + n] : 0.f;
    __nv_bfloat16 h = __float2bfloat16(v);
    hi[idx] = h;
    lo[idx] = __float2bfloat16(v - __bfloat162float(h));
}

// ------------------- mma.sync bf16 hi/lo GEMM with cp.async double buffering ---------
// d_hw[M,256] = A @ W^T.  A [M][Kpad] bf16 hi/lo; W [256 n][Kpad k] bf16 hi/lo.
// Grid (946, 2): CTA tile 128m x 128n. 8 warps: warp tile 32m x 64n.
// K chunks of 32 staged in dynamic SMEM, 2 stages (stride-40 rows, conflict-free ldmatrix).
#define ASTRIDE 40
#define TILE_B  (128 * ASTRIDE * 2)    // 10240 bytes per operand tile
#define STAGE_B (4 * TILE_B)           // 40960 bytes per stage
#define GEMM_DSMEM (2 * STAGE_B)       // 81920

__global__ __launch_bounds__(256) void mma_gemm_k(
    const __nv_bfloat16* __restrict__ Ahi, const __nv_bfloat16* __restrict__ Alo,
    const __nv_bfloat16* __restrict__ Whi, const __nv_bfloat16* __restrict__ Wlo,
    int Kpad)
{
    extern __shared__ char dsm[];
    uint32_t dsm_b = smem_u32(dsm);

    int tid = threadIdx.x, wid = tid >> 5, lane = tid & 31;
    int rowBase = blockIdx.x * 128;
    int colBase = blockIdx.y * 128;
    int wm = wid >> 1, wn = wid & 1;
    int m0 = wm * 32, n0 = wn * 64;

    float acc[2][8][4];
    #pragma unroll
    for (int i = 0; i < 2; i++)
        #pragma unroll
        for (int j = 0; j < 8; j++)
            #pragma unroll
            for (int q = 0; q < 4; q++) acc[i][j][q] = 0.f;

    int nch = Kpad >> 5;

    // precompute per-thread load coordinates (2 iters of i = tid, tid+256)
    // i -> r = i>>2 (row 0..127), q = i&3 (16B group within 64B row)
    auto load_chunk = [&](int c, int st) {
        int k0 = c * 32;
        uint32_t sbase = dsm_b + st * STAGE_B;
        #pragma unroll
        for (int ii = 0; ii < 2; ii++) {
            int i = tid + ii * 256;
            int r = i >> 2, q = i & 3;
            uint32_t doff = (uint32_t)(r * (ASTRIDE * 2) + q * 16);
            // A hi/lo
            int grow = rowBase + r;
            uint32_t ok = (grow < MM) ? 16u : 0u;
            int gr = (grow < MM) ? grow : 0;
            const __nv_bfloat16* pH = Ahi + (size_t)gr * Kpad + k0 + q * 8;
            const __nv_bfloat16* pL = Alo + (size_t)gr * Kpad + k0 + q * 8;
            cp16(sbase + doff,              pH, ok);
            cp16(sbase + TILE_B + doff,     pL, ok);
            // B hi/lo (always in range)
            int gn = colBase + r;
            cp16(sbase + 2 * TILE_B + doff, Whi + (size_t)gn * Kpad + k0 + q * 8, 16u);
            cp16(sbase + 3 * TILE_B + doff, Wlo + (size_t)gn * Kpad + k0 + q * 8, 16u);
        }
        cp_commit();
    };

    load_chunk(0, 0);

    for (int c = 0; c < nch; c++) {
        if (c + 1 < nch) {
            load_chunk(c + 1, (c + 1) & 1);
            asm volatile("cp.async.wait_group 1;" ::: "memory");
        } else {
            asm volatile("cp.async.wait_group 0;" ::: "memory");
        }
        __syncthreads();

        char* stg = dsm + (c & 1) * STAGE_B;
        __nv_bfloat16* AsH = (__nv_bfloat16*)(stg);
        __nv_bfloat16* AsL = (__nv_bfloat16*)(stg + TILE_B);
        __nv_bfloat16* BsH = (__nv_bfloat16*)(stg + 2 * TILE_B);
        __nv_bfloat16* BsL = (__nv_bfloat16*)(stg + 3 * TILE_B);

        #pragma unroll
        for (int s = 0; s < 2; s++) {
            int kk = s * 16;
            uint32_t ah[2][4], al[2][4];
            {
                int t = lane >> 3, rr = lane & 7;
                int arow = ((t & 1) << 3) + rr;
                int acol = kk + ((t >> 1) << 3);
                #pragma unroll
                for (int mt = 0; mt < 2; mt++) {
                    uint32_t ad = smem_u32(&AsH[(m0 + mt * 16 + arow) * ASTRIDE + acol]);
                    ldm_x4(ah[mt][0], ah[mt][1], ah[mt][2], ah[mt][3], ad);
                    uint32_t ad2 = smem_u32(&AsL[(m0 + mt * 16 + arow) * ASTRIDE + acol]);
                    ldm_x4(al[mt][0], al[mt][1], al[mt][2], al[mt][3], ad2);
                }
            }
            uint32_t bh[8][2], bl[8][2];
            {
                int brow = (((lane >> 4) & 1) << 3) + (lane & 7);
                int bcol = kk + (((lane >> 3) & 1) << 3);
                #pragma unroll
                for (int nt = 0; nt < 4; nt++) {
                    uint32_t bd = smem_u32(&BsH[(n0 + nt * 16 + brow) * ASTRIDE + bcol]);
                    uint32_t r0, r1, r2, r3;
                    ldm_x4(r0, r1, r2, r3, bd);
                    bh[nt * 2][0] = r0; bh[nt * 2][1] = r1;
                    bh[nt * 2 + 1][0] = r2; bh[nt * 2 + 1][1] = r3;
                    uint32_t bd2 = smem_u32(&BsL[(n0 + nt * 16 + brow) * ASTRIDE + bcol]);
                    ldm_x4(r0, r1, r2, r3, bd2);
                    bl[nt * 2][0] = r0; bl[nt * 2][1] = r1;
                    bl[nt * 2 + 1][0] = r2; bl[nt * 2 + 1][1] = r3;
                }
            }
            #pragma unroll
            for (int mt = 0; mt < 2; mt++)
                #pragma unroll
                for (int nt = 0; nt < 8; nt++) {
                    mma16816(acc[mt][nt], ah[mt][0], ah[mt][1], ah[mt][2], ah[mt][3], bh[nt][0], bh[nt][1]);
                    mma16816(acc[mt][nt], ah[mt][0], ah[mt][1], ah[mt][2], ah[mt][3], bl[nt][0], bl[nt][1]);
                    mma16816(acc[mt][nt], al[mt][0], al[mt][1], al[mt][2], al[mt][3], bh[nt][0], bh[nt][1]);
                }
        }
        __syncthreads();
    }

    // ---- epilogue ----
    int g = lane >> 2, tig = lane & 3;
    #pragma unroll
    for (int mt = 0; mt < 2; mt++) {
        int r0 = rowBase + m0 + mt * 16 + g;
        int r1 = r0 + 8;
        #pragma unroll
        for (int nt = 0; nt < 8; nt++) {
            int col = colBase + n0 + nt * 8 + tig * 2;
            if (r0 < MM) *(float2*)(d_hw + (size_t)r0 * 256 + col) = make_float2(acc[mt][nt][0], acc[mt][nt][1]);
            if (r1 < MM) *(float2*)(d_hw + (size_t)r1 * 256 + col) = make_float2(acc[mt][nt][2], acc[mt][nt][3]);
        }
    }
}

// ------------------- CSR gather + self-loop + bias + ELU (per feature chunk) -------------------
// Also emits bf16 hi/lo copy for next layer's GEMM (layers 0,1).
__global__ __launch_bounds__(128) void gather_k(const float* __restrict__ bias, int chunk, int layer)
{
    float4* hout = (layer == 0) ? (float4*)d_h1 : (layer == 1) ? (float4*)d_h2 : (float4*)d_h3;
    const float4* hw = (const float4*)d_hw;

    int j   = blockIdx.x;
    int tid = threadIdx.x;          // 0..127
    int fo  = chunk * 128 + tid;    // float4 offset within node row (512 per node)

    float dj = d_dis[j];
    float di = d_dinv[j];
    float4 a = hw[j * 512 + fo];
    float4 acc;
    acc.x = a.x * di; acc.y = a.y * di; acc.z = a.z * di; acc.w = a.w * di;

    int s0 = d_rowptr[j], s1 = d_rowptr[j + 1];
    for (int k = s0; k < s1; k++) {
        int s = d_src[k];
        float w = d_dis[s] * dj;
        float4 v = hw[s * 512 + fo];
        acc.x = fmaf(w, v.x, acc.x);
        acc.y = fmaf(w, v.y, acc.y);
        acc.z = fmaf(w, v.z, acc.z);
        acc.w = fmaf(w, v.w, acc.w);
    }

    int h = (tid & 63) * 4;         // feature index within H=256
    acc.x = elu1(acc.x + bias[h]);
    acc.y = elu1(acc.y + bias[h + 1]);
    acc.z = elu1(acc.z + bias[h + 2]);
    acc.w = elu1(acc.w + bias[h + 3]);
    hout[j * 512 + fo] = acc;

    if (layer < 2) {
        int b = fo >> 6;
        size_t row = (size_t)(j * 8 + b) * 256 + h;
        __nv_bfloat162 h0, h1, l0, l1;
        h0.x = __float2bfloat16(acc.x); h0.y = __float2bfloat16(acc.y);
        h1.x = __float2bfloat16(acc.z); h1.y = __float2bfloat16(acc.w);
        l0.x = __float2bfloat16(acc.x - __bfloat162float(h0.x));
        l0.y = __float2bfloat16(acc.y - __bfloat162float(h0.y));
        l1.x = __float2bfloat16(acc.z - __bfloat162float(h1.x));
        l1.y = __float2bfloat16(acc.w - __bfloat162float(h1.y));
        *(__nv_bfloat162*)(d_ahi + row)     = h0;
        *(__nv_bfloat162*)(d_ahi + row + 2) = h1;
        *(__nv_bfloat162*)(d_alo + row)     = l0;
        *(__nv_bfloat162*)(d_alo + row + 2) = l1;
    }
}

// ------------------- g[b][n] = sum_l sum_h h_l[b,n,h] * fcW[3h+l] + fcb -------------------
__global__ __launch_bounds__(256) void g_k(const float* __restrict__ fcW, const float* __restrict__ fcb)
{
    int j = blockIdx.x;
    int b = threadIdx.x >> 5;
    int lane = threadIdx.x & 31;
    int base = (j * 8 + b) * 256;
    float s = 0.f;
    #pragma unroll
    for (int i = 0; i < 8; i++) {
        int h = lane + i * 32;
        s = fmaf(d_h1[base + h], fcW[3 * h],     s);
        s = fmaf(d_h2[base + h], fcW[3 * h + 1], s);
        s = fmaf(d_h3[base + h], fcW[3 * h + 2], s);
    }
    #pragma unroll
    for (int o = 16; o; o >>= 1) s += __shfl_xor_sync(0xffffffffu, s, o);
    if (lane == 0) d_g[b * NN + j] = s + fcb[0];
}

// ------------------- z = elu(g @ lin1_W + lin1_b), split-K -------------------
__global__ __launch_bounds__(256) void lin1_k(const float* __restrict__ W)
{
    int o = blockIdx.x * 256 + threadIdx.x;  // 0..511
    const int NS = (NN + 63) / 64;           // 237
    int n0 = blockIdx.y * NS;
    int n1 = n0 + NS; if (n1 > NN) n1 = NN;
    float acc[8];
    #pragma unroll
    for (int b = 0; b < 8; b++) acc[b] = 0.f;
    for (int n = n0; n < n1; n++) {
        float w = W[n * 512 + o];
        #pragma unroll
        for (int b = 0; b < 8; b++) acc[b] = fmaf(d_g[b * NN + n], w, acc[b]);
    }
    #pragma unroll
    for (int b = 0; b < 8; b++) atomicAdd(&d_zacc[b * 512 + o], acc[b]);
}

__global__ void lin1fin_k(const float* __restrict__ bias)
{
    int i = blockIdx.x * 256 + threadIdx.x;
    if (i >= BSZ * HFCC) return;
    d_z[i] = elu1(d_zacc[i] + bias[i & 511]);
}

// ------------------- out = log_softmax(z @ lin2_W + lin2_b) -------------------
__global__ void final_k(const float* __restrict__ W, const float* __restrict__ bv,
                        float* __restrict__ out)
{
    int b = threadIdx.x >> 5;
    int lane = threadIdx.x & 31;
    float a0 = 0.f, a1 = 0.f;
    for (int i = lane; i < 512; i += 32) {
        float z = d_z[b * 512 + i];
        a0 = fmaf(z, W[2 * i],     a0);
        a1 = fmaf(z, W[2 * i + 1], a1);
    }
    #pragma unroll
    for (int o = 16; o; o >>= 1) {
        a0 += __shfl_xor_sync(0xffffffffu, a0, o);
        a1 += __shfl_xor_sync(0xffffffffu, a1, o);
    }
    if (lane == 0) {
        float v0 = a0 + bv[0], v1 = a1 + bv[1];
        float m = fmaxf(v0, v1);
        float l = m + logf(expf(v0 - m) + expf(v1 - m));
        out[2 * b]     = v0 - l;
        out[2 * b + 1] = v1 - l;
    }
}

// ------------------- host launcher -------------------
extern "C" void kernel_launch(void* const* d_in, const int* in_sizes, int n_in,
                              void* d_out, int out_size)
{
    const float* x      = (const float*)d_in[0];
    // d_in[1] = batch (unused, all zeros)
    const void*  ei     = d_in[2];                 // int32 or int64, auto-detected
    const float* pe     = (const float*)d_in[3];
    const float* W1     = (const float*)d_in[4];
    const float* b1     = (const float*)d_in[5];
    const float* W2     = (const float*)d_in[6];
    const float* b2     = (const float*)d_in[7];
    const float* W3     = (const float*)d_in[8];
    const float* b3     = (const float*)d_in[9];
    const float* fcW    = (const float*)d_in[10];
    const float* fcb    = (const float*)d_in[11];
    const float* lin1W  = (const float*)d_in[12];
    const float* lin1b  = (const float*)d_in[13];
    const float* lin2W  = (const float*)d_in[14];
    const float* lin2b  = (const float*)d_in[15];
    float* out = (float*)d_out;

    static int attr_done = 0;
    if (!attr_done) {
        cudaFuncSetAttribute(mma_gemm_k, cudaFuncAttributeMaxDynamicSharedMemorySize, GEMM_DSMEM);
        attr_done = 1;
    }

    // resolve device-global addresses for kernel args
    __nv_bfloat16 *a0hi, *a0lo, *ahi, *alo, *w0hi, *w0lo, *w1hi, *w1lo, *w2hi, *w2lo;
    cudaGetSymbolAddress((void**)&a0hi, d_a0hi);
    cudaGetSymbolAddress((void**)&a0lo, d_a0lo);
    cudaGetSymbolAddress((void**)&ahi,  d_ahi);
    cudaGetSymbolAddress((void**)&alo,  d_alo);
    cudaGetSymbolAddress((void**)&w0hi, d_w0hi);
    cudaGetSymbolAddress((void**)&w0lo, d_w0lo);
    cudaGetSymbolAddress((void**)&w1hi, d_w1hi);
    cudaGetSymbolAddress((void**)&w1lo, d_w1lo);
    cudaGetSymbolAddress((void**)&w2hi, d_w2hi);
    cudaGetSymbolAddress((void**)&w2lo, d_w2lo);

    // graph preprocessing
    zero_k<<<(NN + 255) / 256, 256>>>();
    edges_k<<<(EE + 255) / 256, 256>>>(ei);
    deg_k<<<(NN + 255) / 256, 256>>>();
    scan_k<<<1, 1024>>>();
    fill_k<<<(EE + 255) / 256, 256>>>();

    // operand conversion
    concat_k<<<(MM * K1P + 255) / 256, 256>>>(x, pe);
    convw_k<<<(HH * K1P + 255) / 256, 256>>>(W1, w0hi, w0lo, K1, K1P);
    convw_k<<<(HH * HH + 255) / 256, 256>>>(W2, w1hi, w1lo, HH, HH);
    convw_k<<<(HH * HH + 255) / 256, 256>>>(W3, w2hi, w2lo, HH, HH);

    const int MTILES = (MM + 127) / 128;  // 946
    dim3 ggrid(MTILES, 2);

    // layer 1
    mma_gemm_k<<<ggrid, 256, GEMM_DSMEM>>>(a0hi, a0lo, w0hi, w0lo, K1P);
    for (int c = 0; c < 4; c++) gather_k<<<NN, 128>>>(b1, c, 0);
    // layer 2
    mma_gemm_k<<<ggrid, 256, GEMM_DSMEM>>>(ahi, alo, w1hi, w1lo, HH);
    for (int c = 0; c < 4; c++) gather_k<<<NN, 128>>>(b2, c, 1);
    // layer 3
    mma_gemm_k<<<ggrid, 256, GEMM_DSMEM>>>(ahi, alo, w2hi, w2lo, HH);
    for (int c = 0; c < 4; c++) gather_k<<<NN, 128>>>(b3, c, 2);

    // head
    g_k<<<NN, 256>>>(fcW, fcb);
    {
        dim3 lg(2, 64);
        lin1_k<<<lg, 256>>>(lin1W);
    }
    lin1fin_k<<<16, 256>>>(lin1b);
    final_k<<<1, 256>>>(lin2W, lin2b, out);
}

// round 8
// speedup vs baseline: 1.9064x; 1.1383x over previous
#include <cuda_runtime.h>
#include <cuda_bf16.h>
#include <math.h>
#include <stdint.h>

// Problem constants (fixed shapes)
#define NN   15135
#define BSZ  8
#define FF   64
#define GG   73
#define HH   256
#define EE   242160
#define MM   (NN*BSZ)       // 121080 rows
#define K1   (FF+GG)        // 137
#define K1P  160            // padded to multiple of 32
#define HFCC 512

// ------------------- scratch (device globals; no allocation) -------------------
__device__ __align__(16) float d_hw[MM*HH];     // GEMM output (pre-aggregation)
// bf16 hi/lo GEMM operands
__device__ __align__(16) __nv_bfloat16 d_a0hi[MM*K1P];
__device__ __align__(16) __nv_bfloat16 d_a0lo[MM*K1P];
__device__ __align__(16) __nv_bfloat16 d_ahi[MM*HH];
__device__ __align__(16) __nv_bfloat16 d_alo[MM*HH];
__device__ __align__(16) __nv_bfloat16 d_w0hi[HH*K1P];
__device__ __align__(16) __nv_bfloat16 d_w0lo[HH*K1P];
__device__ __align__(16) __nv_bfloat16 d_w1hi[HH*HH];
__device__ __align__(16) __nv_bfloat16 d_w1lo[HH*HH];
__device__ __align__(16) __nv_bfloat16 d_w2hi[HH*HH];
__device__ __align__(16) __nv_bfloat16 d_w2lo[HH*HH];

__device__ float d_dis[NN];
__device__ float d_dinv[NN];
__device__ int   d_cnt[NN];
__device__ int   d_rowptr[NN+1];
__device__ int   d_cursor[NN];
__device__ int   d_src[EE];
__device__ float d_wgt[EE];
__device__ int   d_row32[EE];
__device__ int   d_col32[EE];
__device__ float d_g[BSZ*NN];
__device__ float d_zacc[BSZ*HFCC];
__device__ float d_z[BSZ*HFCC];

__device__ __forceinline__ float elu1(float x) { return x > 0.f ? x : expm1f(x); }

__device__ __forceinline__ uint32_t smem_u32(const void* p) {
    uint32_t a;
    asm("{ .reg .u64 t; cvta.to.shared.u64 t, %1; cvt.u32.u64 %0, t; }" : "=r"(a) : "l"(p));
    return a;
}
__device__ __forceinline__ void ldm_x4(uint32_t& r0, uint32_t& r1, uint32_t& r2, uint32_t& r3, uint32_t addr)
{
    asm volatile("ldmatrix.sync.aligned.m8n8.x4.shared.b16 {%0,%1,%2,%3}, [%4];"
                 : "=r"(r0), "=r"(r1), "=r"(r2), "=r"(r3) : "r"(addr));
}
__device__ __forceinline__ void mma16816(float* c, uint32_t a0, uint32_t a1, uint32_t a2, uint32_t a3,
                                         uint32_t b0, uint32_t b1)
{
    asm volatile(
        "mma.sync.aligned.m16n8k16.row.col.f32.bf16.bf16.f32 "
        "{%0,%1,%2,%3}, {%4,%5,%6,%7}, {%8,%9}, {%0,%1,%2,%3};"
        : "+f"(c[0]), "+f"(c[1]), "+f"(c[2]), "+f"(c[3])
        : "r"(a0), "r"(a1), "r"(a2), "r"(a3), "r"(b0), "r"(b1));
}
__device__ __forceinline__ void cp16(uint32_t dst, const void* src, uint32_t srcsize)
{
    asm volatile("cp.async.cg.shared.global [%0], [%1], 16, %2;"
                 :: "r"(dst), "l"(src), "r"(srcsize) : "memory");
}
__device__ __forceinline__ void cp_commit() { asm volatile("cp.async.commit_group;" ::: "memory"); }

// ------------------- graph preprocessing -------------------
__global__ void zero_k(const float* __restrict__ fcb)
{
    int i = blockIdx.x * 256 + threadIdx.x;
    if (i < NN) { d_cnt[i] = 0; d_cursor[i] = 0; }
    if (i < BSZ*HFCC) d_zacc[i] = 0.f;
    if (i < BSZ*NN) d_g[i] = fcb[0];
}

// edge_index may be int64 or int32 (auto-detect).
__global__ void edges_k(const void* __restrict__ ei_raw)
{
    __shared__ int is64;
    const int* ei32 = (const int*)ei_raw;
    if (threadIdx.x == 0) {
        int allz = 1;
        for (int i = 0; i < 64; i++) if (ei32[2 * i + 1] != 0) { allz = 0; break; }
        is64 = allz;
    }
    __syncthreads();

    int e = blockIdx.x * 256 + threadIdx.x;
    if (e >= EE) return;
    int r, c;
    if (is64) {
        const long long* ei = (const long long*)ei_raw;
        r = (int)ei[e];
        c = (int)ei[EE + e];
    } else {
        r = ei32[e];
        c = ei32[EE + e];
    }
    d_row32[e] = r;
    d_col32[e] = c;
    atomicAdd(&d_cnt[c], 1);
}

__global__ void deg_k()
{
    int j = blockIdx.x * 256 + threadIdx.x;
    if (j >= NN) return;
    float dg = (float)d_cnt[j] + 1.0f;
    d_dis[j]  = rsqrtf(dg);
    d_dinv[j] = 1.0f / dg;
}

// exclusive scan d_cnt -> d_rowptr, 1024 threads, 15 elems/thread, shuffle scan
__global__ void scan_k()
{
    __shared__ int wsum[32];
    int t = threadIdx.x, lane = t & 31, w = t >> 5;
    int base = t * 15;
    int v[15];
    int s = 0;
    #pragma unroll
    for (int i = 0; i < 15; i++) {
        int idx = base + i;
        v[i] = (idx < NN) ? d_cnt[idx] : 0;
        s += v[i];
    }
    int ps = s;
    #pragma unroll
    for (int o = 1; o < 32; o <<= 1) {
        int u = __shfl_up_sync(0xffffffffu, ps, o);
        if (lane >= o) ps += u;
    }
    if (lane == 31) wsum[w] = ps;
    __syncthreads();
    if (w == 0) {
        int ws = wsum[lane];
        #pragma unroll
        for (int o = 1; o < 32; o <<= 1) {
            int u = __shfl_up_sync(0xffffffffu, ws, o);
            if (lane >= o) ws += u;
        }
        wsum[lane] = ws;
    }
    __syncthreads();
    int prefix = ps - s + (w > 0 ? wsum[w - 1] : 0);
    #pragma unroll
    for (int i = 0; i < 15; i++) {
        int idx = base + i;
        if (idx <= NN) d_rowptr[idx] = prefix;
        prefix += v[i];
    }
}

__global__ void fill_k()
{
    int e = blockIdx.x * 256 + threadIdx.x;
    if (e >= EE) return;
    int c = d_col32[e];
    int r = d_row32[e];
    int p = atomicAdd(&d_cursor[c], 1);
    int pos = d_rowptr[c] + p;
    d_src[pos] = r;
    d_wgt[pos] = d_dis[r] * d_dis[c];
}

// ------------------- input concat -> bf16 hi/lo, padded K=160 -------------------
__global__ void concat_k(const float* __restrict__ x, const float* __restrict__ pe)
{
    int idx = blockIdx.x * 256 + threadIdx.x;
    if (idx >= MM * K1P) return;
    int r = idx / K1P;
    int k = idx - r * K1P;
    int n = r >> 3, b = r & 7;
    float v = 0.f;
    if (k < FF) v = x[(b * NN + n) * FF + k];
    else if (k < K1) v = pe[n * GG + (k - FF)];
    __nv_bfloat16 h = __float2bfloat16(v);
    d_a0hi[idx] = h;
    d_a0lo[idx] = __float2bfloat16(v - __bfloat162float(h));
}

// ------------------- weight transpose + bf16 hi/lo split: [K,256] -> [256,Kpad] -------------------
__global__ void convw_k(const float* __restrict__ W, __nv_bfloat16* __restrict__ hi,
                        __nv_bfloat16* __restrict__ lo, int K, int Kpad)
{
    int idx = blockIdx.x * 256 + threadIdx.x;
    if (idx >= HH * Kpad) return;
    int n = idx / Kpad, k = idx - n * Kpad;
    float v = (k < K) ? W[k * HH + n] : 0.f;
    __nv_bfloat16 h = __float2bfloat16(v);
    hi[idx] = h;
    lo[idx] = __float2bfloat16(v - __bfloat162float(h));
}

// ------------------- mma.sync bf16 hi/lo GEMM, 3-stage cp.async pipeline ---------
// d_hw[M,256] = A @ W^T.  A [M][Kpad] bf16 hi/lo; W [256 n][Kpad k] bf16 hi/lo.
// Grid (946, 2): CTA tile 128m x 128n. 8 warps: warp tile 32m x 64n.
// K chunks of 32 staged in dynamic SMEM, 3 stages (stride-40 rows, conflict-free ldmatrix).
#define ASTRIDE 40
#define TILE_B  (128 * ASTRIDE * 2)    // 10240 bytes per operand tile
#define STAGE_B (4 * TILE_B)           // 40960 bytes per stage
#define GEMM_DSMEM (3 * STAGE_B)       // 122880

__global__ __launch_bounds__(256) void mma_gemm_k(
    const __nv_bfloat16* __restrict__ Ahi, const __nv_bfloat16* __restrict__ Alo,
    const __nv_bfloat16* __restrict__ Whi, const __nv_bfloat16* __restrict__ Wlo,
    int Kpad)
{
    extern __shared__ char dsm[];
    uint32_t dsm_b = smem_u32(dsm);

    int tid = threadIdx.x, wid = tid >> 5, lane = tid & 31;
    int rowBase = blockIdx.x * 128;
    int colBase = blockIdx.y * 128;
    int wm = wid >> 1, wn = wid & 1;
    int m0 = wm * 32, n0 = wn * 64;

    float acc[2][8][4];
    #pragma unroll
    for (int i = 0; i < 2; i++)
        #pragma unroll
        for (int j = 0; j < 8; j++)
            #pragma unroll
            for (int q = 0; q < 4; q++) acc[i][j][q] = 0.f;

    int nch = Kpad >> 5;

    auto load_chunk = [&](int c, int st) {
        int k0 = c * 32;
        uint32_t sbase = dsm_b + st * STAGE_B;
        #pragma unroll
        for (int ii = 0; ii < 2; ii++) {
            int i = tid + ii * 256;
            int r = i >> 2, q = i & 3;
            uint32_t doff = (uint32_t)(r * (ASTRIDE * 2) + q * 16);
            int grow = rowBase + r;
            uint32_t ok = (grow < MM) ? 16u : 0u;
            int gr = (grow < MM) ? grow : 0;
            cp16(sbase + doff,              Ahi + (size_t)gr * Kpad + k0 + q * 8, ok);
            cp16(sbase + TILE_B + doff,     Alo + (size_t)gr * Kpad + k0 + q * 8, ok);
            int gn = colBase + r;
            cp16(sbase + 2 * TILE_B + doff, Whi + (size_t)gn * Kpad + k0 + q * 8, 16u);
            cp16(sbase + 3 * TILE_B + doff, Wlo + (size_t)gn * Kpad + k0 + q * 8, 16u);
        }
        cp_commit();
    };

    load_chunk(0, 0);
    if (nch > 1) load_chunk(1, 1);

    int st = 0;
    for (int c = 0; c < nch; c++) {
        if (c + 2 < nch) {
            int st2 = st + 2; if (st2 >= 3) st2 -= 3;
            load_chunk(c + 2, st2);
            asm volatile("cp.async.wait_group 2;" ::: "memory");
        } else if (c + 1 < nch) {
            asm volatile("cp.async.wait_group 1;" ::: "memory");
        } else {
            asm volatile("cp.async.wait_group 0;" ::: "memory");
        }
        __syncthreads();

        char* stg = dsm + st * STAGE_B;
        __nv_bfloat16* AsH = (__nv_bfloat16*)(stg);
        __nv_bfloat16* AsL = (__nv_bfloat16*)(stg + TILE_B);
        __nv_bfloat16* BsH = (__nv_bfloat16*)(stg + 2 * TILE_B);
        __nv_bfloat16* BsL = (__nv_bfloat16*)(stg + 3 * TILE_B);

        #pragma unroll
        for (int s = 0; s < 2; s++) {
            int kk = s * 16;
            uint32_t ah[2][4], al[2][4];
            {
                int t = lane >> 3, rr = lane & 7;
                int arow = ((t & 1) << 3) + rr;
                int acol = kk + ((t >> 1) << 3);
                #pragma unroll
                for (int mt = 0; mt < 2; mt++) {
                    uint32_t ad = smem_u32(&AsH[(m0 + mt * 16 + arow) * ASTRIDE + acol]);
                    ldm_x4(ah[mt][0], ah[mt][1], ah[mt][2], ah[mt][3], ad);
                    uint32_t ad2 = smem_u32(&AsL[(m0 + mt * 16 + arow) * ASTRIDE + acol]);
                    ldm_x4(al[mt][0], al[mt][1], al[mt][2], al[mt][3], ad2);
                }
            }
            uint32_t bh[8][2], bl[8][2];
            {
                int brow = (((lane >> 4) & 1) << 3) + (lane & 7);
                int bcol = kk + (((lane >> 3) & 1) << 3);
                #pragma unroll
                for (int nt = 0; nt < 4; nt++) {
                    uint32_t bd = smem_u32(&BsH[(n0 + nt * 16 + brow) * ASTRIDE + bcol]);
                    uint32_t r0, r1, r2, r3;
                    ldm_x4(r0, r1, r2, r3, bd);
                    bh[nt * 2][0] = r0; bh[nt * 2][1] = r1;
                    bh[nt * 2 + 1][0] = r2; bh[nt * 2 + 1][1] = r3;
                    uint32_t bd2 = smem_u32(&BsL[(n0 + nt * 16 + brow) * ASTRIDE + bcol]);
                    ldm_x4(r0, r1, r2, r3, bd2);
                    bl[nt * 2][0] = r0; bl[nt * 2][1] = r1;
                    bl[nt * 2 + 1][0] = r2; bl[nt * 2 + 1][1] = r3;
                }
            }
            #pragma unroll
            for (int mt = 0; mt < 2; mt++)
                #pragma unroll
                for (int nt = 0; nt < 8; nt++) {
                    mma16816(acc[mt][nt], ah[mt][0], ah[mt][1], ah[mt][2], ah[mt][3], bh[nt][0], bh[nt][1]);
                    mma16816(acc[mt][nt], ah[mt][0], ah[mt][1], ah[mt][2], ah[mt][3], bl[nt][0], bl[nt][1]);
                    mma16816(acc[mt][nt], al[mt][0], al[mt][1], al[mt][2], al[mt][3], bh[nt][0], bh[nt][1]);
                }
        }
        __syncthreads();
        if (++st == 3) st = 0;
    }

    // ---- epilogue ----
    int g = lane >> 2, tig = lane & 3;
    #pragma unroll
    for (int mt = 0; mt < 2; mt++) {
        int r0 = rowBase + m0 + mt * 16 + g;
        int r1 = r0 + 8;
        #pragma unroll
        for (int nt = 0; nt < 8; nt++) {
            int col = colBase + n0 + nt * 8 + tig * 2;
            if (r0 < MM) *(float2*)(d_hw + (size_t)r0 * 256 + col) = make_float2(acc[mt][nt][0], acc[mt][nt][1]);
            if (r1 < MM) *(float2*)(d_hw + (size_t)r1 * 256 + col) = make_float2(acc[mt][nt][2], acc[mt][nt][3]);
        }
    }
}

// ------------------- CSR gather + self-loop + bias + ELU + fused fc-dot ------------
// Per feature chunk (2KB/node -> 31MB working set, L2 resident).
// Emits bf16 hi/lo next-layer operand (layers 0,1), accumulates g via atomics (all layers).
__global__ __launch_bounds__(128) void gather_k(const float* __restrict__ bias,
                                                const float* __restrict__ fcW,
                                                int chunk, int layer)
{
    const float4* hw = (const float4*)d_hw;

    int j   = blockIdx.x;
    int tid = threadIdx.x;          // 0..127
    int fo  = chunk * 128 + tid;    // float4 offset within node row (512 per node)

    float di = d_dinv[j];
    float4 a = hw[j * 512 + fo];
    float4 acc;
    acc.x = a.x * di; acc.y = a.y * di; acc.z = a.z * di; acc.w = a.w * di;

    int s0 = d_rowptr[j], s1 = d_rowptr[j + 1];
    int k = s0;
    for (; k + 4 <= s1; k += 4) {
        int sa = d_src[k], sb = d_src[k + 1], sc = d_src[k + 2], sd = d_src[k + 3];
        float wa = d_wgt[k], wb = d_wgt[k + 1], wc = d_wgt[k + 2], wd = d_wgt[k + 3];
        float4 va = hw[sa * 512 + fo];
        float4 vb = hw[sb * 512 + fo];
        float4 vc = hw[sc * 512 + fo];
        float4 vd = hw[sd * 512 + fo];
        acc.x = fmaf(wa, va.x, acc.x); acc.y = fmaf(wa, va.y, acc.y);
        acc.z = fmaf(wa, va.z, acc.z); acc.w = fmaf(wa, va.w, acc.w);
        acc.x = fmaf(wb, vb.x, acc.x); acc.y = fmaf(wb, vb.y, acc.y);
        acc.z = fmaf(wb, vb.z, acc.z); acc.w = fmaf(wb, vb.w, acc.w);
        acc.x = fmaf(wc, vc.x, acc.x); acc.y = fmaf(wc, vc.y, acc.y);
        acc.z = fmaf(wc, vc.z, acc.z); acc.w = fmaf(wc, vc.w, acc.w);
        acc.x = fmaf(wd, vd.x, acc.x); acc.y = fmaf(wd, vd.y, acc.y);
        acc.z = fmaf(wd, vd.z, acc.z); acc.w = fmaf(wd, vd.w, acc.w);
    }
    for (; k < s1; k++) {
        int s = d_src[k];
        float w = d_wgt[k];
        float4 v = hw[s * 512 + fo];
        acc.x = fmaf(w, v.x, acc.x);
        acc.y = fmaf(w, v.y, acc.y);
        acc.z = fmaf(w, v.z, acc.z);
        acc.w = fmaf(w, v.w, acc.w);
    }

    int h = (tid & 63) * 4;         // feature index within H=256
    acc.x = elu1(acc.x + bias[h]);
    acc.y = elu1(acc.y + bias[h + 1]);
    acc.z = elu1(acc.z + bias[h + 2]);
    acc.w = elu1(acc.w + bias[h + 3]);

    int b = (chunk * 2) + (tid >> 6);   // batch index (warp-uniform)

    if (layer < 2) {
        size_t row = (size_t)(j * 8 + b) * 256 + h;
        __nv_bfloat162 h0, h1, l0, l1;
        h0.x = __float2bfloat16(acc.x); h0.y = __float2bfloat16(acc.y);
        h1.x = __float2bfloat16(acc.z); h1.y = __float2bfloat16(acc.w);
        l0.x = __float2bfloat16(acc.x - __bfloat162float(h0.x));
        l0.y = __float2bfloat16(acc.y - __bfloat162float(h0.y));
        l1.x = __float2bfloat16(acc.z - __bfloat162float(h1.x));
        l1.y = __float2bfloat16(acc.w - __bfloat162float(h1.y));
        *(__nv_bfloat162*)(d_ahi + row)     = h0;
        *(__nv_bfloat162*)(d_ahi + row + 2) = h1;
        *(__nv_bfloat162*)(d_alo + row)     = l0;
        *(__nv_bfloat162*)(d_alo + row + 2) = l1;
    }

    // fused JK/fc contribution: g[b][j] += sum_h h*fcW[3h+layer]
    float gc = acc.x * fcW[3 * h + layer]
             + acc.y * fcW[3 * (h + 1) + layer]
             + acc.z * fcW[3 * (h + 2) + layer]
             + acc.w * fcW[3 * (h + 3) + layer];
    #pragma unroll
    for (int o = 16; o; o >>= 1) gc += __shfl_xor_sync(0xffffffffu, gc, o);
    if ((tid & 31) == 0) atomicAdd(&d_g[b * NN + j], gc);
}

// ------------------- z = elu(g @ lin1_W + lin1_b), split-K -------------------
__global__ __launch_bounds__(256) void lin1_k(const float* __restrict__ W)
{
    int o = blockIdx.x * 256 + threadIdx.x;  // 0..511
    const int NS = (NN + 63) / 64;           // 237
    int n0 = blockIdx.y * NS;
    int n1 = n0 + NS; if (n1 > NN) n1 = NN;
    float acc[8];
    #pragma unroll
    for (int b = 0; b < 8; b++) acc[b] = 0.f;
    for (int n = n0; n < n1; n++) {
        float w = W[n * 512 + o];
        #pragma unroll
        for (int b = 0; b < 8; b++) acc[b] = fmaf(d_g[b * NN + n], w, acc[b]);
    }
    #pragma unroll
    for (int b = 0; b < 8; b++) atomicAdd(&d_zacc[b * 512 + o], acc[b]);
}

__global__ void lin1fin_k(const float* __restrict__ bias)
{
    int i = blockIdx.x * 256 + threadIdx.x;
    if (i >= BSZ * HFCC) return;
    d_z[i] = elu1(d_zacc[i] + bias[i & 511]);
}

// ------------------- out = log_softmax(z @ lin2_W + lin2_b) -------------------
__global__ void final_k(const float* __restrict__ W, const float* __restrict__ bv,
                        float* __restrict__ out)
{
    int b = threadIdx.x >> 5;
    int lane = threadIdx.x & 31;
    float a0 = 0.f, a1 = 0.f;
    for (int i = lane; i < 512; i += 32) {
        float z = d_z[b * 512 + i];
        a0 = fmaf(z, W[2 * i],     a0);
        a1 = fmaf(z, W[2 * i + 1], a1);
    }
    #pragma unroll
    for (int o = 16; o; o >>= 1) {
        a0 += __shfl_xor_sync(0xffffffffu, a0, o);
        a1 += __shfl_xor_sync(0xffffffffu, a1, o);
    }
    if (lane == 0) {
        float v0 = a0 + bv[0], v1 = a1 + bv[1];
        float m = fmaxf(v0, v1);
        float l = m + logf(expf(v0 - m) + expf(v1 - m));
        out[2 * b]     = v0 - l;
        out[2 * b + 1] = v1 - l;
    }
}

// ------------------- host launcher -------------------
extern "C" void kernel_launch(void* const* d_in, const int* in_sizes, int n_in,
                              void* d_out, int out_size)
{
    const float* x      = (const float*)d_in[0];
    // d_in[1] = batch (unused, all zeros)
    const void*  ei     = d_in[2];                 // int32 or int64, auto-detected
    const float* pe     = (const float*)d_in[3];
    const float* W1     = (const float*)d_in[4];
    const float* b1     = (const float*)d_in[5];
    const float* W2     = (const float*)d_in[6];
    const float* b2     = (const float*)d_in[7];
    const float* W3     = (const float*)d_in[8];
    const float* b3     = (const float*)d_in[9];
    const float* fcW    = (const float*)d_in[10];
    const float* fcb    = (const float*)d_in[11];
    const float* lin1W  = (const float*)d_in[12];
    const float* lin1b  = (const float*)d_in[13];
    const float* lin2W  = (const float*)d_in[14];
    const float* lin2b  = (const float*)d_in[15];
    float* out = (float*)d_out;

    cudaFuncSetAttribute(mma_gemm_k, cudaFuncAttributeMaxDynamicSharedMemorySize, GEMM_DSMEM);

    // resolve device-global addresses for kernel args
    __nv_bfloat16 *a0hi, *a0lo, *ahi, *alo, *w0hi, *w0lo, *w1hi, *w1lo, *w2hi, *w2lo;
    cudaGetSymbolAddress((void**)&a0hi, d_a0hi);
    cudaGetSymbolAddress((void**)&a0lo, d_a0lo);
    cudaGetSymbolAddress((void**)&ahi,  d_ahi);
    cudaGetSymbolAddress((void**)&alo,  d_alo);
    cudaGetSymbolAddress((void**)&w0hi, d_w0hi);
    cudaGetSymbolAddress((void**)&w0lo, d_w0lo);
    cudaGetSymbolAddress((void**)&w1hi, d_w1hi);
    cudaGetSymbolAddress((void**)&w1lo, d_w1lo);
    cudaGetSymbolAddress((void**)&w2hi, d_w2hi);
    cudaGetSymbolAddress((void**)&w2lo, d_w2lo);

    // graph preprocessing
    zero_k<<<(BSZ * NN + 255) / 256, 256>>>(fcb);
    edges_k<<<(EE + 255) / 256, 256>>>(ei);
    deg_k<<<(NN + 255) / 256, 256>>>();
    scan_k<<<1, 1024>>>();
    fill_k<<<(EE + 255) / 256, 256>>>();

    // operand conversion
    concat_k<<<(MM * K1P + 255) / 256, 256>>>(x, pe);
    convw_k<<<(HH * K1P + 255) / 256, 256>>>(W1, w0hi, w0lo, K1, K1P);
    convw_k<<<(HH * HH + 255) / 256, 256>>>(W2, w1hi, w1lo, HH, HH);
    convw_k<<<(HH * HH + 255) / 256, 256>>>(W3, w2hi, w2lo, HH, HH);

    const int MTILES = (MM + 127) / 128;  // 946
    dim3 ggrid(MTILES, 2);

    // layer 1
    mma_gemm_k<<<ggrid, 256, GEMM_DSMEM>>>(a0hi, a0lo, w0hi, w0lo, K1P);
    for (int c = 0; c < 4; c++) gather_k<<<NN, 128>>>(b1, fcW, c, 0);
    // layer 2
    mma_gemm_k<<<ggrid, 256, GEMM_DSMEM>>>(ahi, alo, w1hi, w1lo, HH);
    for (int c = 0; c < 4; c++) gather_k<<<NN, 128>>>(b2, fcW, c, 1);
    // layer 3
    mma_gemm_k<<<ggrid, 256, GEMM_DSMEM>>>(ahi, alo, w2hi, w2lo, HH);
    for (int c = 0; c < 4; c++) gather_k<<<NN, 128>>>(b3, fcW, c, 2);

    // head
    {
        dim3 lg(2, 64);
        lin1_k<<<lg, 256>>>(lin1W);
    }
    lin1fin_k<<<16, 256>>>(lin1b);
    final_k<<<1, 256>>>(lin2W, lin2b, out);
}

// round 10
// speedup vs baseline: 2.0665x; 1.0840x over previous
#include <cuda_runtime.h>
#include <cuda_bf16.h>
#include <cuda_fp16.h>
#include <math.h>
#include <stdint.h>

// Problem constants (fixed shapes)
#define NN   15135
#define BSZ  8
#define FF   64
#define GG   73
#define HH   256
#define EE   242160
#define MM   (NN*BSZ)       // 121080 rows
#define K1   (FF+GG)        // 137
#define K1P  160            // padded to multiple of 32
#define HFCC 512

// ------------------- scratch (device globals; no allocation) -------------------
__device__ __align__(16) __half d_hwh[MM*HH];   // GEMM output (fp16, pre-aggregation)
// bf16 hi/lo GEMM operands
__device__ __align__(16) __nv_bfloat16 d_a0hi[MM*K1P];
__device__ __align__(16) __nv_bfloat16 d_a0lo[MM*K1P];
__device__ __align__(16) __nv_bfloat16 d_ahi[MM*HH];
__device__ __align__(16) __nv_bfloat16 d_alo[MM*HH];
__device__ __align__(16) __nv_bfloat16 d_w0hi[HH*K1P];
__device__ __align__(16) __nv_bfloat16 d_w0lo[HH*K1P];
__device__ __align__(16) __nv_bfloat16 d_w1hi[HH*HH];
__device__ __align__(16) __nv_bfloat16 d_w1lo[HH*HH];
__device__ __align__(16) __nv_bfloat16 d_w2hi[HH*HH];
__device__ __align__(16) __nv_bfloat16 d_w2lo[HH*HH];

__device__ float d_dis[NN];
__device__ float d_dinv[NN];
__device__ int   d_cnt[NN];
__device__ int   d_rowptr[NN+1];
__device__ int   d_cursor[NN];
__device__ int   d_src[EE];
__device__ float d_wgt[EE];
__device__ int   d_row32[EE];
__device__ int   d_col32[EE];
__device__ float d_g[BSZ*NN];
__device__ float d_zacc[BSZ*HFCC];
__device__ float d_z[BSZ*HFCC];

__device__ __forceinline__ float elu1(float x) { return x > 0.f ? x : expm1f(x); }

__device__ __forceinline__ uint32_t smem_u32(const void* p) {
    uint32_t a;
    asm("{ .reg .u64 t; cvta.to.shared.u64 t, %1; cvt.u32.u64 %0, t; }" : "=r"(a) : "l"(p));
    return a;
}
__device__ __forceinline__ void ldm_x4(uint32_t& r0, uint32_t& r1, uint32_t& r2, uint32_t& r3, uint32_t addr)
{
    asm volatile("ldmatrix.sync.aligned.m8n8.x4.shared.b16 {%0,%1,%2,%3}, [%4];"
                 : "=r"(r0), "=r"(r1), "=r"(r2), "=r"(r3) : "r"(addr));
}
__device__ __forceinline__ void mma16816(float* c, uint32_t a0, uint32_t a1, uint32_t a2, uint32_t a3,
                                         uint32_t b0, uint32_t b1)
{
    asm volatile(
        "mma.sync.aligned.m16n8k16.row.col.f32.bf16.bf16.f32 "
        "{%0,%1,%2,%3}, {%4,%5,%6,%7}, {%8,%9}, {%0,%1,%2,%3};"
        : "+f"(c[0]), "+f"(c[1]), "+f"(c[2]), "+f"(c[3])
        : "r"(a0), "r"(a1), "r"(a2), "r"(a3), "r"(b0), "r"(b1));
}
__device__ __forceinline__ void cp16(uint32_t dst, const void* src, uint32_t srcsize)
{
    asm volatile("cp.async.cg.shared.global [%0], [%1], 16, %2;"
                 :: "r"(dst), "l"(src), "r"(srcsize) : "memory");
}
__device__ __forceinline__ void cp_commit() { asm volatile("cp.async.commit_group;" ::: "memory"); }

// ------------------- graph preprocessing -------------------
__global__ void zero_k(const float* __restrict__ fcb)
{
    int i = blockIdx.x * 256 + threadIdx.x;
    if (i < NN) { d_cnt[i] = 0; d_cursor[i] = 0; }
    if (i < BSZ*HFCC) d_zacc[i] = 0.f;
    if (i < BSZ*NN) d_g[i] = fcb[0];
}

// edge_index may be int64 or int32 (auto-detect).
__global__ void edges_k(const void* __restrict__ ei_raw)
{
    __shared__ int is64;
    const int* ei32 = (const int*)ei_raw;
    if (threadIdx.x == 0) {
        int allz = 1;
        for (int i = 0; i < 64; i++) if (ei32[2 * i + 1] != 0) { allz = 0; break; }
        is64 = allz;
    }
    __syncthreads();

    int e = blockIdx.x * 256 + threadIdx.x;
    if (e >= EE) return;
    int r, c;
    if (is64) {
        const long long* ei = (const long long*)ei_raw;
        r = (int)ei[e];
        c = (int)ei[EE + e];
    } else {
        r = ei32[e];
        c = ei32[EE + e];
    }
    d_row32[e] = r;
    d_col32[e] = c;
    atomicAdd(&d_cnt[c], 1);
}

__global__ void deg_k()
{
    int j = blockIdx.x * 256 + threadIdx.x;
    if (j >= NN) return;
    float dg = (float)d_cnt[j] + 1.0f;
    d_dis[j]  = rsqrtf(dg);
    d_dinv[j] = 1.0f / dg;
}

// exclusive scan d_cnt -> d_rowptr, 1024 threads, 15 elems/thread, shuffle scan
__global__ void scan_k()
{
    __shared__ int wsum[32];
    int t = threadIdx.x, lane = t & 31, w = t >> 5;
    int base = t * 15;
    int v[15];
    int s = 0;
    #pragma unroll
    for (int i = 0; i < 15; i++) {
        int idx = base + i;
        v[i] = (idx < NN) ? d_cnt[idx] : 0;
        s += v[i];
    }
    int ps = s;
    #pragma unroll
    for (int o = 1; o < 32; o <<= 1) {
        int u = __shfl_up_sync(0xffffffffu, ps, o);
        if (lane >= o) ps += u;
    }
    if (lane == 31) wsum[w] = ps;
    __syncthreads();
    if (w == 0) {
        int ws = wsum[lane];
        #pragma unroll
        for (int o = 1; o < 32; o <<= 1) {
            int u = __shfl_up_sync(0xffffffffu, ws, o);
            if (lane >= o) ws += u;
        }
        wsum[lane] = ws;
    }
    __syncthreads();
    int prefix = ps - s + (w > 0 ? wsum[w - 1] : 0);
    #pragma unroll
    for (int i = 0; i < 15; i++) {
        int idx = base + i;
        if (idx <= NN) d_rowptr[idx] = prefix;
        prefix += v[i];
    }
}

__global__ void fill_k()
{
    int e = blockIdx.x * 256 + threadIdx.x;
    if (e >= EE) return;
    int c = d_col32[e];
    int r = d_row32[e];
    int p = atomicAdd(&d_cursor[c], 1);
    int pos = d_rowptr[c] + p;
    d_src[pos] = r;
    d_wgt[pos] = d_dis[r] * d_dis[c];
}

// ------------------- input concat -> bf16 hi/lo, padded K=160 -------------------
__global__ void concat_k(const float* __restrict__ x, const float* __restrict__ pe)
{
    int idx = blockIdx.x * 256 + threadIdx.x;
    if (idx >= MM * K1P) return;
    int r = idx / K1P;
    int k = idx - r * K1P;
    int n = r >> 3, b = r & 7;
    float v = 0.f;
    if (k < FF) v = x[(b * NN + n) * FF + k];
    else if (k < K1) v = pe[n * GG + (k - FF)];
    __nv_bfloat16 h = __float2bfloat16(v);
    d_a0hi[idx] = h;
    d_a0lo[idx] = __float2bfloat16(v - __bfloat162float(h));
}

// ------------------- weight transpose + bf16 hi/lo split: [K,256] -> [256,Kpad] -------------------
__global__ void convw_k(const float* __restrict__ W, __nv_bfloat16* __restrict__ hi,
                        __nv_bfloat16* __restrict__ lo, int K, int Kpad)
{
    int idx = blockIdx.x * 256 + threadIdx.x;
    if (idx >= HH * Kpad) return;
    int n = idx / Kpad, k = idx - n * Kpad;
    float v = (k < K) ? W[k * HH + n] : 0.f;
    __nv_bfloat16 h = __float2bfloat16(v);
    hi[idx] = h;
    lo[idx] = __float2bfloat16(v - __bfloat162float(h));
}

// ------------------- mma.sync bf16 hi/lo GEMM, 3-stage cp.async pipeline ---------
// d_hwh[M,256](fp16) = A @ W^T.  A [M][Kpad] bf16 hi/lo; W [256 n][Kpad k] bf16 hi/lo.
// Grid (946, 2): CTA tile 128m x 128n. 8 warps: warp tile 32m x 64n.
#define ASTRIDE 40
#define TILE_B  (128 * ASTRIDE * 2)    // 10240 bytes per operand tile
#define STAGE_B (4 * TILE_B)           // 40960 bytes per stage
#define GEMM_DSMEM (3 * STAGE_B)       // 122880

__global__ __launch_bounds__(256) void mma_gemm_k(
    const __nv_bfloat16* __restrict__ Ahi, const __nv_bfloat16* __restrict__ Alo,
    const __nv_bfloat16* __restrict__ Whi, const __nv_bfloat16* __restrict__ Wlo,
    int Kpad)
{
    extern __shared__ char dsm[];
    uint32_t dsm_b = smem_u32(dsm);

    int tid = threadIdx.x, wid = tid >> 5, lane = tid & 31;
    int rowBase = blockIdx.x * 128;
    int colBase = blockIdx.y * 128;
    int wm = wid >> 1, wn = wid & 1;
    int m0 = wm * 32, n0 = wn * 64;

    float acc[2][8][4];
    #pragma unroll
    for (int i = 0; i < 2; i++)
        #pragma unroll
        for (int j = 0; j < 8; j++)
            #pragma unroll
            for (int q = 0; q < 4; q++) acc[i][j][q] = 0.f;

    int nch = Kpad >> 5;

    auto load_chunk = [&](int c, int st) {
        int k0 = c * 32;
        uint32_t sbase = dsm_b + st * STAGE_B;
        #pragma unroll
        for (int ii = 0; ii < 2; ii++) {
            int i = tid + ii * 256;
            int r = i >> 2, q = i & 3;
            uint32_t doff = (uint32_t)(r * (ASTRIDE * 2) + q * 16);
            int grow = rowBase + r;
            uint32_t ok = (grow < MM) ? 16u : 0u;
            int gr = (grow < MM) ? grow : 0;
            cp16(sbase + doff,              Ahi + (size_t)gr * Kpad + k0 + q * 8, ok);
            cp16(sbase + TILE_B + doff,     Alo + (size_t)gr * Kpad + k0 + q * 8, ok);
            int gn = colBase + r;
            cp16(sbase + 2 * TILE_B + doff, Whi + (size_t)gn * Kpad + k0 + q * 8, 16u);
            cp16(sbase + 3 * TILE_B + doff, Wlo + (size_t)gn * Kpad + k0 + q * 8, 16u);
        }
        cp_commit();
    };

    load_chunk(0, 0);
    if (nch > 1) load_chunk(1, 1);

    int st = 0;
    for (int c = 0; c < nch; c++) {
        if (c + 2 < nch) {
            int st2 = st + 2; if (st2 >= 3) st2 -= 3;
            load_chunk(c + 2, st2);
            asm volatile("cp.async.wait_group 2;" ::: "memory");
        } else if (c + 1 < nch) {
            asm volatile("cp.async.wait_group 1;" ::: "memory");
        } else {
            asm volatile("cp.async.wait_group 0;" ::: "memory");
        }
        __syncthreads();

        char* stg = dsm + st * STAGE_B;
        __nv_bfloat16* AsH = (__nv_bfloat16*)(stg);
        __nv_bfloat16* AsL = (__nv_bfloat16*)(stg + TILE_B);
        __nv_bfloat16* BsH = (__nv_bfloat16*)(stg + 2 * TILE_B);
        __nv_bfloat16* BsL = (__nv_bfloat16*)(stg + 3 * TILE_B);

        #pragma unroll
        for (int s = 0; s < 2; s++) {
            int kk = s * 16;
            uint32_t ah[2][4], al[2][4];
            {
                int t = lane >> 3, rr = lane & 7;
                int arow = ((t & 1) << 3) + rr;
                int acol = kk + ((t >> 1) << 3);
                #pragma unroll
                for (int mt = 0; mt < 2; mt++) {
                    uint32_t ad = smem_u32(&AsH[(m0 + mt * 16 + arow) * ASTRIDE + acol]);
                    ldm_x4(ah[mt][0], ah[mt][1], ah[mt][2], ah[mt][3], ad);
                    uint32_t ad2 = smem_u32(&AsL[(m0 + mt * 16 + arow) * ASTRIDE + acol]);
                    ldm_x4(al[mt][0], al[mt][1], al[mt][2], al[mt][3], ad2);
                }
            }
            uint32_t bh[8][2], bl[8][2];
            {
                int brow = (((lane >> 4) & 1) << 3) + (lane & 7);
                int bcol = kk + (((lane >> 3) & 1) << 3);
                #pragma unroll
                for (int nt = 0; nt < 4; nt++) {
                    uint32_t bd = smem_u32(&BsH[(n0 + nt * 16 + brow) * ASTRIDE + bcol]);
                    uint32_t r0, r1, r2, r3;
                    ldm_x4(r0, r1, r2, r3, bd);
                    bh[nt * 2][0] = r0; bh[nt * 2][1] = r1;
                    bh[nt * 2 + 1][0] = r2; bh[nt * 2 + 1][1] = r3;
                    uint32_t bd2 = smem_u32(&BsL[(n0 + nt * 16 + brow) * ASTRIDE + bcol]);
                    ldm_x4(r0, r1, r2, r3, bd2);
                    bl[nt * 2][0] = r0; bl[nt * 2][1] = r1;
                    bl[nt * 2 + 1][0] = r2; bl[nt * 2 + 1][1] = r3;
                }
            }
            #pragma unroll
            for (int mt = 0; mt < 2; mt++)
                #pragma unroll
                for (int nt = 0; nt < 8; nt++) {
                    mma16816(acc[mt][nt], ah[mt][0], ah[mt][1], ah[mt][2], ah[mt][3], bh[nt][0], bh[nt][1]);
                    mma16816(acc[mt][nt], ah[mt][0], ah[mt][1], ah[mt][2], ah[mt][3], bl[nt][0], bl[nt][1]);
                    mma16816(acc[mt][nt], al[mt][0], al[mt][1], al[mt][2], al[mt][3], bh[nt][0], bh[nt][1]);
                }
        }
        __syncthreads();
        if (++st == 3) st = 0;
    }

    // ---- epilogue: convert to fp16, store ----
    int g = lane >> 2, tig = lane & 3;
    #pragma unroll
    for (int mt = 0; mt < 2; mt++) {
        int r0 = rowBase + m0 + mt * 16 + g;
        int r1 = r0 + 8;
        #pragma unroll
        for (int nt = 0; nt < 8; nt++) {
            int col = colBase + n0 + nt * 8 + tig * 2;
            if (r0 < MM) {
                __half2 p = __floats2half2_rn(acc[mt][nt][0], acc[mt][nt][1]);
                *(__half2*)(d_hwh + (size_t)r0 * 256 + col) = p;
            }
            if (r1 < MM) {
                __half2 p = __floats2half2_rn(acc[mt][nt][2], acc[mt][nt][3]);
                *(__half2*)(d_hwh + (size_t)r1 * 256 + col) = p;
            }
        }
    }
}

// ------------------- CSR gather (fp16 in) + self-loop + bias + ELU + fused fc-dot ----
// One launch per layer. Block = 256 threads per node: warp = batch, lane covers 8 feats.
// fp16 row = 4KB/node -> 62MB working set, fully L2 resident.
__global__ __launch_bounds__(256) void gather_k(const float* __restrict__ bias,
                                                const float* __restrict__ fcW,
                                                int layer)
{
    int j = blockIdx.x;
    int tid = threadIdx.x;
    int b = tid >> 5, lane = tid & 31;
    int f8 = lane * 8;                      // feature base (0..248)

    const __half* hw = d_hwh;
    size_t selfoff = ((size_t)(j * 8 + b)) * 256 + f8;

    float acc[8];
    {
        float di = d_dinv[j];
        uint4 sv = *(const uint4*)(hw + selfoff);
        const __half2* p = (const __half2*)&sv;
        #pragma unroll
        for (int q = 0; q < 4; q++) {
            float2 f = __half22float2(p[q]);
            acc[2 * q]     = f.x * di;
            acc[2 * q + 1] = f.y * di;
        }
    }

    int s0 = d_rowptr[j], s1 = d_rowptr[j + 1];
    int k = s0;
    #define ACC8(v, w) { const __half2* pp = (const __half2*)&(v); \
        _Pragma("unroll") for (int q = 0; q < 4; q++) { float2 f = __half22float2(pp[q]); \
            acc[2*q]   = fmaf((w), f.x, acc[2*q]); \
            acc[2*q+1] = fmaf((w), f.y, acc[2*q+1]); } }

    for (; k + 4 <= s1; k += 4) {
        int sa = d_src[k], sb = d_src[k + 1], sc = d_src[k + 2], sd = d_src[k + 3];
        float wa = d_wgt[k], wb = d_wgt[k + 1], wc = d_wgt[k + 2], wd = d_wgt[k + 3];
        uint4 va = *(const uint4*)(hw + ((size_t)(sa * 8 + b)) * 256 + f8);
        uint4 vb = *(const uint4*)(hw + ((size_t)(sb * 8 + b)) * 256 + f8);
        uint4 vc = *(const uint4*)(hw + ((size_t)(sc * 8 + b)) * 256 + f8);
        uint4 vd = *(const uint4*)(hw + ((size_t)(sd * 8 + b)) * 256 + f8);
        ACC8(va, wa) ACC8(vb, wb) ACC8(vc, wc) ACC8(vd, wd)
    }
    for (; k < s1; k++) {
        int s = d_src[k];
        float w = d_wgt[k];
        uint4 v = *(const uint4*)(hw + ((size_t)(s * 8 + b)) * 256 + f8);
        ACC8(v, w)
    }
    #undef ACC8

    // bias + ELU
    #pragma unroll
    for (int q = 0; q < 8; q++) acc[q] = elu1(acc[q] + bias[f8 + q]);

    // next-layer bf16 hi/lo operand (layers 0,1); streaming stores
    if (layer < 2) {
        uint4 hv, lv;
        __nv_bfloat162 t;
        float lo0, lo1;
        #pragma unroll
        for (int q = 0; q < 4; q++) {
            t = __floats2bfloat162_rn(acc[2 * q], acc[2 * q + 1]);
            ((uint32_t*)&hv)[q] = *(uint32_t*)&t;
            lo0 = acc[2 * q]     - __bfloat162float(t.x);
            lo1 = acc[2 * q + 1] - __bfloat162float(t.y);
            t = __floats2bfloat162_rn(lo0, lo1);
            ((uint32_t*)&lv)[q] = *(uint32_t*)&t;
        }
        __stcs((uint4*)(d_ahi + selfoff), hv);
        __stcs((uint4*)(d_alo + selfoff), lv);
    }

    // fused JK/fc contribution: g[b][j] += sum_h h*fcW[3h+layer]
    float gc = 0.f;
    #pragma unroll
    for (int q = 0; q < 8; q++) gc = fmaf(acc[q], fcW[3 * (f8 + q) + layer], gc);
    #pragma unroll
    for (int o = 16; o; o >>= 1) gc += __shfl_xor_sync(0xffffffffu, gc, o);
    if (lane == 0) atomicAdd(&d_g[b * NN + j], gc);
}

// ------------------- z = elu(g @ lin1_W + lin1_b), split-K -------------------
__global__ __launch_bounds__(256) void lin1_k(const float* __restrict__ W)
{
    int o = blockIdx.x * 256 + threadIdx.x;  // 0..511
    const int NS = (NN + 63) / 64;           // 237
    int n0 = blockIdx.y * NS;
    int n1 = n0 + NS; if (n1 > NN) n1 = NN;
    float acc[8];
    #pragma unroll
    for (int b = 0; b < 8; b++) acc[b] = 0.f;
    for (int n = n0; n < n1; n++) {
        float w = W[n * 512 + o];
        #pragma unroll
        for (int b = 0; b < 8; b++) acc[b] = fmaf(d_g[b * NN + n], w, acc[b]);
    }
    #pragma unroll
    for (int b = 0; b < 8; b++) atomicAdd(&d_zacc[b * 512 + o], acc[b]);
}

__global__ void lin1fin_k(const float* __restrict__ bias)
{
    int i = blockIdx.x * 256 + threadIdx.x;
    if (i >= BSZ * HFCC) return;
    d_z[i] = elu1(d_zacc[i] + bias[i & 511]);
}

// ------------------- out = log_softmax(z @ lin2_W + lin2_b) -------------------
__global__ void final_k(const float* __restrict__ W, const float* __restrict__ bv,
                        float* __restrict__ out)
{
    int b = threadIdx.x >> 5;
    int lane = threadIdx.x & 31;
    float a0 = 0.f, a1 = 0.f;
    for (int i = lane; i < 512; i += 32) {
        float z = d_z[b * 512 + i];
        a0 = fmaf(z, W[2 * i],     a0);
        a1 = fmaf(z, W[2 * i + 1], a1);
    }
    #pragma unroll
    for (int o = 16; o; o >>= 1) {
        a0 += __shfl_xor_sync(0xffffffffu, a0, o);
        a1 += __shfl_xor_sync(0xffffffffu, a1, o);
    }
    if (lane == 0) {
        float v0 = a0 + bv[0], v1 = a1 + bv[1];
        float m = fmaxf(v0, v1);
        float l = m + logf(expf(v0 - m) + expf(v1 - m));
        out[2 * b]     = v0 - l;
        out[2 * b + 1] = v1 - l;
    }
}

// ------------------- host launcher -------------------
extern "C" void kernel_launch(void* const* d_in, const int* in_sizes, int n_in,
                              void* d_out, int out_size)
{
    const float* x      = (const float*)d_in[0];
    // d_in[1] = batch (unused, all zeros)
    const void*  ei     = d_in[2];                 // int32 or int64, auto-detected
    const float* pe     = (const float*)d_in[3];
    const float* W1     = (const float*)d_in[4];
    const float* b1     = (const float*)d_in[5];
    const float* W2     = (const float*)d_in[6];
    const float* b2     = (const float*)d_in[7];
    const float* W3     = (const float*)d_in[8];
    const float* b3     = (const float*)d_in[9];
    const float* fcW    = (const float*)d_in[10];
    const float* fcb    = (const float*)d_in[11];
    const float* lin1W  = (const float*)d_in[12];
    const float* lin1b  = (const float*)d_in[13];
    const float* lin2W  = (const float*)d_in[14];
    const float* lin2b  = (const float*)d_in[15];
    float* out = (float*)d_out;

    cudaFuncSetAttribute(mma_gemm_k, cudaFuncAttributeMaxDynamicSharedMemorySize, GEMM_DSMEM);

    // resolve device-global addresses for kernel args
    __nv_bfloat16 *a0hi, *a0lo, *ahi, *alo, *w0hi, *w0lo, *w1hi, *w1lo, *w2hi, *w2lo;
    cudaGetSymbolAddress((void**)&a0hi, d_a0hi);
    cudaGetSymbolAddress((void**)&a0lo, d_a0lo);
    cudaGetSymbolAddress((void**)&ahi,  d_ahi);
    cudaGetSymbolAddress((void**)&alo,  d_alo);
    cudaGetSymbolAddress((void**)&w0hi, d_w0hi);
    cudaGetSymbolAddress((void**)&w0lo, d_w0lo);
    cudaGetSymbolAddress((void**)&w1hi, d_w1hi);
    cudaGetSymbolAddress((void**)&w1lo, d_w1lo);
    cudaGetSymbolAddress((void**)&w2hi, d_w2hi);
    cudaGetSymbolAddress((void**)&w2lo, d_w2lo);

    // graph preprocessing
    zero_k<<<(BSZ * NN + 255) / 256, 256>>>(fcb);
    edges_k<<<(EE + 255) / 256, 256>>>(ei);
    deg_k<<<(NN + 255) / 256, 256>>>();
    scan_k<<<1, 1024>>>();
    fill_k<<<(EE + 255) / 256, 256>>>();

    // operand conversion
    concat_k<<<(MM * K1P + 255) / 256, 256>>>(x, pe);
    convw_k<<<(HH * K1P + 255) / 256, 256>>>(W1, w0hi, w0lo, K1, K1P);
    convw_k<<<(HH * HH + 255) / 256, 256>>>(W2, w1hi, w1lo, HH, HH);
    convw_k<<<(HH * HH + 255) / 256, 256>>>(W3, w2hi, w2lo, HH, HH);

    const int MTILES = (MM + 127) / 128;  // 946
    dim3 ggrid(MTILES, 2);

    // layer 1
    mma_gemm_k<<<ggrid, 256, GEMM_DSMEM>>>(a0hi, a0lo, w0hi, w0lo, K1P);
    gather_k<<<NN, 256>>>(b1, fcW, 0);
    // layer 2
    mma_gemm_k<<<ggrid, 256, GEMM_DSMEM>>>(ahi, alo, w1hi, w1lo, HH);
    gather_k<<<NN, 256>>>(b2, fcW, 1);
    // layer 3
    mma_gemm_k<<<ggrid, 256, GEMM_DSMEM>>>(ahi, alo, w2hi, w2lo, HH);
    gather_k<<<NN, 256>>>(b3, fcW, 2);

    // head
    {
        dim3 lg(2, 64);
        lin1_k<<<lg, 256>>>(lin1W);
    }
    lin1fin_k<<<16, 256>>>(lin1b);
    final_k<<<1, 256>>>(lin2W, lin2b, out);
}

// round 12
// speedup vs baseline: 2.5650x; 1.2412x over previous
#include <cuda_runtime.h>
#include <cuda_fp16.h>
#include <math.h>
#include <stdint.h>

// Problem constants (fixed shapes)
#define NN   15135
#define BSZ  8
#define FF   64
#define GG   73
#define HH   256
#define EE   242160
#define MM   (NN*BSZ)       // 121080 rows
#define K1   (FF+GG)        // 137
#define K1P  160            // padded to multiple of 32
#define HFCC 512

// ------------------- scratch (device globals; no allocation) -------------------
__device__ __align__(16) __half d_hwh[MM*HH];   // GEMM output (fp16, pre-aggregation)
__device__ __align__(16) __half d_a0f[MM*K1P];  // layer-1 A operand (fp16)
__device__ __align__(16) __half d_af[MM*HH];    // layers-2/3 A operand (fp16, gather output)
// fp16 hi/lo weights [256 n][Kpad k]
__device__ __align__(16) __half d_w0hi[HH*K1P];
__device__ __align__(16) __half d_w0lo[HH*K1P];
__device__ __align__(16) __half d_w1hi[HH*HH];
__device__ __align__(16) __half d_w1lo[HH*HH];
__device__ __align__(16) __half d_w2hi[HH*HH];
__device__ __align__(16) __half d_w2lo[HH*HH];

__device__ float d_dis[NN];
__device__ float d_dinv[NN];
__device__ int   d_cnt[NN];
__device__ int   d_rowptr[NN+1];
__device__ int   d_cursor[NN];
__device__ int   d_src[EE];
__device__ float d_wgt[EE];
__device__ int   d_row32[EE];
__device__ int   d_col32[EE];
__device__ float d_g[BSZ*NN];
__device__ float d_zacc[BSZ*HFCC];
__device__ float d_z[BSZ*HFCC];

__device__ __forceinline__ float elu1(float x) { return x > 0.f ? x : expm1f(x); }

__device__ __forceinline__ uint32_t smem_u32(const void* p) {
    uint32_t a;
    asm("{ .reg .u64 t; cvta.to.shared.u64 t, %1; cvt.u32.u64 %0, t; }" : "=r"(a) : "l"(p));
    return a;
}
__device__ __forceinline__ void ldm_x4(uint32_t& r0, uint32_t& r1, uint32_t& r2, uint32_t& r3, uint32_t addr)
{
    asm volatile("ldmatrix.sync.aligned.m8n8.x4.shared.b16 {%0,%1,%2,%3}, [%4];"
                 : "=r"(r0), "=r"(r1), "=r"(r2), "=r"(r3) : "r"(addr));
}
__device__ __forceinline__ void mma16816h(float* c, uint32_t a0, uint32_t a1, uint32_t a2, uint32_t a3,
                                          uint32_t b0, uint32_t b1)
{
    asm volatile(
        "mma.sync.aligned.m16n8k16.row.col.f32.f16.f16.f32 "
        "{%0,%1,%2,%3}, {%4,%5,%6,%7}, {%8,%9}, {%0,%1,%2,%3};"
        : "+f"(c[0]), "+f"(c[1]), "+f"(c[2]), "+f"(c[3])
        : "r"(a0), "r"(a1), "r"(a2), "r"(a3), "r"(b0), "r"(b1));
}
__device__ __forceinline__ void cp16(uint32_t dst, const void* src, uint32_t srcsize)
{
    asm volatile("cp.async.cg.shared.global [%0], [%1], 16, %2;"
                 :: "r"(dst), "l"(src), "r"(srcsize) : "memory");
}
__device__ __forceinline__ void cp_commit() { asm volatile("cp.async.commit_group;" ::: "memory"); }

// ------------------- graph preprocessing -------------------
__global__ void zero_k(const float* __restrict__ fcb)
{
    int i = blockIdx.x * 256 + threadIdx.x;
    if (i < NN) { d_cnt[i] = 0; d_cursor[i] = 0; }
    if (i < BSZ*HFCC) d_zacc[i] = 0.f;
    if (i < BSZ*NN) d_g[i] = fcb[0];
}

// edge_index may be int64 or int32 (auto-detect).
__global__ void edges_k(const void* __restrict__ ei_raw)
{
    __shared__ int is64;
    const int* ei32 = (const int*)ei_raw;
    if (threadIdx.x == 0) {
        int allz = 1;
        for (int i = 0; i < 64; i++) if (ei32[2 * i + 1] != 0) { allz = 0; break; }
        is64 = allz;
    }
    __syncthreads();

    int e = blockIdx.x * 256 + threadIdx.x;
    if (e >= EE) return;
    int r, c;
    if (is64) {
        const long long* ei = (const long long*)ei_raw;
        r = (int)ei[e];
        c = (int)ei[EE + e];
    } else {
        r = ei32[e];
        c = ei32[EE + e];
    }
    d_row32[e] = r;
    d_col32[e] = c;
    atomicAdd(&d_cnt[c], 1);
}

__global__ void deg_k()
{
    int j = blockIdx.x * 256 + threadIdx.x;
    if (j >= NN) return;
    float dg = (float)d_cnt[j] + 1.0f;
    d_dis[j]  = rsqrtf(dg);
    d_dinv[j] = 1.0f / dg;
}

// exclusive scan d_cnt -> d_rowptr, 1024 threads, 15 elems/thread, shuffle scan
__global__ void scan_k()
{
    __shared__ int wsum[32];
    int t = threadIdx.x, lane = t & 31, w = t >> 5;
    int base = t * 15;
    int v[15];
    int s = 0;
    #pragma unroll
    for (int i = 0; i < 15; i++) {
        int idx = base + i;
        v[i] = (idx < NN) ? d_cnt[idx] : 0;
        s += v[i];
    }
    int ps = s;
    #pragma unroll
    for (int o = 1; o < 32; o <<= 1) {
        int u = __shfl_up_sync(0xffffffffu, ps, o);
        if (lane >= o) ps += u;
    }
    if (lane == 31) wsum[w] = ps;
    __syncthreads();
    if (w == 0) {
        int ws = wsum[lane];
        #pragma unroll
        for (int o = 1; o < 32; o <<= 1) {
            int u = __shfl_up_sync(0xffffffffu, ws, o);
            if (lane >= o) ws += u;
        }
        wsum[lane] = ws;
    }
    __syncthreads();
    int prefix = ps - s + (w > 0 ? wsum[w - 1] : 0);
    #pragma unroll
    for (int i = 0; i < 15; i++) {
        int idx = base + i;
        if (idx <= NN) d_rowptr[idx] = prefix;
        prefix += v[i];
    }
}

__global__ void fill_k()
{
    int e = blockIdx.x * 256 + threadIdx.x;
    if (e >= EE) return;
    int c = d_col32[e];
    int r = d_row32[e];
    int p = atomicAdd(&d_cursor[c], 1);
    int pos = d_rowptr[c] + p;
    d_src[pos] = r;
    d_wgt[pos] = d_dis[r] * d_dis[c];
}

// ------------------- input concat -> fp16, padded K=160 -------------------
__global__ void concat_k(const float* __restrict__ x, const float* __restrict__ pe)
{
    int idx = blockIdx.x * 256 + threadIdx.x;
    if (idx >= MM * K1P) return;
    int r = idx / K1P;
    int k = idx - r * K1P;
    int n = r >> 3, b = r & 7;
    float v = 0.f;
    if (k < FF) v = x[(b * NN + n) * FF + k];
    else if (k < K1) v = pe[n * GG + (k - FF)];
    d_a0f[idx] = __float2half_rn(v);
}

// ------------------- weight transpose + fp16 hi/lo split: [K,256] -> [256,Kpad] -------------------
__global__ void convw_k(const float* __restrict__ W, __half* __restrict__ hi,
                        __half* __restrict__ lo, int K, int Kpad)
{
    int idx = blockIdx.x * 256 + threadIdx.x;
    if (idx >= HH * Kpad) return;
    int n = idx / Kpad, k = idx - n * Kpad;
    float v = (k < K) ? W[k * HH + n] : 0.f;
    __half h = __float2half_rn(v);
    hi[idx] = h;
    lo[idx] = __float2half_rn(v - __half2float(h));
}

// ------------------- mma.sync fp16 2-pass GEMM, 3-stage cp.async pipeline ---------
// d_hwh[M,256](fp16) = A @ W^T.  A [M][Kpad] fp16; W [256 n][Kpad k] fp16 hi/lo.
// Grid (946, 2): CTA tile 128m x 128n. 8 warps: warp tile 32m x 64n.
#define ASTRIDE 40
#define TILE_B  (128 * ASTRIDE * 2)    // 10240 bytes per operand tile
#define STAGE_B (3 * TILE_B)           // 30720 bytes per stage (A, Bh, Bl)
#define GEMM_DSMEM (3 * STAGE_B)       // 92160

__global__ __launch_bounds__(256) void mma_gemm_k(
    const __half* __restrict__ Af,
    const __half* __restrict__ Whi, const __half* __restrict__ Wlo,
    int Kpad)
{
    extern __shared__ char dsm[];
    uint32_t dsm_b = smem_u32(dsm);

    int tid = threadIdx.x, wid = tid >> 5, lane = tid & 31;
    int rowBase = blockIdx.x * 128;
    int colBase = blockIdx.y * 128;
    int wm = wid >> 1, wn = wid & 1;
    int m0 = wm * 32, n0 = wn * 64;

    float acc[2][8][4];
    #pragma unroll
    for (int i = 0; i < 2; i++)
        #pragma unroll
        for (int j = 0; j < 8; j++)
            #pragma unroll
            for (int q = 0; q < 4; q++) acc[i][j][q] = 0.f;

    int nch = Kpad >> 5;

    auto load_chunk = [&](int c, int st) {
        int k0 = c * 32;
        uint32_t sbase = dsm_b + st * STAGE_B;
        #pragma unroll
        for (int ii = 0; ii < 2; ii++) {
            int i = tid + ii * 256;
            int r = i >> 2, q = i & 3;
            uint32_t doff = (uint32_t)(r * (ASTRIDE * 2) + q * 16);
            int grow = rowBase + r;
            uint32_t ok = (grow < MM) ? 16u : 0u;
            int gr = (grow < MM) ? grow : 0;
            cp16(sbase + doff,              Af  + (size_t)gr * Kpad + k0 + q * 8, ok);
            int gn = colBase + r;
            cp16(sbase + TILE_B + doff,     Whi + (size_t)gn * Kpad + k0 + q * 8, 16u);
            cp16(sbase + 2 * TILE_B + doff, Wlo + (size_t)gn * Kpad + k0 + q * 8, 16u);
        }
        cp_commit();
    };

    load_chunk(0, 0);
    if (nch > 1) load_chunk(1, 1);

    int st = 0;
    for (int c = 0; c < nch; c++) {
        if (c + 2 < nch) {
            int st2 = st + 2; if (st2 >= 3) st2 -= 3;
            load_chunk(c + 2, st2);
            asm volatile("cp.async.wait_group 2;" ::: "memory");
        } else if (c + 1 < nch) {
            asm volatile("cp.async.wait_group 1;" ::: "memory");
        } else {
            asm volatile("cp.async.wait_group 0;" ::: "memory");
        }
        __syncthreads();

        char* stg = dsm + st * STAGE_B;
        __half* As  = (__half*)(stg);
        __half* BsH = (__half*)(stg + TILE_B);
        __half* BsL = (__half*)(stg + 2 * TILE_B);

        #pragma unroll
        for (int s = 0; s < 2; s++) {
            int kk = s * 16;
            uint32_t ah[2][4];
            {
                int t = lane >> 3, rr = lane & 7;
                int arow = ((t & 1) << 3) + rr;
                int acol = kk + ((t >> 1) << 3);
                #pragma unroll
                for (int mt = 0; mt < 2; mt++) {
                    uint32_t ad = smem_u32(&As[(m0 + mt * 16 + arow) * ASTRIDE + acol]);
                    ldm_x4(ah[mt][0], ah[mt][1], ah[mt][2], ah[mt][3], ad);
                }
            }
            uint32_t bh[8][2], bl[8][2];
            {
                int brow = (((lane >> 4) & 1) << 3) + (lane & 7);
                int bcol = kk + (((lane >> 3) & 1) << 3);
                #pragma unroll
                for (int nt = 0; nt < 4; nt++) {
                    uint32_t bd = smem_u32(&BsH[(n0 + nt * 16 + brow) * ASTRIDE + bcol]);
                    uint32_t r0, r1, r2, r3;
                    ldm_x4(r0, r1, r2, r3, bd);
                    bh[nt * 2][0] = r0; bh[nt * 2][1] = r1;
                    bh[nt * 2 + 1][0] = r2; bh[nt * 2 + 1][1] = r3;
                    uint32_t bd2 = smem_u32(&BsL[(n0 + nt * 16 + brow) * ASTRIDE + bcol]);
                    ldm_x4(r0, r1, r2, r3, bd2);
                    bl[nt * 2][0] = r0; bl[nt * 2][1] = r1;
                    bl[nt * 2 + 1][0] = r2; bl[nt * 2 + 1][1] = r3;
                }
            }
            #pragma unroll
            for (int mt = 0; mt < 2; mt++)
                #pragma unroll
                for (int nt = 0; nt < 8; nt++) {
                    mma16816h(acc[mt][nt], ah[mt][0], ah[mt][1], ah[mt][2], ah[mt][3], bh[nt][0], bh[nt][1]);
                    mma16816h(acc[mt][nt], ah[mt][0], ah[mt][1], ah[mt][2], ah[mt][3], bl[nt][0], bl[nt][1]);
                }
        }
        __syncthreads();
        if (++st == 3) st = 0;
    }

    // ---- epilogue: convert to fp16, store ----
    int g = lane >> 2, tig = lane & 3;
    #pragma unroll
    for (int mt = 0; mt < 2; mt++) {
        int r0 = rowBase + m0 + mt * 16 + g;
        int r1 = r0 + 8;
        #pragma unroll
        for (int nt = 0; nt < 8; nt++) {
            int col = colBase + n0 + nt * 8 + tig * 2;
            if (r0 < MM) {
                __half2 p = __floats2half2_rn(acc[mt][nt][0], acc[mt][nt][1]);
                *(__half2*)(d_hwh + (size_t)r0 * 256 + col) = p;
            }
            if (r1 < MM) {
                __half2 p = __floats2half2_rn(acc[mt][nt][2], acc[mt][nt][3]);
                *(__half2*)(d_hwh + (size_t)r1 * 256 + col) = p;
            }
        }
    }
}

// ------------------- CSR gather (fp16 in) + self-loop + bias + ELU + fused fc-dot ----
// One launch per layer. Block = 256 threads per node: warp = batch, lane covers 8 feats.
__global__ __launch_bounds__(256) void gather_k(const float* __restrict__ bias,
                                                const float* __restrict__ fcW,
                                                int layer)
{
    int j = blockIdx.x;
    int tid = threadIdx.x;
    int b = tid >> 5, lane = tid & 31;
    int f8 = lane * 8;                      // feature base (0..248)

    const __half* hw = d_hwh;
    size_t selfoff = ((size_t)(j * 8 + b)) * 256 + f8;

    float acc[8];
    {
        float di = d_dinv[j];
        uint4 sv = *(const uint4*)(hw + selfoff);
        const __half2* p = (const __half2*)&sv;
        #pragma unroll
        for (int q = 0; q < 4; q++) {
            float2 f = __half22float2(p[q]);
            acc[2 * q]     = f.x * di;
            acc[2 * q + 1] = f.y * di;
        }
    }

    int s0 = d_rowptr[j], s1 = d_rowptr[j + 1];
    int k = s0;
    #define ACC8(v, w) { const __half2* pp = (const __half2*)&(v); \
        _Pragma("unroll") for (int q = 0; q < 4; q++) { float2 f = __half22float2(pp[q]); \
            acc[2*q]   = fmaf((w), f.x, acc[2*q]); \
            acc[2*q+1] = fmaf((w), f.y, acc[2*q+1]); } }

    for (; k + 4 <= s1; k += 4) {
        int sa = d_src[k], sb = d_src[k + 1], sc = d_src[k + 2], sd = d_src[k + 3];
        float wa = d_wgt[k], wb = d_wgt[k + 1], wc = d_wgt[k + 2], wd = d_wgt[k + 3];
        uint4 va = *(const uint4*)(hw + ((size_t)(sa * 8 + b)) * 256 + f8);
        uint4 vb = *(const uint4*)(hw + ((size_t)(sb * 8 + b)) * 256 + f8);
        uint4 vc = *(const uint4*)(hw + ((size_t)(sc * 8 + b)) * 256 + f8);
        uint4 vd = *(const uint4*)(hw + ((size_t)(sd * 8 + b)) * 256 + f8);
        ACC8(va, wa) ACC8(vb, wb) ACC8(vc, wc) ACC8(vd, wd)
    }
    for (; k < s1; k++) {
        int s = d_src[k];
        float w = d_wgt[k];
        uint4 v = *(const uint4*)(hw + ((size_t)(s * 8 + b)) * 256 + f8);
        ACC8(v, w)
    }
    #undef ACC8

    // bias + ELU
    #pragma unroll
    for (int q = 0; q < 8; q++) acc[q] = elu1(acc[q] + bias[f8 + q]);

    // next-layer fp16 operand (layers 0,1); streaming stores
    if (layer < 2) {
        uint4 hv;
        #pragma unroll
        for (int q = 0; q < 4; q++) {
            __half2 t = __floats2half2_rn(acc[2 * q], acc[2 * q + 1]);
            ((uint32_t*)&hv)[q] = *(uint32_t*)&t;
        }
        __stcs((uint4*)(d_af + selfoff), hv);
    }

    // fused JK/fc contribution: g[b][j] += sum_h h*fcW[3h+layer]
    float gc = 0.f;
    #pragma unroll
    for (int q = 0; q < 8; q++) gc = fmaf(acc[q], fcW[3 * (f8 + q) + layer], gc);
    #pragma unroll
    for (int o = 16; o; o >>= 1) gc += __shfl_xor_sync(0xffffffffu, gc, o);
    if (lane == 0) atomicAdd(&d_g[b * NN + j], gc);
}

// ------------------- z = elu(g @ lin1_W + lin1_b), split-K -------------------
__global__ __launch_bounds__(256) void lin1_k(const float* __restrict__ W)
{
    int o = blockIdx.x * 256 + threadIdx.x;  // 0..511
    const int NS = (NN + 63) / 64;           // 237
    int n0 = blockIdx.y * NS;
    int n1 = n0 + NS; if (n1 > NN) n1 = NN;
    float acc[8];
    #pragma unroll
    for (int b = 0; b < 8; b++) acc[b] = 0.f;
    for (int n = n0; n < n1; n++) {
        float w = W[n * 512 + o];
        #pragma unroll
        for (int b = 0; b < 8; b++) acc[b] = fmaf(d_g[b * NN + n], w, acc[b]);
    }
    #pragma unroll
    for (int b = 0; b < 8; b++) atomicAdd(&d_zacc[b * 512 + o], acc[b]);
}

__global__ void lin1fin_k(const float* __restrict__ bias)
{
    int i = blockIdx.x * 256 + threadIdx.x;
    if (i >= BSZ * HFCC) return;
    d_z[i] = elu1(d_zacc[i] + bias[i & 511]);
}

// ------------------- out = log_softmax(z @ lin2_W + lin2_b) -------------------
__global__ void final_k(const float* __restrict__ W, const float* __restrict__ bv,
                        float* __restrict__ out)
{
    int b = threadIdx.x >> 5;
    int lane = threadIdx.x & 31;
    float a0 = 0.f, a1 = 0.f;
    for (int i = lane; i < 512; i += 32) {
        float z = d_z[b * 512 + i];
        a0 = fmaf(z, W[2 * i],     a0);
        a1 = fmaf(z, W[2 * i + 1], a1);
    }
    #pragma unroll
    for (int o = 16; o; o >>= 1) {
        a0 += __shfl_xor_sync(0xffffffffu, a0, o);
        a1 += __shfl_xor_sync(0xffffffffu, a1, o);
    }
    if (lane == 0) {
        float v0 = a0 + bv[0], v1 = a1 + bv[1];
        float m = fmaxf(v0, v1);
        float l = m + logf(expf(v0 - m) + expf(v1 - m));
        out[2 * b]     = v0 - l;
        out[2 * b + 1] = v1 - l;
    }
}

// ------------------- host launcher -------------------
extern "C" void kernel_launch(void* const* d_in, const int* in_sizes, int n_in,
                              void* d_out, int out_size)
{
    const float* x      = (const float*)d_in[0];
    // d_in[1] = batch (unused, all zeros)
    const void*  ei     = d_in[2];                 // int32 or int64, auto-detected
    const float* pe     = (const float*)d_in[3];
    const float* W1     = (const float*)d_in[4];
    const float* b1     = (const float*)d_in[5];
    const float* W2     = (const float*)d_in[6];
    const float* b2     = (const float*)d_in[7];
    const float* W3     = (const float*)d_in[8];
    const float* b3     = (const float*)d_in[9];
    const float* fcW    = (const float*)d_in[10];
    const float* fcb    = (const float*)d_in[11];
    const float* lin1W  = (const float*)d_in[12];
    const float* lin1b  = (const float*)d_in[13];
    const float* lin2W  = (const float*)d_in[14];
    const float* lin2b  = (const float*)d_in[15];
    float* out = (float*)d_out;

    cudaFuncSetAttribute(mma_gemm_k, cudaFuncAttributeMaxDynamicSharedMemorySize, GEMM_DSMEM);

    // resolve device-global addresses for kernel args
    __half *a0f, *af, *w0hi, *w0lo, *w1hi, *w1lo, *w2hi, *w2lo;
    cudaGetSymbolAddress((void**)&a0f,  d_a0f);
    cudaGetSymbolAddress((void**)&af,   d_af);
    cudaGetSymbolAddress((void**)&w0hi, d_w0hi);
    cudaGetSymbolAddress((void**)&w0lo, d_w0lo);
    cudaGetSymbolAddress((void**)&w1hi, d_w1hi);
    cudaGetSymbolAddress((void**)&w1lo, d_w1lo);
    cudaGetSymbolAddress((void**)&w2hi, d_w2hi);
    cudaGetSymbolAddress((void**)&w2lo, d_w2lo);

    // graph preprocessing
    zero_k<<<(BSZ * NN + 255) / 256, 256>>>(fcb);
    edges_k<<<(EE + 255) / 256, 256>>>(ei);
    deg_k<<<(NN + 255) / 256, 256>>>();
    scan_k<<<1, 1024>>>();
    fill_k<<<(EE + 255) / 256, 256>>>();

    // operand conversion
    concat_k<<<(MM * K1P + 255) / 256, 256>>>(x, pe);
    convw_k<<<(HH * K1P + 255) / 256, 256>>>(W1, w0hi, w0lo, K1, K1P);
    convw_k<<<(HH * HH + 255) / 256, 256>>>(W2, w1hi, w1lo, HH, HH);
    convw_k<<<(HH * HH + 255) / 256, 256>>>(W3, w2hi, w2lo, HH, HH);

    const int MTILES = (MM + 127) / 128;  // 946
    dim3 ggrid(MTILES, 2);

    // layer 1
    mma_gemm_k<<<ggrid, 256, GEMM_DSMEM>>>(a0f, w0hi, w0lo, K1P);
    gather_k<<<NN, 256>>>(b1, fcW, 0);
    // layer 2
    mma_gemm_k<<<ggrid, 256, GEMM_DSMEM>>>(af, w1hi, w1lo, HH);
    gather_k<<<NN, 256>>>(b2, fcW, 1);
    // layer 3
    mma_gemm_k<<<ggrid, 256, GEMM_DSMEM>>>(af, w2hi, w2lo, HH);
    gather_k<<<NN, 256>>>(b3, fcW, 2);

    // head
    {
        dim3 lg(2, 64);
        lin1_k<<<lg, 256>>>(lin1W);
    }
    lin1fin_k<<<16, 256>>>(lin1b);
    final_k<<<1, 256>>>(lin2W, lin2b, out);
}

// round 13
// speedup vs baseline: 2.9272x; 1.1412x over previous
#include <cuda_runtime.h>
#include <cuda_fp16.h>
#include <math.h>
#include <stdint.h>

// Problem constants (fixed shapes)
#define NN   15135
#define BSZ  8
#define FF   64
#define GG   73
#define HH   256
#define EE   242160
#define MM   (NN*BSZ)       // 121080 rows
#define K1   (FF+GG)        // 137
#define K1P  160            // padded to multiple of 32
#define HFCC 512

// ------------------- scratch (device globals; no allocation) -------------------
__device__ __align__(16) __half d_hwh[MM*HH];   // GEMM output (fp16, pre-aggregation)
__device__ __align__(16) __half d_a0f[MM*K1P];  // layer-1 A operand (fp16)
__device__ __align__(16) __half d_af[MM*HH];    // layers-2/3 A operand (fp16, gather output)
// fp16 weights [256 n][Kpad k]
__device__ __align__(16) __half d_w0[HH*K1P];
__device__ __align__(16) __half d_w1[HH*HH];
__device__ __align__(16) __half d_w2[HH*HH];

__device__ float d_dis[NN];
__device__ float d_dinv[NN];
__device__ int   d_cnt[NN];
__device__ int   d_rowptr[NN+1];
__device__ int   d_cursor[NN];
__device__ int   d_src[EE];
__device__ float d_wgt[EE];
__device__ int   d_row32[EE];
__device__ int   d_col32[EE];
__device__ float d_g[BSZ*NN];
__device__ float d_zacc[BSZ*HFCC];
__device__ float d_z[BSZ*HFCC];

__device__ __forceinline__ float elu1(float x) { return x > 0.f ? x : expm1f(x); }

__device__ __forceinline__ uint32_t smem_u32(const void* p) {
    uint32_t a;
    asm("{ .reg .u64 t; cvta.to.shared.u64 t, %1; cvt.u32.u64 %0, t; }" : "=r"(a) : "l"(p));
    return a;
}
__device__ __forceinline__ void ldm_x4(uint32_t& r0, uint32_t& r1, uint32_t& r2, uint32_t& r3, uint32_t addr)
{
    asm volatile("ldmatrix.sync.aligned.m8n8.x4.shared.b16 {%0,%1,%2,%3}, [%4];"
                 : "=r"(r0), "=r"(r1), "=r"(r2), "=r"(r3) : "r"(addr));
}
__device__ __forceinline__ void mma16816h(float* c, uint32_t a0, uint32_t a1, uint32_t a2, uint32_t a3,
                                          uint32_t b0, uint32_t b1)
{
    asm volatile(
        "mma.sync.aligned.m16n8k16.row.col.f32.f16.f16.f32 "
        "{%0,%1,%2,%3}, {%4,%5,%6,%7}, {%8,%9}, {%0,%1,%2,%3};"
        : "+f"(c[0]), "+f"(c[1]), "+f"(c[2]), "+f"(c[3])
        : "r"(a0), "r"(a1), "r"(a2), "r"(a3), "r"(b0), "r"(b1));
}
__device__ __forceinline__ void cp16(uint32_t dst, const void* src, uint32_t srcsize)
{
    asm volatile("cp.async.cg.shared.global [%0], [%1], 16, %2;"
                 :: "r"(dst), "l"(src), "r"(srcsize) : "memory");
}
__device__ __forceinline__ void cp_commit() { asm volatile("cp.async.commit_group;" ::: "memory"); }

// ------------------- graph preprocessing -------------------
__global__ void zero_k(const float* __restrict__ fcb)
{
    int i = blockIdx.x * 256 + threadIdx.x;
    if (i < NN) { d_cnt[i] = 0; d_cursor[i] = 0; }
    if (i < BSZ*HFCC) d_zacc[i] = 0.f;
    if (i < BSZ*NN) d_g[i] = fcb[0];
}

// edge_index may be int64 or int32 (auto-detect).
__global__ void edges_k(const void* __restrict__ ei_raw)
{
    __shared__ int is64;
    const int* ei32 = (const int*)ei_raw;
    if (threadIdx.x == 0) {
        int allz = 1;
        for (int i = 0; i < 64; i++) if (ei32[2 * i + 1] != 0) { allz = 0; break; }
        is64 = allz;
    }
    __syncthreads();

    int e = blockIdx.x * 256 + threadIdx.x;
    if (e >= EE) return;
    int r, c;
    if (is64) {
        const long long* ei = (const long long*)ei_raw;
        r = (int)ei[e];
        c = (int)ei[EE + e];
    } else {
        r = ei32[e];
        c = ei32[EE + e];
    }
    d_row32[e] = r;
    d_col32[e] = c;
    atomicAdd(&d_cnt[c], 1);
}

__global__ void deg_k()
{
    int j = blockIdx.x * 256 + threadIdx.x;
    if (j >= NN) return;
    float dg = (float)d_cnt[j] + 1.0f;
    d_dis[j]  = rsqrtf(dg);
    d_dinv[j] = 1.0f / dg;
}

// exclusive scan d_cnt -> d_rowptr, 1024 threads, 15 elems/thread, shuffle scan
__global__ void scan_k()
{
    __shared__ int wsum[32];
    int t = threadIdx.x, lane = t & 31, w = t >> 5;
    int base = t * 15;
    int v[15];
    int s = 0;
    #pragma unroll
    for (int i = 0; i < 15; i++) {
        int idx = base + i;
        v[i] = (idx < NN) ? d_cnt[idx] : 0;
        s += v[i];
    }
    int ps = s;
    #pragma unroll
    for (int o = 1; o < 32; o <<= 1) {
        int u = __shfl_up_sync(0xffffffffu, ps, o);
        if (lane >= o) ps += u;
    }
    if (lane == 31) wsum[w] = ps;
    __syncthreads();
    if (w == 0) {
        int ws = wsum[lane];
        #pragma unroll
        for (int o = 1; o < 32; o <<= 1) {
            int u = __shfl_up_sync(0xffffffffu, ws, o);
            if (lane >= o) ws += u;
        }
        wsum[lane] = ws;
    }
    __syncthreads();
    int prefix = ps - s + (w > 0 ? wsum[w - 1] : 0);
    #pragma unroll
    for (int i = 0; i < 15; i++) {
        int idx = base + i;
        if (idx <= NN) d_rowptr[idx] = prefix;
        prefix += v[i];
    }
}

__global__ void fill_k()
{
    int e = blockIdx.x * 256 + threadIdx.x;
    if (e >= EE) return;
    int c = d_col32[e];
    int r = d_row32[e];
    int p = atomicAdd(&d_cursor[c], 1);
    int pos = d_rowptr[c] + p;
    d_src[pos] = r;
    d_wgt[pos] = d_dis[r] * d_dis[c];
}

// ------------------- input concat -> fp16, padded K=160 -------------------
__global__ void concat_k(const float* __restrict__ x, const float* __restrict__ pe)
{
    int idx = blockIdx.x * 256 + threadIdx.x;
    if (idx >= MM * K1P) return;
    int r = idx / K1P;
    int k = idx - r * K1P;
    int n = r >> 3, b = r & 7;
    float v = 0.f;
    if (k < FF) v = x[(b * NN + n) * FF + k];
    else if (k < K1) v = pe[n * GG + (k - FF)];
    d_a0f[idx] = __float2half_rn(v);
}

// ------------------- weight transpose -> fp16: [K,256] -> [256,Kpad] -------------------
__global__ void convw_k(const float* __restrict__ W, __half* __restrict__ hi, int K, int Kpad)
{
    int idx = blockIdx.x * 256 + threadIdx.x;
    if (idx >= HH * Kpad) return;
    int n = idx / Kpad, k = idx - n * Kpad;
    float v = (k < K) ? W[k * HH + n] : 0.f;
    hi[idx] = __float2half_rn(v);
}

// ------------------- mma.sync fp16 single-pass GEMM, 3-stage cp.async pipeline ---------
// d_hwh[M,256](fp16) = A @ W^T.  A [M][Kpad] fp16; W [256 n][Kpad k] fp16.
// Grid (946, 2): CTA tile 128m x 128n. 8 warps: warp tile 32m x 64n.
#define ASTRIDE 40
#define TILE_B  (128 * ASTRIDE * 2)    // 10240 bytes per operand tile
#define STAGE_B (2 * TILE_B)           // 20480 bytes per stage (A, B)
#define GEMM_DSMEM (3 * STAGE_B)       // 61440

__global__ __launch_bounds__(256) void mma_gemm_k(
    const __half* __restrict__ Af,
    const __half* __restrict__ Wh,
    int Kpad)
{
    extern __shared__ char dsm[];
    uint32_t dsm_b = smem_u32(dsm);

    int tid = threadIdx.x, wid = tid >> 5, lane = tid & 31;
    int rowBase = blockIdx.x * 128;
    int colBase = blockIdx.y * 128;
    int wm = wid >> 1, wn = wid & 1;
    int m0 = wm * 32, n0 = wn * 64;

    float acc[2][8][4];
    #pragma unroll
    for (int i = 0; i < 2; i++)
        #pragma unroll
        for (int j = 0; j < 8; j++)
            #pragma unroll
            for (int q = 0; q < 4; q++) acc[i][j][q] = 0.f;

    int nch = Kpad >> 5;

    auto load_chunk = [&](int c, int st) {
        int k0 = c * 32;
        uint32_t sbase = dsm_b + st * STAGE_B;
        #pragma unroll
        for (int ii = 0; ii < 2; ii++) {
            int i = tid + ii * 256;
            int r = i >> 2, q = i & 3;
            uint32_t doff = (uint32_t)(r * (ASTRIDE * 2) + q * 16);
            int grow = rowBase + r;
            uint32_t ok = (grow < MM) ? 16u : 0u;
            int gr = (grow < MM) ? grow : 0;
            cp16(sbase + doff,          Af + (size_t)gr * Kpad + k0 + q * 8, ok);
            int gn = colBase + r;
            cp16(sbase + TILE_B + doff, Wh + (size_t)gn * Kpad + k0 + q * 8, 16u);
        }
        cp_commit();
    };

    load_chunk(0, 0);
    if (nch > 1) load_chunk(1, 1);

    int st = 0;
    for (int c = 0; c < nch; c++) {
        if (c + 2 < nch) {
            int st2 = st + 2; if (st2 >= 3) st2 -= 3;
            load_chunk(c + 2, st2);
            asm volatile("cp.async.wait_group 2;" ::: "memory");
        } else if (c + 1 < nch) {
            asm volatile("cp.async.wait_group 1;" ::: "memory");
        } else {
            asm volatile("cp.async.wait_group 0;" ::: "memory");
        }
        __syncthreads();

        char* stg = dsm + st * STAGE_B;
        __half* As = (__half*)(stg);
        __half* Bs = (__half*)(stg + TILE_B);

        #pragma unroll
        for (int s = 0; s < 2; s++) {
            int kk = s * 16;
            uint32_t ah[2][4];
            {
                int t = lane >> 3, rr = lane & 7;
                int arow = ((t & 1) << 3) + rr;
                int acol = kk + ((t >> 1) << 3);
                #pragma unroll
                for (int mt = 0; mt < 2; mt++) {
                    uint32_t ad = smem_u32(&As[(m0 + mt * 16 + arow) * ASTRIDE + acol]);
                    ldm_x4(ah[mt][0], ah[mt][1], ah[mt][2], ah[mt][3], ad);
                }
            }
            uint32_t bh[8][2];
            {
                int brow = (((lane >> 4) & 1) << 3) + (lane & 7);
                int bcol = kk + (((lane >> 3) & 1) << 3);
                #pragma unroll
                for (int nt = 0; nt < 4; nt++) {
                    uint32_t bd = smem_u32(&Bs[(n0 + nt * 16 + brow) * ASTRIDE + bcol]);
                    uint32_t r0, r1, r2, r3;
                    ldm_x4(r0, r1, r2, r3, bd);
                    bh[nt * 2][0] = r0; bh[nt * 2][1] = r1;
                    bh[nt * 2 + 1][0] = r2; bh[nt * 2 + 1][1] = r3;
                }
            }
            #pragma unroll
            for (int mt = 0; mt < 2; mt++)
                #pragma unroll
                for (int nt = 0; nt < 8; nt++)
                    mma16816h(acc[mt][nt], ah[mt][0], ah[mt][1], ah[mt][2], ah[mt][3], bh[nt][0], bh[nt][1]);
        }
        __syncthreads();
        if (++st == 3) st = 0;
    }

    // ---- epilogue: convert to fp16, store ----
    int g = lane >> 2, tig = lane & 3;
    #pragma unroll
    for (int mt = 0; mt < 2; mt++) {
        int r0 = rowBase + m0 + mt * 16 + g;
        int r1 = r0 + 8;
        #pragma unroll
        for (int nt = 0; nt < 8; nt++) {
            int col = colBase + n0 + nt * 8 + tig * 2;
            if (r0 < MM) {
                __half2 p = __floats2half2_rn(acc[mt][nt][0], acc[mt][nt][1]);
                *(__half2*)(d_hwh + (size_t)r0 * 256 + col) = p;
            }
            if (r1 < MM) {
                __half2 p = __floats2half2_rn(acc[mt][nt][2], acc[mt][nt][3]);
                *(__half2*)(d_hwh + (size_t)r1 * 256 + col) = p;
            }
        }
    }
}

// ------------------- CSR gather (fp16 in) + self-loop + bias + ELU + fused fc-dot ----
// One launch per layer. Block = 256 threads per node: warp = batch, lane covers 8 feats.
__global__ __launch_bounds__(256) void gather_k(const float* __restrict__ bias,
                                                const float* __restrict__ fcW,
                                                int layer)
{
    int j = blockIdx.x;
    int tid = threadIdx.x;
    int b = tid >> 5, lane = tid & 31;
    int f8 = lane * 8;                      // feature base (0..248)

    const __half* hw = d_hwh;
    size_t selfoff = ((size_t)(j * 8 + b)) * 256 + f8;

    float acc[8];
    {
        float di = d_dinv[j];
        uint4 sv = *(const uint4*)(hw + selfoff);
        const __half2* p = (const __half2*)&sv;
        #pragma unroll
        for (int q = 0; q < 4; q++) {
            float2 f = __half22float2(p[q]);
            acc[2 * q]     = f.x * di;
            acc[2 * q + 1] = f.y * di;
        }
    }

    int s0 = d_rowptr[j], s1 = d_rowptr[j + 1];
    int k = s0;
    #define ACC8(v, w) { const __half2* pp = (const __half2*)&(v); \
        _Pragma("unroll") for (int q = 0; q < 4; q++) { float2 f = __half22float2(pp[q]); \
            acc[2*q]   = fmaf((w), f.x, acc[2*q]); \
            acc[2*q+1] = fmaf((w), f.y, acc[2*q+1]); } }

    for (; k + 4 <= s1; k += 4) {
        int sa = d_src[k], sb = d_src[k + 1], sc = d_src[k + 2], sd = d_src[k + 3];
        float wa = d_wgt[k], wb = d_wgt[k + 1], wc = d_wgt[k + 2], wd = d_wgt[k + 3];
        uint4 va = *(const uint4*)(hw + ((size_t)(sa * 8 + b)) * 256 + f8);
        uint4 vb = *(const uint4*)(hw + ((size_t)(sb * 8 + b)) * 256 + f8);
        uint4 vc = *(const uint4*)(hw + ((size_t)(sc * 8 + b)) * 256 + f8);
        uint4 vd = *(const uint4*)(hw + ((size_t)(sd * 8 + b)) * 256 + f8);
        ACC8(va, wa) ACC8(vb, wb) ACC8(vc, wc) ACC8(vd, wd)
    }
    for (; k < s1; k++) {
        int s = d_src[k];
        float w = d_wgt[k];
        uint4 v = *(const uint4*)(hw + ((size_t)(s * 8 + b)) * 256 + f8);
        ACC8(v, w)
    }
    #undef ACC8

    // bias + ELU
    #pragma unroll
    for (int q = 0; q < 8; q++) acc[q] = elu1(acc[q] + bias[f8 + q]);

    // next-layer fp16 operand (layers 0,1); streaming stores
    if (layer < 2) {
        uint4 hv;
        #pragma unroll
        for (int q = 0; q < 4; q++) {
            __half2 t = __floats2half2_rn(acc[2 * q], acc[2 * q + 1]);
            ((uint32_t*)&hv)[q] = *(uint32_t*)&t;
        }
        __stcs((uint4*)(d_af + selfoff), hv);
    }

    // fused JK/fc contribution: g[b][j] += sum_h h*fcW[3h+layer]
    float gc = 0.f;
    #pragma unroll
    for (int q = 0; q < 8; q++) gc = fmaf(acc[q], fcW[3 * (f8 + q) + layer], gc);
    #pragma unroll
    for (int o = 16; o; o >>= 1) gc += __shfl_xor_sync(0xffffffffu, gc, o);
    if (lane == 0) atomicAdd(&d_g[b * NN + j], gc);
}

// ------------------- z = elu(g @ lin1_W + lin1_b), split-K -------------------
__global__ __launch_bounds__(256) void lin1_k(const float* __restrict__ W)
{
    int o = blockIdx.x * 256 + threadIdx.x;  // 0..511
    const int NS = (NN + 63) / 64;           // 237
    int n0 = blockIdx.y * NS;
    int n1 = n0 + NS; if (n1 > NN) n1 = NN;
    float acc[8];
    #pragma unroll
    for (int b = 0; b < 8; b++) acc[b] = 0.f;
    for (int n = n0; n < n1; n++) {
        float w = W[n * 512 + o];
        #pragma unroll
        for (int b = 0; b < 8; b++) acc[b] = fmaf(d_g[b * NN + n], w, acc[b]);
    }
    #pragma unroll
    for (int b = 0; b < 8; b++) atomicAdd(&d_zacc[b * 512 + o], acc[b]);
}

__global__ void lin1fin_k(const float* __restrict__ bias)
{
    int i = blockIdx.x * 256 + threadIdx.x;
    if (i >= BSZ * HFCC) return;
    d_z[i] = elu1(d_zacc[i] + bias[i & 511]);
}

// ------------------- out = log_softmax(z @ lin2_W + lin2_b) -------------------
__global__ void final_k(const float* __restrict__ W, const float* __restrict__ bv,
                        float* __restrict__ out)
{
    int b = threadIdx.x >> 5;
    int lane = threadIdx.x & 31;
    float a0 = 0.f, a1 = 0.f;
    for (int i = lane; i < 512; i += 32) {
        float z = d_z[b * 512 + i];
        a0 = fmaf(z, W[2 * i],     a0);
        a1 = fmaf(z, W[2 * i + 1], a1);
    }
    #pragma unroll
    for (int o = 16; o; o >>= 1) {
        a0 += __shfl_xor_sync(0xffffffffu, a0, o);
        a1 += __shfl_xor_sync(0xffffffffu, a1, o);
    }
    if (lane == 0) {
        float v0 = a0 + bv[0], v1 = a1 + bv[1];
        float m = fmaxf(v0, v1);
        float l = m + logf(expf(v0 - m) + expf(v1 - m));
        out[2 * b]     = v0 - l;
        out[2 * b + 1] = v1 - l;
    }
}

// ------------------- host launcher -------------------
extern "C" void kernel_launch(void* const* d_in, const int* in_sizes, int n_in,
                              void* d_out, int out_size)
{
    const float* x      = (const float*)d_in[0];
    // d_in[1] = batch (unused, all zeros)
    const void*  ei     = d_in[2];                 // int32 or int64, auto-detected
    const float* pe     = (const float*)d_in[3];
    const float* W1     = (const float*)d_in[4];
    const float* b1     = (const float*)d_in[5];
    const float* W2     = (const float*)d_in[6];
    const float* b2     = (const float*)d_in[7];
    const float* W3     = (const float*)d_in[8];
    const float* b3     = (const float*)d_in[9];
    const float* fcW    = (const float*)d_in[10];
    const float* fcb    = (const float*)d_in[11];
    const float* lin1W  = (const float*)d_in[12];
    const float* lin1b  = (const float*)d_in[13];
    const float* lin2W  = (const float*)d_in[14];
    const float* lin2b  = (const float*)d_in[15];
    float* out = (float*)d_out;

    cudaFuncSetAttribute(mma_gemm_k, cudaFuncAttributeMaxDynamicSharedMemorySize, GEMM_DSMEM);

    // resolve device-global addresses for kernel args
    __half *a0f, *af, *w0, *w1, *w2;
    cudaGetSymbolAddress((void**)&a0f, d_a0f);
    cudaGetSymbolAddress((void**)&af,  d_af);
    cudaGetSymbolAddress((void**)&w0,  d_w0);
    cudaGetSymbolAddress((void**)&w1,  d_w1);
    cudaGetSymbolAddress((void**)&w2,  d_w2);

    // graph preprocessing
    zero_k<<<(BSZ * NN + 255) / 256, 256>>>(fcb);
    edges_k<<<(EE + 255) / 256, 256>>>(ei);
    deg_k<<<(NN + 255) / 256, 256>>>();
    scan_k<<<1, 1024>>>();
    fill_k<<<(EE + 255) / 256, 256>>>();

    // operand conversion
    concat_k<<<(MM * K1P + 255) / 256, 256>>>(x, pe);
    convw_k<<<(HH * K1P + 255) / 256, 256>>>(W1, w0, K1, K1P);
    convw_k<<<(HH * HH + 255) / 256, 256>>>(W2, w1, HH, HH);
    convw_k<<<(HH * HH + 255) / 256, 256>>>(W3, w2, HH, HH);

    const int MTILES = (MM + 127) / 128;  // 946
    dim3 ggrid(MTILES, 2);

    // layer 1
    mma_gemm_k<<<ggrid, 256, GEMM_DSMEM>>>(a0f, w0, K1P);
    gather_k<<<NN, 256>>>(b1, fcW, 0);
    // layer 2
    mma_gemm_k<<<ggrid, 256, GEMM_DSMEM>>>(af, w1, HH);
    gather_k<<<NN, 256>>>(b2, fcW, 1);
    // layer 3
    mma_gemm_k<<<ggrid, 256, GEMM_DSMEM>>>(af, w2, HH);
    gather_k<<<NN, 256>>>(b3, fcW, 2);

    // head
    {
        dim3 lg(2, 64);
        lin1_k<<<lg, 256>>>(lin1W);
    }
    lin1fin_k<<<16, 256>>>(lin1b);
    final_k<<<1, 256>>>(lin2W, lin2b, out);
}

// round 15
// speedup vs baseline: 3.0244x; 1.0332x over previous
#include <cuda_runtime.h>
#include <cuda_fp16.h>
#include <math.h>
#include <stdint.h>

// Problem constants (fixed shapes)
#define NN   15135
#define BSZ  8
#define FF   64
#define GG   73
#define HH   256
#define EE   242160
#define MM   (NN*BSZ)       // 121080 rows
#define K1   (FF+GG)        // 137
#define K1P  160            // padded to multiple of 32
#define HFCC 512

// ------------------- scratch (device globals; no allocation) -------------------
__device__ __align__(16) __half d_a0[MM*K1P];   // layer-1 input (fp16, concat)
__device__ __align__(16) __half d_agg[MM*HH];   // aggregated GEMM A operand (fp16)
__device__ __align__(16) __half d_af[MM*HH];    // post-ELU activations (fp16)
// fp16 weights [256 n][Kpad k]
__device__ __align__(16) __half d_w0[HH*K1P];
__device__ __align__(16) __half d_w1[HH*HH];
__device__ __align__(16) __half d_w2[HH*HH];

__device__ float d_dis[NN];
__device__ float d_dinv[NN];
__device__ int   d_cnt[NN];
__device__ int   d_rowptr[NN+1];
__device__ int   d_cursor[NN];
__device__ int   d_src[EE];
__device__ float d_wgt[EE];
__device__ int   d_row32[EE];
__device__ int   d_col32[EE];
__device__ float d_g[BSZ*NN];
__device__ float d_zacc[BSZ*HFCC];
__device__ float d_z[BSZ*HFCC];

__device__ __forceinline__ float elu1(float x) { return x > 0.f ? x : expm1f(x); }

__device__ __forceinline__ uint32_t smem_u32(const void* p) {
    uint32_t a;
    asm("{ .reg .u64 t; cvta.to.shared.u64 t, %1; cvt.u32.u64 %0, t; }" : "=r"(a) : "l"(p));
    return a;
}
__device__ __forceinline__ void ldm_x4(uint32_t& r0, uint32_t& r1, uint32_t& r2, uint32_t& r3, uint32_t addr)
{
    asm volatile("ldmatrix.sync.aligned.m8n8.x4.shared.b16 {%0,%1,%2,%3}, [%4];"
                 : "=r"(r0), "=r"(r1), "=r"(r2), "=r"(r3) : "r"(addr));
}
__device__ __forceinline__ void mma16816h(float* c, uint32_t a0, uint32_t a1, uint32_t a2, uint32_t a3,
                                          uint32_t b0, uint32_t b1)
{
    asm volatile(
        "mma.sync.aligned.m16n8k16.row.col.f32.f16.f16.f32 "
        "{%0,%1,%2,%3}, {%4,%5,%6,%7}, {%8,%9}, {%0,%1,%2,%3};"
        : "+f"(c[0]), "+f"(c[1]), "+f"(c[2]), "+f"(c[3])
        : "r"(a0), "r"(a1), "r"(a2), "r"(a3), "r"(b0), "r"(b1));
}
__device__ __forceinline__ void cp16(uint32_t dst, const void* src, uint32_t srcsize)
{
    asm volatile("cp.async.cg.shared.global [%0], [%1], 16, %2;"
                 :: "r"(dst), "l"(src), "r"(srcsize) : "memory");
}
__device__ __forceinline__ void cp_commit() { asm volatile("cp.async.commit_group;" ::: "memory"); }

// ------------------- graph preprocessing -------------------
__global__ void zero_k(const float* __restrict__ fcb)
{
    int i = blockIdx.x * 256 + threadIdx.x;
    if (i < NN) { d_cnt[i] = 0; d_cursor[i] = 0; }
    if (i < BSZ*HFCC) d_zacc[i] = 0.f;
    if (i < BSZ*NN) d_g[i] = fcb[0];
}

// edge_index may be int64 or int32 (auto-detect).
__global__ void edges_k(const void* __restrict__ ei_raw)
{
    __shared__ int is64;
    const int* ei32 = (const int*)ei_raw;
    if (threadIdx.x == 0) {
        int allz = 1;
        for (int i = 0; i < 64; i++) if (ei32[2 * i + 1] != 0) { allz = 0; break; }
        is64 = allz;
    }
    __syncthreads();

    int e = blockIdx.x * 256 + threadIdx.x;
    if (e >= EE) return;
    int r, c;
    if (is64) {
        const long long* ei = (const long long*)ei_raw;
        r = (int)ei[e];
        c = (int)ei[EE + e];
    } else {
        r = ei32[e];
        c = ei32[EE + e];
    }
    d_row32[e] = r;
    d_col32[e] = c;
    atomicAdd(&d_cnt[c], 1);
}

// exclusive scan d_cnt -> d_rowptr (+ fused deg: dis/dinv), 1024 threads
__global__ void scan_k()
{
    __shared__ int wsum[32];
    int t = threadIdx.x, lane = t & 31, w = t >> 5;
    int base = t * 15;
    int v[15];
    int s = 0;
    #pragma unroll
    for (int i = 0; i < 15; i++) {
        int idx = base + i;
        v[i] = (idx < NN) ? d_cnt[idx] : 0;
        s += v[i];
        if (idx < NN) {
            float dg = (float)v[i] + 1.0f;
            d_dis[idx]  = rsqrtf(dg);
            d_dinv[idx] = 1.0f / dg;
        }
    }
    int ps = s;
    #pragma unroll
    for (int o = 1; o < 32; o <<= 1) {
        int u = __shfl_up_sync(0xffffffffu, ps, o);
        if (lane >= o) ps += u;
    }
    if (lane == 31) wsum[w] = ps;
    __syncthreads();
    if (w == 0) {
        int ws = wsum[lane];
        #pragma unroll
        for (int o = 1; o < 32; o <<= 1) {
            int u = __shfl_up_sync(0xffffffffu, ws, o);
            if (lane >= o) ws += u;
        }
        wsum[lane] = ws;
    }
    __syncthreads();
    int prefix = ps - s + (w > 0 ? wsum[w - 1] : 0);
    #pragma unroll
    for (int i = 0; i < 15; i++) {
        int idx = base + i;
        if (idx <= NN) d_rowptr[idx] = prefix;
        prefix += v[i];
    }
}

__global__ void fill_k()
{
    int e = blockIdx.x * 256 + threadIdx.x;
    if (e >= EE) return;
    int c = d_col32[e];
    int r = d_row32[e];
    int p = atomicAdd(&d_cursor[c], 1);
    int pos = d_rowptr[c] + p;
    d_src[pos] = r;
    d_wgt[pos] = d_dis[r] * d_dis[c];
}

// ------------------- input concat -> fp16, padded K=160; block per row -------------------
__global__ __launch_bounds__(160) void concat_k(const float* __restrict__ x, const float* __restrict__ pe)
{
    int r = blockIdx.x;            // 0..MM-1 = n*8+b
    int k = threadIdx.x;           // 0..159
    int n = r >> 3, b = r & 7;
    float v = 0.f;
    if (k < FF) v = x[(b * NN + n) * FF + k];
    else if (k < K1) v = pe[n * GG + (k - FF)];
    d_a0[(size_t)r * K1P + k] = __float2half_rn(v);
}

// ------------------- weight transpose -> fp16: [K,256] -> [256,Kpad] -------------------
__global__ void convw_k(const float* __restrict__ W, __half* __restrict__ hi, int K, int Kpad)
{
    int idx = blockIdx.x * 256 + threadIdx.x;
    if (idx >= HH * Kpad) return;
    int n = idx / Kpad, k = idx - n * Kpad;
    float v = (k < K) ? W[k * HH + n] : 0.f;
    hi[idx] = __float2half_rn(v);
}

// ------------------- CSR gather: agg[row] = dinv*ain[row] + sum_e w*ain[src_row] ---------
// Pure weighted sum, fp16 in/out, fp32 accumulate. Block 256 = 8 warps = 8 batches.
// Lane covers 8 halves; DIMH=160 -> lanes 0..19 active, DIMH=256 -> all.
template<int DIMH>
__global__ __launch_bounds__(256) void gather_k(const __half* __restrict__ ain,
                                                __half* __restrict__ aout)
{
    int j = blockIdx.x;
    int tid = threadIdx.x;
    int b = tid >> 5, lane = tid & 31;
    if (lane * 8 >= DIMH) return;
    size_t off = ((size_t)(j * 8 + b)) * DIMH + lane * 8;

    float acc[8];
    {
        float di = d_dinv[j];
        uint4 sv = *(const uint4*)(ain + off);
        const __half2* p = (const __half2*)&sv;
        #pragma unroll
        for (int q = 0; q < 4; q++) {
            float2 f = __half22float2(p[q]);
            acc[2 * q]     = f.x * di;
            acc[2 * q + 1] = f.y * di;
        }
    }

    int s0 = d_rowptr[j], s1 = d_rowptr[j + 1];
    int k = s0;
    #define ACC8(v, w) { const __half2* pp = (const __half2*)&(v); \
        _Pragma("unroll") for (int q = 0; q < 4; q++) { float2 f = __half22float2(pp[q]); \
            acc[2*q]   = fmaf((w), f.x, acc[2*q]); \
            acc[2*q+1] = fmaf((w), f.y, acc[2*q+1]); } }

    size_t lo = (size_t)b * DIMH + lane * 8;
    for (; k + 4 <= s1; k += 4) {
        int sa = d_src[k], sb = d_src[k + 1], sc = d_src[k + 2], sd = d_src[k + 3];
        float wa = d_wgt[k], wb = d_wgt[k + 1], wc = d_wgt[k + 2], wd = d_wgt[k + 3];
        uint4 va = *(const uint4*)(ain + (size_t)sa * (8 * DIMH) + lo);
        uint4 vb = *(const uint4*)(ain + (size_t)sb * (8 * DIMH) + lo);
        uint4 vc = *(const uint4*)(ain + (size_t)sc * (8 * DIMH) + lo);
        uint4 vd = *(const uint4*)(ain + (size_t)sd * (8 * DIMH) + lo);
        ACC8(va, wa) ACC8(vb, wb) ACC8(vc, wc) ACC8(vd, wd)
    }
    for (; k < s1; k++) {
        int s = d_src[k];
        float w = d_wgt[k];
        uint4 v = *(const uint4*)(ain + (size_t)s * (8 * DIMH) + lo);
        ACC8(v, w)
    }
    #undef ACC8

    uint4 hv;
    #pragma unroll
    for (int q = 0; q < 4; q++) {
        __half2 t = __floats2half2_rn(acc[2 * q], acc[2 * q + 1]);
        ((uint32_t*)&hv)[q] = *(uint32_t*)&t;
    }
    *(uint4*)(aout + off) = hv;
}

// ------------------- mma.sync fp16 GEMM + fused bias/ELU/fc-dot epilogue ---------------
// af[M,256](fp16) = elu(A @ W^T + bias); also d_g[b][j] += sum_h elu(..)*fcW[3h+layer].
// A [M][Kpad] fp16 (aggregated); W [256 n][Kpad k] fp16.
// Grid (946, 2): CTA tile 128m x 128n. 8 warps: warp tile 32m x 64n.
#define ASTRIDE 40
#define TILE_B  (128 * ASTRIDE * 2)    // 10240 bytes per operand tile
#define STAGE_B (2 * TILE_B)           // 20480 bytes per stage (A, B)
#define GEMM_DSMEM (3 * STAGE_B)       // 61440

__global__ __launch_bounds__(256) void mma_gemm_k(
    const __half* __restrict__ Af,
    const __half* __restrict__ Wh,
    int Kpad,
    const float* __restrict__ bias,
    const float* __restrict__ fcW,
    int layer)
{
    extern __shared__ char dsm[];
    uint32_t dsm_b = smem_u32(dsm);

    int tid = threadIdx.x, wid = tid >> 5, lane = tid & 31;
    int rowBase = blockIdx.x * 128;
    int colBase = blockIdx.y * 128;
    int wm = wid >> 1, wn = wid & 1;
    int m0 = wm * 32, n0 = wn * 64;

    float acc[2][8][4];
    #pragma unroll
    for (int i = 0; i < 2; i++)
        #pragma unroll
        for (int j = 0; j < 8; j++)
            #pragma unroll
            for (int q = 0; q < 4; q++) acc[i][j][q] = 0.f;

    int nch = Kpad >> 5;

    auto load_chunk = [&](int c, int st) {
        int k0 = c * 32;
        uint32_t sbase = dsm_b + st * STAGE_B;
        #pragma unroll
        for (int ii = 0; ii < 2; ii++) {
            int i = tid + ii * 256;
            int r = i >> 2, q = i & 3;
            uint32_t doff = (uint32_t)(r * (ASTRIDE * 2) + q * 16);
            int grow = rowBase + r;
            uint32_t ok = (grow < MM) ? 16u : 0u;
            int gr = (grow < MM) ? grow : 0;
            cp16(sbase + doff,          Af + (size_t)gr * Kpad + k0 + q * 8, ok);
            int gn = colBase + r;
            cp16(sbase + TILE_B + doff, Wh + (size_t)gn * Kpad + k0 + q * 8, 16u);
        }
        cp_commit();
    };

    load_chunk(0, 0);
    if (nch > 1) load_chunk(1, 1);

    int st = 0;
    for (int c = 0; c < nch; c++) {
        if (c + 2 < nch) {
            int st2 = st + 2; if (st2 >= 3) st2 -= 3;
            load_chunk(c + 2, st2);
            asm volatile("cp.async.wait_group 2;" ::: "memory");
        } else if (c + 1 < nch) {
            asm volatile("cp.async.wait_group 1;" ::: "memory");
        } else {
            asm volatile("cp.async.wait_group 0;" ::: "memory");
        }
        __syncthreads();

        char* stg = dsm + st * STAGE_B;
        __half* As = (__half*)(stg);
        __half* Bs = (__half*)(stg + TILE_B);

        #pragma unroll
        for (int s = 0; s < 2; s++) {
            int kk = s * 16;
            uint32_t ah[2][4];
            {
                int t = lane >> 3, rr = lane & 7;
                int arow = ((t & 1) << 3) + rr;
                int acol = kk + ((t >> 1) << 3);
                #pragma unroll
                for (int mt = 0; mt < 2; mt++) {
                    uint32_t ad = smem_u32(&As[(m0 + mt * 16 + arow) * ASTRIDE + acol]);
                    ldm_x4(ah[mt][0], ah[mt][1], ah[mt][2], ah[mt][3], ad);
                }
            }
            uint32_t bh[8][2];
            {
                int brow = (((lane >> 4) & 1) << 3) + (lane & 7);
                int bcol = kk + (((lane >> 3) & 1) << 3);
                #pragma unroll
                for (int nt = 0; nt < 4; nt++) {
                    uint32_t bd = smem_u32(&Bs[(n0 + nt * 16 + brow) * ASTRIDE + bcol]);
                    uint32_t r0, r1, r2, r3;
                    ldm_x4(r0, r1, r2, r3, bd);
                    bh[nt * 2][0] = r0; bh[nt * 2][1] = r1;
                    bh[nt * 2 + 1][0] = r2; bh[nt * 2 + 1][1] = r3;
                }
            }
            #pragma unroll
            for (int mt = 0; mt < 2; mt++)
                #pragma unroll
                for (int nt = 0; nt < 8; nt++)
                    mma16816h(acc[mt][nt], ah[mt][0], ah[mt][1], ah[mt][2], ah[mt][3], bh[nt][0], bh[nt][1]);
        }
        __syncthreads();
        if (++st == 3) st = 0;
    }

    // ---- fused epilogue: bias + ELU + fp16 store + fc-dot atomics ----
    int g = lane >> 2, tig = lane & 3;
    // per-thread column constants (same for all rows)
    float2 bias_v[8], fcw_v[8];
    #pragma unroll
    for (int nt = 0; nt < 8; nt++) {
        int col = colBase + n0 + nt * 8 + tig * 2;
        bias_v[nt] = make_float2(bias[col], bias[col + 1]);
        fcw_v[nt]  = make_float2(fcW[3 * col + layer], fcW[3 * (col + 1) + layer]);
    }

    #pragma unroll
    for (int mt = 0; mt < 2; mt++) {
        #pragma unroll
        for (int half = 0; half < 2; half++) {
            int row = rowBase + m0 + mt * 16 + g + half * 8;
            bool ok = (row < MM);
            float gc = 0.f;
            #pragma unroll
            for (int nt = 0; nt < 8; nt++) {
                float v0 = elu1(acc[mt][nt][half * 2]     + bias_v[nt].x);
                float v1 = elu1(acc[mt][nt][half * 2 + 1] + bias_v[nt].y);
                gc = fmaf(v0, fcw_v[nt].x, gc);
                gc = fmaf(v1, fcw_v[nt].y, gc);
                if (ok && layer < 2) {
                    int col = colBase + n0 + nt * 8 + tig * 2;
                    __half2 p = __floats2half2_rn(v0, v1);
                    *(__half2*)(d_af + (size_t)row * 256 + col) = p;
                }
            }
            // quad reduce (lanes g*4..g*4+3 share row)
            gc += __shfl_xor_sync(0xffffffffu, gc, 1);
            gc += __shfl_xor_sync(0xffffffffu, gc, 2);
            if (ok && tig == 0) {
                int j = row >> 3, b = row & 7;
                atomicAdd(&d_g[b * NN + j], gc);
            }
        }
    }
}

// ------------------- z = elu(g @ lin1_W + lin1_b), split-K -------------------
__global__ __launch_bounds__(256) void lin1_k(const float* __restrict__ W)
{
    int o = blockIdx.x * 256 + threadIdx.x;  // 0..511
    const int NS = (NN + 63) / 64;           // 237
    int n0 = blockIdx.y * NS;
    int n1 = n0 + NS; if (n1 > NN) n1 = NN;
    float acc[8];
    #pragma unroll
    for (int b = 0; b < 8; b++) acc[b] = 0.f;
    for (int n = n0; n < n1; n++) {
        float w = W[n * 512 + o];
        #pragma unroll
        for (int b = 0; b < 8; b++) acc[b] = fmaf(d_g[b * NN + n], w, acc[b]);
    }
    #pragma unroll
    for (int b = 0; b < 8; b++) atomicAdd(&d_zacc[b * 512 + o], acc[b]);
}

__global__ void lin1fin_k(const float* __restrict__ bias)
{
    int i = blockIdx.x * 256 + threadIdx.x;
    if (i >= BSZ * HFCC) return;
    d_z[i] = elu1(d_zacc[i] + bias[i & 511]);
}

// ------------------- out = log_softmax(z @ lin2_W + lin2_b) -------------------
__global__ void final_k(const float* __restrict__ W, const float* __restrict__ bv,
                        float* __restrict__ out)
{
    int b = threadIdx.x >> 5;
    int lane = threadIdx.x & 31;
    float a0 = 0.f, a1 = 0.f;
    for (int i = lane; i < 512; i += 32) {
        float z = d_z[b * 512 + i];
        a0 = fmaf(z, W[2 * i],     a0);
        a1 = fmaf(z, W[2 * i + 1], a1);
    }
    #pragma unroll
    for (int o = 16; o; o >>= 1) {
        a0 += __shfl_xor_sync(0xffffffffu, a0, o);
        a1 += __shfl_xor_sync(0xffffffffu, a1, o);
    }
    if (lane == 0) {
        float v0 = a0 + bv[0], v1 = a1 + bv[1];
        float m = fmaxf(v0, v1);
        float l = m + logf(expf(v0 - m) + expf(v1 - m));
        out[2 * b]     = v0 - l;
        out[2 * b + 1] = v1 - l;
    }
}

// ------------------- host launcher -------------------
extern "C" void kernel_launch(void* const* d_in, const int* in_sizes, int n_in,
                              void* d_out, int out_size)
{
    const float* x      = (const float*)d_in[0];
    // d_in[1] = batch (unused, all zeros)
    const void*  ei     = d_in[2];                 // int32 or int64, auto-detected
    const float* pe     = (const float*)d_in[3];
    const float* W1     = (const float*)d_in[4];
    const float* b1     = (const float*)d_in[5];
    const float* W2     = (const float*)d_in[6];
    const float* b2     = (const float*)d_in[7];
    const float* W3     = (const float*)d_in[8];
    const float* b3     = (const float*)d_in[9];
    const float* fcW    = (const float*)d_in[10];
    const float* fcb    = (const float*)d_in[11];
    const float* lin1W  = (const float*)d_in[12];
    const float* lin1b  = (const float*)d_in[13];
    const float* lin2W  = (const float*)d_in[14];
    const float* lin2b  = (const float*)d_in[15];
    float* out = (float*)d_out;

    cudaFuncSetAttribute(mma_gemm_k, cudaFuncAttributeMaxDynamicSharedMemorySize, GEMM_DSMEM);

    // resolve device-global addresses for kernel args
    __half *a0, *agg, *af, *w0, *w1, *w2;
    cudaGetSymbolAddress((void**)&a0,  d_a0);
    cudaGetSymbolAddress((void**)&agg, d_agg);
    cudaGetSymbolAddress((void**)&af,  d_af);
    cudaGetSymbolAddress((void**)&w0,  d_w0);
    cudaGetSymbolAddress((void**)&w1,  d_w1);
    cudaGetSymbolAddress((void**)&w2,  d_w2);

    // graph preprocessing
    zero_k<<<(BSZ * NN + 255) / 256, 256>>>(fcb);
    edges_k<<<(EE + 255) / 256, 256>>>(ei);
    scan_k<<<1, 1024>>>();
    fill_k<<<(EE + 255) / 256, 256>>>();

    // operand conversion
    concat_k<<<MM, 160>>>(x, pe);
    convw_k<<<(HH * K1P + 255) / 256, 256>>>(W1, w0, K1, K1P);
    convw_k<<<(HH * HH + 255) / 256, 256>>>(W2, w1, HH, HH);
    convw_k<<<(HH * HH + 255) / 256, 256>>>(W3, w2, HH, HH);

    const int MTILES = (MM + 127) / 128;  // 946
    dim3 ggrid(MTILES, 2);

    // layer 1: gather(a0, 160) -> agg; GEMM(agg,W1) -> af (+fc-dot layer 0)
    gather_k<K1P><<<NN, 256>>>(a0, agg);
    mma_gemm_k<<<ggrid, 256, GEMM_DSMEM>>>(agg, w0, K1P, b1, fcW, 0);
    // layer 2
    gather_k<HH><<<NN, 256>>>(af, agg);
    mma_gemm_k<<<ggrid, 256, GEMM_DSMEM>>>(agg, w1, HH, b2, fcW, 1);
    // layer 3 (no af write; epilogue only fc-dot)
    gather_k<HH><<<NN, 256>>>(af, agg);
    mma_gemm_k<<<ggrid, 256, GEMM_DSMEM>>>(agg, w2, HH, b3, fcW, 2);

    // head
    {
        dim3 lg(2, 64);
        lin1_k<<<lg, 256>>>(lin1W);
    }
    lin1fin_k<<<16, 256>>>(lin1b);
    final_k<<<1, 256>>>(lin2W, lin2b, out);
}

// round 16
// speedup vs baseline: 3.4284x; 1.1336x over previous
#include <cuda_runtime.h>
#include <cuda_fp16.h>
#include <math.h>
#include <stdint.h>

// Problem constants (fixed shapes)
#define NN   15135
#define BSZ  8
#define FF   64
#define GG   73
#define HH   256
#define EE   242160
#define MM   (NN*BSZ)       // 121080 rows
#define K1   (FF+GG)        // 137
#define K1P  160            // padded to multiple of 32
#define HFCC 512

// ------------------- scratch (device globals; no allocation) -------------------
__device__ __align__(16) __half d_a0[MM*K1P];   // layer-1 input (fp16, concat)
__device__ __align__(16) __half d_agg[MM*HH];   // aggregated GEMM A operand (fp16)
__device__ __align__(16) __half d_af[MM*HH];    // post-ELU activations (fp16)
// fp16 weights [256 n][Kpad k]
__device__ __align__(16) __half d_w0[HH*K1P];
__device__ __align__(16) __half d_w1[HH*HH];
__device__ __align__(16) __half d_w2[HH*HH];

struct __align__(8) Edge { int s; float w; };
__device__ Edge d_edge[EE];

__device__ float d_dis[NN];
__device__ float d_dinv[NN];
__device__ int   d_cnt[NN];
__device__ int   d_rowptr[NN+1];
__device__ int   d_cursor[NN];
__device__ float d_g[BSZ*NN];
__device__ float d_zacc[BSZ*HFCC];

__device__ __forceinline__ float elu1(float x) { return x > 0.f ? x : expm1f(x); }

__device__ __forceinline__ uint32_t smem_u32(const void* p) {
    uint32_t a;
    asm("{ .reg .u64 t; cvta.to.shared.u64 t, %1; cvt.u32.u64 %0, t; }" : "=r"(a) : "l"(p));
    return a;
}
__device__ __forceinline__ void ldm_x4(uint32_t& r0, uint32_t& r1, uint32_t& r2, uint32_t& r3, uint32_t addr)
{
    asm volatile("ldmatrix.sync.aligned.m8n8.x4.shared.b16 {%0,%1,%2,%3}, [%4];"
                 : "=r"(r0), "=r"(r1), "=r"(r2), "=r"(r3) : "r"(addr));
}
__device__ __forceinline__ void mma16816h(float* c, uint32_t a0, uint32_t a1, uint32_t a2, uint32_t a3,
                                          uint32_t b0, uint32_t b1)
{
    asm volatile(
        "mma.sync.aligned.m16n8k16.row.col.f32.f16.f16.f32 "
        "{%0,%1,%2,%3}, {%4,%5,%6,%7}, {%8,%9}, {%0,%1,%2,%3};"
        : "+f"(c[0]), "+f"(c[1]), "+f"(c[2]), "+f"(c[3])
        : "r"(a0), "r"(a1), "r"(a2), "r"(a3), "r"(b0), "r"(b1));
}
__device__ __forceinline__ void cp16(uint32_t dst, const void* src, uint32_t srcsize)
{
    asm volatile("cp.async.cg.shared.global [%0], [%1], 16, %2;"
                 :: "r"(dst), "l"(src), "r"(srcsize) : "memory");
}
__device__ __forceinline__ void cp_commit() { asm volatile("cp.async.commit_group;" ::: "memory"); }

// ------------------- graph preprocessing -------------------
__global__ void zero_k(const float* __restrict__ fcb)
{
    int i = blockIdx.x * 256 + threadIdx.x;
    if (i < NN) { d_cnt[i] = 0; d_cursor[i] = 0; }
    if (i < BSZ*HFCC) d_zacc[i] = 0.f;
    if (i < BSZ*NN) d_g[i] = fcb[0];
}

// edge_index may be int64 or int32 (auto-detect).
__device__ __forceinline__ int ei_is64(const int* ei32)
{
    int allz = 1;
    #pragma unroll 8
    for (int i = 0; i < 64; i++) if (ei32[2 * i + 1] != 0) { allz = 0; break; }
    return allz;
}

__global__ void edges_k(const void* __restrict__ ei_raw)
{
    __shared__ int is64;
    if (threadIdx.x == 0) is64 = ei_is64((const int*)ei_raw);
    __syncthreads();

    int e = blockIdx.x * 256 + threadIdx.x;
    if (e >= EE) return;
    int c;
    if (is64) c = (int)((const long long*)ei_raw)[EE + e];
    else      c = ((const int*)ei_raw)[EE + e];
    atomicAdd(&d_cnt[c], 1);
}

// exclusive scan d_cnt -> d_rowptr (+ fused deg: dis/dinv), 1024 threads
__global__ void scan_k()
{
    __shared__ int wsum[32];
    int t = threadIdx.x, lane = t & 31, w = t >> 5;
    int base = t * 15;
    int v[15];
    int s = 0;
    #pragma unroll
    for (int i = 0; i < 15; i++) {
        int idx = base + i;
        v[i] = (idx < NN) ? d_cnt[idx] : 0;
        s += v[i];
        if (idx < NN) {
            float dg = (float)v[i] + 1.0f;
            d_dis[idx]  = rsqrtf(dg);
            d_dinv[idx] = 1.0f / dg;
        }
    }
    int ps = s;
    #pragma unroll
    for (int o = 1; o < 32; o <<= 1) {
        int u = __shfl_up_sync(0xffffffffu, ps, o);
        if (lane >= o) ps += u;
    }
    if (lane == 31) wsum[w] = ps;
    __syncthreads();
    if (w == 0) {
        int ws = wsum[lane];
        #pragma unroll
        for (int o = 1; o < 32; o <<= 1) {
            int u = __shfl_up_sync(0xffffffffu, ws, o);
            if (lane >= o) ws += u;
        }
        wsum[lane] = ws;
    }
    __syncthreads();
    int prefix = ps - s + (w > 0 ? wsum[w - 1] : 0);
    #pragma unroll
    for (int i = 0; i < 15; i++) {
        int idx = base + i;
        if (idx <= NN) d_rowptr[idx] = prefix;
        prefix += v[i];
    }
}

__global__ void fill_k(const void* __restrict__ ei_raw)
{
    __shared__ int is64;
    if (threadIdx.x == 0) is64 = ei_is64((const int*)ei_raw);
    __syncthreads();

    int e = blockIdx.x * 256 + threadIdx.x;
    if (e >= EE) return;
    int r, c;
    if (is64) {
        const long long* ei = (const long long*)ei_raw;
        r = (int)ei[e];
        c = (int)ei[EE + e];
    } else {
        const int* ei = (const int*)ei_raw;
        r = ei[e];
        c = ei[EE + e];
    }
    int p = atomicAdd(&d_cursor[c], 1);
    Edge ed; ed.s = r; ed.w = d_dis[r] * d_dis[c];
    d_edge[d_rowptr[c] + p] = ed;
}

// ------------------- input concat -> fp16, padded K=160 (flat) -------------------
__global__ void concat_k(const float* __restrict__ x, const float* __restrict__ pe)
{
    int idx = blockIdx.x * 256 + threadIdx.x;
    if (idx >= MM * K1P) return;
    int r = idx / K1P;
    int k = idx - r * K1P;
    int n = r >> 3, b = r & 7;
    float v = 0.f;
    if (k < FF) v = x[(b * NN + n) * FF + k];
    else if (k < K1) v = pe[n * GG + (k - FF)];
    d_a0[idx] = __float2half_rn(v);
}

// ------------------- weight transpose -> fp16: [K,256] -> [256,Kpad] -------------------
__global__ void convw_k(const float* __restrict__ W, __half* __restrict__ hi, int K, int Kpad)
{
    int idx = blockIdx.x * 256 + threadIdx.x;
    if (idx >= HH * Kpad) return;
    int n = idx / Kpad, k = idx - n * Kpad;
    float v = (k < K) ? W[k * HH + n] : 0.f;
    hi[idx] = __float2half_rn(v);
}

// ------------------- CSR gather: agg[row] = dinv*ain[row] + sum_e w*ain[src_row] ---------
// Pure weighted sum, fp16 in/out, fp32 accumulate. Block 256 = 8 warps = 8 batches.
// Edge loop unrolled x8 with packed {src, wgt} records for MLP.
template<int DIMH>
__global__ __launch_bounds__(256) void gather_k(const __half* __restrict__ ain,
                                                __half* __restrict__ aout)
{
    int j = blockIdx.x;
    int tid = threadIdx.x;
    int b = tid >> 5, lane = tid & 31;
    if (lane * 8 >= DIMH) return;
    size_t off = ((size_t)(j * 8 + b)) * DIMH + lane * 8;

    float acc[8];
    {
        float di = d_dinv[j];
        uint4 sv = *(const uint4*)(ain + off);
        const __half2* p = (const __half2*)&sv;
        #pragma unroll
        for (int q = 0; q < 4; q++) {
            float2 f = __half22float2(p[q]);
            acc[2 * q]     = f.x * di;
            acc[2 * q + 1] = f.y * di;
        }
    }

    int s0 = d_rowptr[j], s1 = d_rowptr[j + 1];
    int k = s0;
    #define ACC8(v, w) { const __half2* pp = (const __half2*)&(v); \
        _Pragma("unroll") for (int q = 0; q < 4; q++) { float2 f = __half22float2(pp[q]); \
            acc[2*q]   = fmaf((w), f.x, acc[2*q]); \
            acc[2*q+1] = fmaf((w), f.y, acc[2*q+1]); } }

    size_t lo = (size_t)b * DIMH + lane * 8;
    for (; k + 8 <= s1; k += 8) {
        Edge e[8];
        #pragma unroll
        for (int u = 0; u < 8; u++) e[u] = d_edge[k + u];
        uint4 v[8];
        #pragma unroll
        for (int u = 0; u < 8; u++)
            v[u] = *(const uint4*)(ain + (size_t)e[u].s * (8 * DIMH) + lo);
        #pragma unroll
        for (int u = 0; u < 8; u++) ACC8(v[u], e[u].w)
    }
    for (; k < s1; k++) {
        Edge e = d_edge[k];
        uint4 v = *(const uint4*)(ain + (size_t)e.s * (8 * DIMH) + lo);
        ACC8(v, e.w)
    }
    #undef ACC8

    uint4 hv;
    #pragma unroll
    for (int q = 0; q < 4; q++) {
        __half2 t = __floats2half2_rn(acc[2 * q], acc[2 * q + 1]);
        ((uint32_t*)&hv)[q] = *(uint32_t*)&t;
    }
    *(uint4*)(aout + off) = hv;
}

// ------------------- mma.sync fp16 GEMM + fused bias/ELU/fc-dot epilogue ---------------
// af[M,256](fp16) = elu(A @ W^T + bias); also d_g[b][j] += sum_h elu(..)*fcW[3h+layer].
// A [M][Kpad] fp16 (aggregated); W [256 n][Kpad k] fp16.
// Grid (946, 2): CTA tile 128m x 128n. 8 warps: warp tile 32m x 64n.
#define ASTRIDE 40
#define TILE_B  (128 * ASTRIDE * 2)    // 10240 bytes per operand tile
#define STAGE_B (2 * TILE_B)           // 20480 bytes per stage (A, B)
#define GEMM_DSMEM (3 * STAGE_B)       // 61440

__global__ __launch_bounds__(256) void mma_gemm_k(
    const __half* __restrict__ Af,
    const __half* __restrict__ Wh,
    int Kpad,
    const float* __restrict__ bias,
    const float* __restrict__ fcW,
    int layer)
{
    extern __shared__ char dsm[];
    uint32_t dsm_b = smem_u32(dsm);

    int tid = threadIdx.x, wid = tid >> 5, lane = tid & 31;
    int rowBase = blockIdx.x * 128;
    int colBase = blockIdx.y * 128;
    int wm = wid >> 1, wn = wid & 1;
    int m0 = wm * 32, n0 = wn * 64;

    float acc[2][8][4];
    #pragma unroll
    for (int i = 0; i < 2; i++)
        #pragma unroll
        for (int j = 0; j < 8; j++)
            #pragma unroll
            for (int q = 0; q < 4; q++) acc[i][j][q] = 0.f;

    int nch = Kpad >> 5;

    auto load_chunk = [&](int c, int st) {
        int k0 = c * 32;
        uint32_t sbase = dsm_b + st * STAGE_B;
        #pragma unroll
        for (int ii = 0; ii < 2; ii++) {
            int i = tid + ii * 256;
            int r = i >> 2, q = i & 3;
            uint32_t doff = (uint32_t)(r * (ASTRIDE * 2) + q * 16);
            int grow = rowBase + r;
            uint32_t ok = (grow < MM) ? 16u : 0u;
            int gr = (grow < MM) ? grow : 0;
            cp16(sbase + doff,          Af + (size_t)gr * Kpad + k0 + q * 8, ok);
            int gn = colBase + r;
            cp16(sbase + TILE_B + doff, Wh + (size_t)gn * Kpad + k0 + q * 8, 16u);
        }
        cp_commit();
    };

    load_chunk(0, 0);
    if (nch > 1) load_chunk(1, 1);

    int st = 0;
    for (int c = 0; c < nch; c++) {
        if (c + 2 < nch) {
            int st2 = st + 2; if (st2 >= 3) st2 -= 3;
            load_chunk(c + 2, st2);
            asm volatile("cp.async.wait_group 2;" ::: "memory");
        } else if (c + 1 < nch) {
            asm volatile("cp.async.wait_group 1;" ::: "memory");
        } else {
            asm volatile("cp.async.wait_group 0;" ::: "memory");
        }
        __syncthreads();

        char* stg = dsm + st * STAGE_B;
        __half* As = (__half*)(stg);
        __half* Bs = (__half*)(stg + TILE_B);

        #pragma unroll
        for (int s = 0; s < 2; s++) {
            int kk = s * 16;
            uint32_t ah[2][4];
            {
                int t = lane >> 3, rr = lane & 7;
                int arow = ((t & 1) << 3) + rr;
                int acol = kk + ((t >> 1) << 3);
                #pragma unroll
                for (int mt = 0; mt < 2; mt++) {
                    uint32_t ad = smem_u32(&As[(m0 + mt * 16 + arow) * ASTRIDE + acol]);
                    ldm_x4(ah[mt][0], ah[mt][1], ah[mt][2], ah[mt][3], ad);
                }
            }
            uint32_t bh[8][2];
            {
                int brow = (((lane >> 4) & 1) << 3) + (lane & 7);
                int bcol = kk + (((lane >> 3) & 1) << 3);
                #pragma unroll
                for (int nt = 0; nt < 4; nt++) {
                    uint32_t bd = smem_u32(&Bs[(n0 + nt * 16 + brow) * ASTRIDE + bcol]);
                    uint32_t r0, r1, r2, r3;
                    ldm_x4(r0, r1, r2, r3, bd);
                    bh[nt * 2][0] = r0; bh[nt * 2][1] = r1;
                    bh[nt * 2 + 1][0] = r2; bh[nt * 2 + 1][1] = r3;
                }
            }
            #pragma unroll
            for (int mt = 0; mt < 2; mt++)
                #pragma unroll
                for (int nt = 0; nt < 8; nt++)
                    mma16816h(acc[mt][nt], ah[mt][0], ah[mt][1], ah[mt][2], ah[mt][3], bh[nt][0], bh[nt][1]);
        }
        __syncthreads();
        if (++st == 3) st = 0;
    }

    // ---- fused epilogue: bias + ELU + fp16 store + fc-dot atomics ----
    int g = lane >> 2, tig = lane & 3;
    float2 bias_v[8], fcw_v[8];
    #pragma unroll
    for (int nt = 0; nt < 8; nt++) {
        int col = colBase + n0 + nt * 8 + tig * 2;
        bias_v[nt] = make_float2(bias[col], bias[col + 1]);
        fcw_v[nt]  = make_float2(fcW[3 * col + layer], fcW[3 * (col + 1) + layer]);
    }

    #pragma unroll
    for (int mt = 0; mt < 2; mt++) {
        #pragma unroll
        for (int half = 0; half < 2; half++) {
            int row = rowBase + m0 + mt * 16 + g + half * 8;
            bool ok = (row < MM);
            float gc = 0.f;
            #pragma unroll
            for (int nt = 0; nt < 8; nt++) {
                float v0 = elu1(acc[mt][nt][half * 2]     + bias_v[nt].x);
                float v1 = elu1(acc[mt][nt][half * 2 + 1] + bias_v[nt].y);
                gc = fmaf(v0, fcw_v[nt].x, gc);
                gc = fmaf(v1, fcw_v[nt].y, gc);
                if (ok && layer < 2) {
                    int col = colBase + n0 + nt * 8 + tig * 2;
                    __half2 p = __floats2half2_rn(v0, v1);
                    *(__half2*)(d_af + (size_t)row * 256 + col) = p;
                }
            }
            gc += __shfl_xor_sync(0xffffffffu, gc, 1);
            gc += __shfl_xor_sync(0xffffffffu, gc, 2);
            if (ok && tig == 0) {
                int j = row >> 3, b = row & 7;
                atomicAdd(&d_g[b * NN + j], gc);
            }
        }
    }
}

// ------------------- z = elu(g @ lin1_W + lin1_b), split-K (grid 2 x 256) ---------
__global__ __launch_bounds__(256) void lin1_k(const float* __restrict__ W)
{
    int o = blockIdx.x * 256 + threadIdx.x;  // 0..511
    const int NS = (NN + 255) / 256;         // 60
    int n0 = blockIdx.y * NS;
    int n1 = n0 + NS; if (n1 > NN) n1 = NN;
    float acc[8];
    #pragma unroll
    for (int b = 0; b < 8; b++) acc[b] = 0.f;
    for (int n = n0; n < n1; n++) {
        float w = W[n * 512 + o];
        #pragma unroll
        for (int b = 0; b < 8; b++) acc[b] = fmaf(d_g[b * NN + n], w, acc[b]);
    }
    #pragma unroll
    for (int b = 0; b < 8; b++) atomicAdd(&d_zacc[b * 512 + o], acc[b]);
}

// ------------------- out = log_softmax(elu(zacc + lin1_b) @ lin2_W + lin2_b) ---------
__global__ void final_k(const float* __restrict__ lin1b,
                        const float* __restrict__ W, const float* __restrict__ bv,
                        float* __restrict__ out)
{
    int b = threadIdx.x >> 5;
    int lane = threadIdx.x & 31;
    float a0 = 0.f, a1 = 0.f;
    for (int i = lane; i < 512; i += 32) {
        float z = elu1(d_zacc[b * 512 + i] + lin1b[i]);
        a0 = fmaf(z, W[2 * i],     a0);
        a1 = fmaf(z, W[2 * i + 1], a1);
    }
    #pragma unroll
    for (int o = 16; o; o >>= 1) {
        a0 += __shfl_xor_sync(0xffffffffu, a0, o);
        a1 += __shfl_xor_sync(0xffffffffu, a1, o);
    }
    if (lane == 0) {
        float v0 = a0 + bv[0], v1 = a1 + bv[1];
        float m = fmaxf(v0, v1);
        float l = m + logf(expf(v0 - m) + expf(v1 - m));
        out[2 * b]     = v0 - l;
        out[2 * b + 1] = v1 - l;
    }
}

// ------------------- host launcher -------------------
extern "C" void kernel_launch(void* const* d_in, const int* in_sizes, int n_in,
                              void* d_out, int out_size)
{
    const float* x      = (const float*)d_in[0];
    // d_in[1] = batch (unused, all zeros)
    const void*  ei     = d_in[2];                 // int32 or int64, auto-detected
    const float* pe     = (const float*)d_in[3];
    const float* W1     = (const float*)d_in[4];
    const float* b1     = (const float*)d_in[5];
    const float* W2     = (const float*)d_in[6];
    const float* b2     = (const float*)d_in[7];
    const float* W3     = (const float*)d_in[8];
    const float* b3     = (const float*)d_in[9];
    const float* fcW    = (const float*)d_in[10];
    const float* fcb    = (const float*)d_in[11];
    const float* lin1W  = (const float*)d_in[12];
    const float* lin1b  = (const float*)d_in[13];
    const float* lin2W  = (const float*)d_in[14];
    const float* lin2b  = (const float*)d_in[15];
    float* out = (float*)d_out;

    cudaFuncSetAttribute(mma_gemm_k, cudaFuncAttributeMaxDynamicSharedMemorySize, GEMM_DSMEM);

    // resolve device-global addresses for kernel args
    __half *a0, *agg, *af, *w0, *w1, *w2;
    cudaGetSymbolAddress((void**)&a0,  d_a0);
    cudaGetSymbolAddress((void**)&agg, d_agg);
    cudaGetSymbolAddress((void**)&af,  d_af);
    cudaGetSymbolAddress((void**)&w0,  d_w0);
    cudaGetSymbolAddress((void**)&w1,  d_w1);
    cudaGetSymbolAddress((void**)&w2,  d_w2);

    // graph preprocessing
    zero_k<<<(BSZ * NN + 255) / 256, 256>>>(fcb);
    edges_k<<<(EE + 255) / 256, 256>>>(ei);
    scan_k<<<1, 1024>>>();
    fill_k<<<(EE + 255) / 256, 256>>>(ei);

    // operand conversion
    concat_k<<<(MM * K1P + 255) / 256, 256>>>(x, pe);
    convw_k<<<(HH * K1P + 255) / 256, 256>>>(W1, w0, K1, K1P);
    convw_k<<<(HH * HH + 255) / 256, 256>>>(W2, w1, HH, HH);
    convw_k<<<(HH * HH + 255) / 256, 256>>>(W3, w2, HH, HH);

    const int MTILES = (MM + 127) / 128;  // 946
    dim3 ggrid(MTILES, 2);

    // layer 1: gather(a0, 160) -> agg; GEMM(agg,W1) -> af (+fc-dot layer 0)
    gather_k<K1P><<<NN, 256>>>(a0, agg);
    mma_gemm_k<<<ggrid, 256, GEMM_DSMEM>>>(agg, w0, K1P, b1, fcW, 0);
    // layer 2
    gather_k<HH><<<NN, 256>>>(af, agg);
    mma_gemm_k<<<ggrid, 256, GEMM_DSMEM>>>(agg, w1, HH, b2, fcW, 1);
    // layer 3 (no af write; epilogue only fc-dot)
    gather_k<HH><<<NN, 256>>>(af, agg);
    mma_gemm_k<<<ggrid, 256, GEMM_DSMEM>>>(agg, w2, HH, b3, fcW, 2);

    // head
    {
        dim3 lg(2, 256);
        lin1_k<<<lg, 256>>>(lin1W);
    }
    final_k<<<1, 256>>>(lin1b, lin2W, lin2b, out);
}